// round 1
// baseline (speedup 1.0000x reference)
#include <cuda_runtime.h>
#include <math.h>

// Problem constants
#define BH    32          // B*H
#define NSEQ  4096
#define DD    128         // head dim
#define FF    256         // feature dim
#define NTOK  (BH*NSEQ)   // 131072 tokens per tensor
#define KSPLIT 8

// Scratch (device globals: allocation-free rule)
__device__ float g_phi_q[(size_t)NTOK*FF];          // 134 MB
__device__ float g_phi_k[(size_t)NTOK*FF];          // 134 MB
__device__ float g_kvp[(size_t)KSPLIT*BH*FF*DD];    // 33.5 MB partials
__device__ float g_ksp[(size_t)KSPLIT*BH*FF];
__device__ float g_kv[(size_t)BH*FF*DD];
__device__ float g_ksum[(size_t)BH*FF];

// ---------------------------------------------------------------------------
// Kernel 1: phi = normalize(elu(silu(x@W1+b1)@W2+b2)+1) for q and k tokens.
// 64-token tile per block, 256 threads, 8x8 microtile (tokens x cols).
// smem: sH[64][257] (overlays sX[64][132]) + sW[16][256] = 82176 B dynamic.
// ---------------------------------------------------------------------------
__global__ void __launch_bounds__(256, 2) phi_kernel(
    const float* __restrict__ q, const float* __restrict__ k,
    const float* __restrict__ W1, const float* __restrict__ b1,
    const float* __restrict__ W2, const float* __restrict__ b2)
{
    extern __shared__ float sm[];
    float* sX = sm;             // [64][132]  (dead after stage 1)
    float* sH = sm;             // [64][257]  (overlays sX)
    float* sW = sm + 64*257;    // [16][256]

    const int tid = threadIdx.x;
    const int ty  = tid >> 5;   // 0..7  -> token group (warp id)
    const int tx  = tid & 31;   // 0..31 -> column lane

    const int bid = blockIdx.x;
    const float* src = (bid < 2048) ? q : k;
    float*       dst = (bid < 2048) ? g_phi_q : g_phi_k;
    const int tok0 = (bid & 2047) * 64;

    // Load X tile [64][128] -> sX (row stride 132, float4)
    {
        const float4* s4 = reinterpret_cast<const float4*>(src + (size_t)tok0 * DD);
        #pragma unroll
        for (int l = 0; l < 8; ++l) {
            int id  = tid + l * 256;            // 0..2047
            int row = id >> 5, c4 = id & 31;
            *reinterpret_cast<float4*>(&sX[row*132 + c4*4]) = s4[row*32 + c4];
        }
    }

    float acc[8][8];
    #pragma unroll
    for (int j = 0; j < 8; ++j) {
        float bj = b1[tx + 32*j];
        #pragma unroll
        for (int i = 0; i < 8; ++i) acc[i][j] = bj;
    }

    // -------- Stage 1: H = silu(X @ W1 + b1), K=128 --------
    for (int kb = 0; kb < 128; kb += 16) {
        __syncthreads();   // prior sW reads done (iter0: X stores done)
        {
            const float4* w4 = reinterpret_cast<const float4*>(W1 + kb*256);
            float4* sW4 = reinterpret_cast<float4*>(sW);
            #pragma unroll
            for (int l = 0; l < 4; ++l) sW4[tid + l*256] = w4[tid + l*256];
        }
        __syncthreads();
        #pragma unroll
        for (int kk = 0; kk < 16; ++kk) {
            float a[8], bb[8];
            #pragma unroll
            for (int i = 0; i < 8; ++i) a[i] = sX[(ty*8+i)*132 + kb + kk]; // broadcast
            #pragma unroll
            for (int j = 0; j < 8; ++j) bb[j] = sW[kk*256 + tx + 32*j];    // cf-free
            #pragma unroll
            for (int i = 0; i < 8; ++i)
                #pragma unroll
                for (int j = 0; j < 8; ++j) acc[i][j] = fmaf(a[i], bb[j], acc[i][j]);
        }
    }
    __syncthreads();   // all sX reads complete before overlaying with sH

    // silu -> sH ; re-init acc with b2
    #pragma unroll
    for (int i = 0; i < 8; ++i)
        #pragma unroll
        for (int j = 0; j < 8; ++j) {
            float h = acc[i][j];
            sH[(ty*8+i)*257 + tx + 32*j] = h / (1.f + __expf(-h));
        }
    #pragma unroll
    for (int j = 0; j < 8; ++j) {
        float bj = b2[tx + 32*j];
        #pragma unroll
        for (int i = 0; i < 8; ++i) acc[i][j] = bj;
    }
    __syncthreads();   // sH visible

    // -------- Stage 2: P = H @ W2 + b2, K=256 --------
    for (int kb = 0; kb < 256; kb += 16) {
        __syncthreads();
        {
            const float4* w4 = reinterpret_cast<const float4*>(W2 + kb*256);
            float4* sW4 = reinterpret_cast<float4*>(sW);
            #pragma unroll
            for (int l = 0; l < 4; ++l) sW4[tid + l*256] = w4[tid + l*256];
        }
        __syncthreads();
        #pragma unroll
        for (int kk = 0; kk < 16; ++kk) {
            float a[8], bb[8];
            #pragma unroll
            for (int i = 0; i < 8; ++i) a[i] = sH[(ty*8+i)*257 + kb + kk]; // broadcast
            #pragma unroll
            for (int j = 0; j < 8; ++j) bb[j] = sW[kk*256 + tx + 32*j];
            #pragma unroll
            for (int i = 0; i < 8; ++i)
                #pragma unroll
                for (int j = 0; j < 8; ++j) acc[i][j] = fmaf(a[i], bb[j], acc[i][j]);
        }
    }

    // -------- Epilogue: p = elu+1, L2-normalize per token (warp reduce) ----
    float s[8];
    #pragma unroll
    for (int i = 0; i < 8; ++i) {
        s[i] = 0.f;
        #pragma unroll
        for (int j = 0; j < 8; ++j) {
            float x = acc[i][j];
            float p = (x > 0.f) ? (x + 1.f) : __expf(x);
            acc[i][j] = p;
            s[i] = fmaf(p, p, s[i]);
        }
    }
    #pragma unroll
    for (int m = 16; m > 0; m >>= 1)
        #pragma unroll
        for (int i = 0; i < 8; ++i) s[i] += __shfl_xor_sync(0xffffffffu, s[i], m);

    #pragma unroll
    for (int i = 0; i < 8; ++i) {
        float inv = 1.f / (sqrtf(s[i]) + 1e-6f);
        float* dr = dst + (size_t)(tok0 + ty*8 + i) * FF;
        #pragma unroll
        for (int j = 0; j < 8; ++j) dr[tx + 32*j] = acc[i][j] * inv;
    }
}

// ---------------------------------------------------------------------------
// Kernel 2: per head, K-split partials of kv[F,D] = phi_k^T @ v and ksum[F].
// grid (32 heads, 2 f-tiles, 8 k-splits). 128x128 tile, 8x8 microtile.
// ---------------------------------------------------------------------------
__global__ void __launch_bounds__(256) kv_kernel(const float* __restrict__ v)
{
    __shared__ float sP[16*128];
    __shared__ float sV[16*128];

    const int hh = blockIdx.x;
    const int f0 = blockIdx.y * 128;
    const int ks = blockIdx.z;
    const int tid = threadIdx.x;
    const int ty = tid >> 4;    // 0..15 -> f rows
    const int tx = tid & 15;    // 0..15 -> d cols

    const float* phik = g_phi_k + (size_t)hh * NSEQ * FF;
    const float* vv   = v       + (size_t)hh * NSEQ * DD;

    float acc[8][8] = {};
    float ksacc = 0.f;
    const int n0 = ks * 512;

    for (int nb = 0; nb < 512; nb += 16) {
        __syncthreads();
        #pragma unroll
        for (int l = 0; l < 2; ++l) {
            int id  = tid + l * 256;       // 0..511
            int row = id >> 5, c4 = id & 31;
            reinterpret_cast<float4*>(sP)[id] =
                reinterpret_cast<const float4*>(phik + (size_t)(n0+nb+row)*FF + f0)[c4];
            reinterpret_cast<float4*>(sV)[id] =
                reinterpret_cast<const float4*>(vv   + (size_t)(n0+nb+row)*DD)[c4];
        }
        __syncthreads();
        if (tid < 128) {
            #pragma unroll
            for (int kk = 0; kk < 16; ++kk) ksacc += sP[kk*128 + tid];
        }
        #pragma unroll
        for (int kk = 0; kk < 16; ++kk) {
            float a[8];
            float4 b0 = reinterpret_cast<float4*>(sV)[kk*32 + tx*2];
            float4 b1v = reinterpret_cast<float4*>(sV)[kk*32 + tx*2 + 1];
            float bb[8] = {b0.x, b0.y, b0.z, b0.w, b1v.x, b1v.y, b1v.z, b1v.w};
            #pragma unroll
            for (int i = 0; i < 8; ++i) a[i] = sP[kk*128 + ty*8 + i];
            #pragma unroll
            for (int i = 0; i < 8; ++i)
                #pragma unroll
                for (int j = 0; j < 8; ++j) acc[i][j] = fmaf(a[i], bb[j], acc[i][j]);
        }
    }

    float* outp = g_kvp + ((size_t)ks * BH + hh) * FF * DD;
    #pragma unroll
    for (int i = 0; i < 8; ++i) {
        float* r = outp + (size_t)(f0 + ty*8 + i) * DD + tx*8;
        *reinterpret_cast<float4*>(r)     = make_float4(acc[i][0], acc[i][1], acc[i][2], acc[i][3]);
        *reinterpret_cast<float4*>(r + 4) = make_float4(acc[i][4], acc[i][5], acc[i][6], acc[i][7]);
    }
    if (tid < 128)
        g_ksp[((size_t)ks * BH + hh) * FF + f0 + tid] = ksacc;
}

// ---------------------------------------------------------------------------
// Kernel 3: deterministic reduction of K-split partials.
// ---------------------------------------------------------------------------
__global__ void reduce_kernel()
{
    const int NKV = BH * FF * DD;         // 1048576
    const int NKS = BH * FF;              // 8192
    int i = blockIdx.x * blockDim.x + threadIdx.x;
    if (i < NKV) {
        float s = 0.f;
        #pragma unroll
        for (int p = 0; p < KSPLIT; ++p) s += g_kvp[(size_t)p * NKV + i];
        g_kv[i] = s;
    } else {
        int j = i - NKV;
        if (j < NKS) {
            float s = 0.f;
            #pragma unroll
            for (int p = 0; p < KSPLIT; ++p) s += g_ksp[(size_t)p * NKS + j];
            g_ksum[j] = s;
        }
    }
}

// ---------------------------------------------------------------------------
// Kernel 4: out = (phi_q @ kv) / max(phi_q @ ksum, eps) per head.
// grid (32 heads, 32 m-tiles). 128x128 tile, K=256, 8x8 microtile.
// ---------------------------------------------------------------------------
__global__ void __launch_bounds__(256) qkv_kernel(float* __restrict__ out)
{
    __shared__ float sA[16*128];   // phi_q chunk, transposed [kk][m]
    __shared__ float sB[16*128];   // kv chunk [kk][d]
    __shared__ float sKs[16];
    __shared__ float sDen[128];

    const int hh = blockIdx.x;
    const int m0 = blockIdx.y * 128;
    const int tid = threadIdx.x;
    const int ty = tid >> 4, tx = tid & 15;

    const float* phiq = g_phi_q + (size_t)hh * NSEQ * FF;
    const float* kvh  = g_kv    + (size_t)hh * FF * DD;

    float acc[8][8] = {};
    float den = 0.f;

    for (int kb = 0; kb < 256; kb += 16) {
        __syncthreads();
        #pragma unroll
        for (int l = 0; l < 2; ++l) {
            int id  = tid + l * 256;        // 0..511
            int row = id >> 2, c4 = id & 3;
            float4 a4 = reinterpret_cast<const float4*>(phiq + (size_t)(m0+row)*FF + kb)[c4];
            sA[(c4*4+0)*128 + row] = a4.x;
            sA[(c4*4+1)*128 + row] = a4.y;
            sA[(c4*4+2)*128 + row] = a4.z;
            sA[(c4*4+3)*128 + row] = a4.w;
            reinterpret_cast<float4*>(sB)[id] =
                reinterpret_cast<const float4*>(kvh + (size_t)kb * DD)[id];
        }
        if (tid < 16) sKs[tid] = g_ksum[hh*FF + kb + tid];
        __syncthreads();

        if (tid < 128) {
            #pragma unroll
            for (int kk = 0; kk < 16; ++kk) den = fmaf(sA[kk*128 + tid], sKs[kk], den);
        }
        #pragma unroll
        for (int kk = 0; kk < 16; ++kk) {
            float a[8];
            float4 b0 = reinterpret_cast<float4*>(sB)[kk*32 + tx*2];
            float4 b1v = reinterpret_cast<float4*>(sB)[kk*32 + tx*2 + 1];
            float bb[8] = {b0.x, b0.y, b0.z, b0.w, b1v.x, b1v.y, b1v.z, b1v.w};
            #pragma unroll
            for (int i = 0; i < 8; ++i) a[i] = sA[kk*128 + ty*8 + i];
            #pragma unroll
            for (int i = 0; i < 8; ++i)
                #pragma unroll
                for (int j = 0; j < 8; ++j) acc[i][j] = fmaf(a[i], bb[j], acc[i][j]);
        }
    }

    if (tid < 128) sDen[tid] = den;
    __syncthreads();

    float* op = out + ((size_t)hh * NSEQ + m0) * DD;
    #pragma unroll
    for (int i = 0; i < 8; ++i) {
        float invd = 1.f / fmaxf(sDen[ty*8 + i], 1e-6f);
        float* r = op + (size_t)(ty*8 + i) * DD + tx*8;
        *reinterpret_cast<float4*>(r) = make_float4(acc[i][0]*invd, acc[i][1]*invd,
                                                    acc[i][2]*invd, acc[i][3]*invd);
        *reinterpret_cast<float4*>(r + 4) = make_float4(acc[i][4]*invd, acc[i][5]*invd,
                                                        acc[i][6]*invd, acc[i][7]*invd);
    }
}

// ---------------------------------------------------------------------------
extern "C" void kernel_launch(void* const* d_in, const int* in_sizes, int n_in,
                              void* d_out, int out_size)
{
    (void)in_sizes; (void)n_in; (void)out_size;
    const float* q  = (const float*)d_in[0];
    const float* k  = (const float*)d_in[1];
    const float* v  = (const float*)d_in[2];
    const float* W1 = (const float*)d_in[3];
    const float* b1 = (const float*)d_in[4];
    const float* W2 = (const float*)d_in[5];
    const float* b2 = (const float*)d_in[6];
    float* out = (float*)d_out;

    const int PHI_SMEM = (64*257 + 16*256) * sizeof(float);  // 82176 B
    cudaFuncSetAttribute(phi_kernel, cudaFuncAttributeMaxDynamicSharedMemorySize, PHI_SMEM);

    phi_kernel<<<4096, 256, PHI_SMEM>>>(q, k, W1, b1, W2, b2);
    kv_kernel<<<dim3(32, 2, KSPLIT), 256>>>(v);
    {
        const int total = BH*FF*DD + BH*FF;   // 1056768
        reduce_kernel<<<(total + 255) / 256, 256>>>();
    }
    qkv_kernel<<<dim3(32, 32), 256>>>(out);
}

// round 3
// speedup vs baseline: 1.6669x; 1.6669x over previous
#include <cuda_runtime.h>
#include <math.h>
#include <stdint.h>

// Problem constants
#define BH    32
#define NSEQ  4096
#define DD    128
#define FF    256
#define NTOK  (BH*NSEQ)
#define KSPLIT 8

// Scratch (device globals: allocation-free rule)
__device__ float g_phi_q[(size_t)NTOK*FF];
__device__ float g_phi_k[(size_t)NTOK*FF];
__device__ float g_kvp[(size_t)KSPLIT*BH*FF*DD];
__device__ float g_ksp[(size_t)KSPLIT*BH*FF];
__device__ float g_kv[(size_t)BH*FF*DD];
__device__ float g_ksum[(size_t)BH*FF];

// ---------------------------------------------------------------------------
// helpers
// ---------------------------------------------------------------------------
__device__ __forceinline__ uint32_t f2tf32(float f) {
    uint32_t r; asm("cvt.rna.tf32.f32 %0, %1;" : "=r"(r) : "f"(f)); return r;
}
__device__ __forceinline__ void mma_tf32(float* d, const uint32_t* a,
                                         uint32_t b0, uint32_t b1) {
    asm volatile("mma.sync.aligned.m16n8k8.row.col.f32.tf32.tf32.f32 "
                 "{%0,%1,%2,%3}, {%4,%5,%6,%7}, {%8,%9}, {%0,%1,%2,%3};"
                 : "+f"(d[0]), "+f"(d[1]), "+f"(d[2]), "+f"(d[3])
                 : "r"(a[0]), "r"(a[1]), "r"(a[2]), "r"(a[3]),
                   "r"(b0), "r"(b1));
}

// ---------------------------------------------------------------------------
// phi kernel (tf32 mma.sync): 128 tokens per CTA, 512 threads (16 warps).
// stage1: H = silu(X[128,128] @ W1[128,256] + b1)   (4 K-chunks of 32)
// stage2: P = elu(H[128,256] @ W2[256,256] + b2)+1  (8 K-chunks of 32)
// epilogue: per-token L2 normalize, write fp32.
//
// SMEM float offsets:
//   A region @0     : sX[128][132] (stage1) overlaid by sH[128][260] (stage2)
//   sW @33280       : 2 x [32][264] weight chunk double buffer
//   sB1 @50176, sB2 @50432, sPart @50688 (4*128), sInv @51200 (128)
// total 51328 floats = 205312 B
// ---------------------------------------------------------------------------
#define XSTR 132
#define HSTR 260
#define WSTR 264
#define OFFW   33280
#define OFFB1  50176
#define OFFB2  50432
#define OFFPRT 50688
#define OFFINV 51200
#define PHI_SMEM (51328 * 4)

__global__ void __launch_bounds__(512) phi_mma_kernel(
    const float* __restrict__ q, const float* __restrict__ k,
    const float* __restrict__ W1, const float* __restrict__ b1,
    const float* __restrict__ W2, const float* __restrict__ b2)
{
    extern __shared__ float smf[];
    uint32_t* sA  = reinterpret_cast<uint32_t*>(smf);        // sX / sH
    uint32_t* sW  = reinterpret_cast<uint32_t*>(smf + OFFW);
    float* sB1  = smf + OFFB1;
    float* sB2  = smf + OFFB2;
    float* sPrt = smf + OFFPRT;
    float* sInv = smf + OFFINV;

    const int tid  = threadIdx.x;
    const int wid  = tid >> 5;
    const int lane = tid & 31;
    const int g    = lane >> 2;   // group id (rows within fragment)
    const int tq   = lane & 3;    // thread-in-quad (cols within fragment)
    const int wm   = wid & 3;     // warp M index (32 rows each)
    const int wn   = wid >> 2;    // warp N index (64 cols each)

    const int bid = blockIdx.x;
    const float* src = (bid < 1024) ? q : k;
    float*       dst = (bid < 1024) ? g_phi_q : g_phi_k;
    const int tok0 = (bid & 1023) * 128;

    // ---- stage X tile [128][128] -> tf32 smem, stride 132 ----
    {
        const float4* s4 = reinterpret_cast<const float4*>(src + (size_t)tok0 * DD);
        #pragma unroll
        for (int l = 0; l < 8; ++l) {
            int id  = tid + l * 512;        // 0..4095 float4
            int row = id >> 5, c4 = id & 31;
            float4 v = s4[row * 32 + c4];
            uint32_t* p = &sA[row * XSTR + c4 * 4];
            p[0] = f2tf32(v.x); p[1] = f2tf32(v.y);
            p[2] = f2tf32(v.z); p[3] = f2tf32(v.w);
        }
    }
    if (tid < 256) { sB1[tid] = b1[tid]; sB2[tid] = b2[tid]; }

    // ---- preload W chunk 0 (W1 rows 0..31) into buf0 ----
    {
        const float4* wp = reinterpret_cast<const float4*>(W1);
        #pragma unroll
        for (int l = 0; l < 4; ++l) {
            int id  = tid + l * 512;        // 0..2047 float4
            int row = id >> 6, c4 = id & 63;
            float4 v = wp[id];
            uint32_t* p = &sW[row * WSTR + c4 * 4];
            p[0] = f2tf32(v.x); p[1] = f2tf32(v.y);
            p[2] = f2tf32(v.z); p[3] = f2tf32(v.w);
        }
    }

    float acc[2][8][4];
    #pragma unroll
    for (int mt = 0; mt < 2; ++mt)
        #pragma unroll
        for (int nt = 0; nt < 8; ++nt)
            #pragma unroll
            for (int e = 0; e < 4; ++e) acc[mt][nt][e] = 0.f;

    // ---- unified K-chunk loop: kc 0..3 = stage1, 4..11 = stage2 ----
    for (int kc = 0; kc < 12; ++kc) {
        if (kc == 4) {
            // ===== epilogue 1: H = silu(acc + b1) -> sH (overlay sX) =====
            __syncthreads();   // all sX reads (kc=3 compute) done
            #pragma unroll
            for (int mt = 0; mt < 2; ++mt)
                #pragma unroll
                for (int nt = 0; nt < 8; ++nt) {
                    const int col = wn*64 + nt*8 + tq*2;
                    #pragma unroll
                    for (int h = 0; h < 2; ++h) {
                        const int row = wm*32 + mt*16 + 8*h + g;
                        #pragma unroll
                        for (int pr = 0; pr < 2; ++pr) {
                            float x = acc[mt][nt][h*2+pr] + sB1[col+pr];
                            float s = x / (1.f + __expf(-x));
                            sA[row * HSTR + col + pr] = f2tf32(s);
                            acc[mt][nt][h*2+pr] = 0.f;
                        }
                    }
                }
        }
        __syncthreads();   // W buf(kc&1) stores + (kc==4) sH visible

        // prefetch next W chunk into registers
        float4 wreg[4];
        if (kc < 11) {
            int nkc = kc + 1;
            const float4* wp = reinterpret_cast<const float4*>(
                (nkc < 4) ? (W1 + nkc*32*256) : (W2 + (nkc-4)*32*256));
            #pragma unroll
            for (int l = 0; l < 4; ++l) wreg[l] = wp[tid + l * 512];
        }

        // ---- compute on buf(kc&1) ----
        {
            const bool s1 = (kc < 4);
            const uint32_t* Abase = s1
                ? (sA + (wm*32)*XSTR + kc*32)
                : (sA + (wm*32)*HSTR + (kc-4)*32);
            const int astr = s1 ? XSTR : HSTR;
            const uint32_t* Wbuf = sW + (kc & 1) * (32 * WSTR);

            #pragma unroll
            for (int k8 = 0; k8 < 4; ++k8) {
                uint32_t a[2][4];
                #pragma unroll
                for (int mt = 0; mt < 2; ++mt) {
                    const uint32_t* Ar = Abase + (mt*16 + g)*astr + k8*8 + tq;
                    a[mt][0] = Ar[0];
                    a[mt][1] = Ar[8*astr];
                    a[mt][2] = Ar[4];
                    a[mt][3] = Ar[8*astr + 4];
                }
                const uint32_t* Bc = Wbuf + (k8*8 + tq)*WSTR + wn*64 + g;
                #pragma unroll
                for (int nt = 0; nt < 8; ++nt) {
                    uint32_t b0 = Bc[nt*8];
                    uint32_t b1v = Bc[4*WSTR + nt*8];
                    mma_tf32(acc[0][nt], a[0], b0, b1v);
                    mma_tf32(acc[1][nt], a[1], b0, b1v);
                }
            }
        }

        // store prefetched chunk into other buffer
        if (kc < 11) {
            uint32_t* Wn = sW + ((kc+1) & 1) * (32 * WSTR);
            #pragma unroll
            for (int l = 0; l < 4; ++l) {
                int id  = tid + l * 512;
                int row = id >> 6, c4 = id & 63;
                uint32_t* p = &Wn[row * WSTR + c4 * 4];
                p[0] = f2tf32(wreg[l].x); p[1] = f2tf32(wreg[l].y);
                p[2] = f2tf32(wreg[l].z); p[3] = f2tf32(wreg[l].w);
            }
        }
    }

    // ===== epilogue 2: p = elu(acc + b2)+1, row L2 norm, write =====
    float ss[2][2] = {};   // [mt][h]
    #pragma unroll
    for (int mt = 0; mt < 2; ++mt)
        #pragma unroll
        for (int nt = 0; nt < 8; ++nt) {
            const int col = wn*64 + nt*8 + tq*2;
            #pragma unroll
            for (int h = 0; h < 2; ++h)
                #pragma unroll
                for (int pr = 0; pr < 2; ++pr) {
                    float x = acc[mt][nt][h*2+pr] + sB2[col+pr];
                    float p = (x > 0.f) ? (x + 1.f) : __expf(x);
                    acc[mt][nt][h*2+pr] = p;
                    ss[mt][h] = fmaf(p, p, ss[mt][h]);
                }
        }
    // quad reduce (cols of one row live in one quad)
    #pragma unroll
    for (int m = 1; m <= 2; m <<= 1)
        #pragma unroll
        for (int mt = 0; mt < 2; ++mt)
            #pragma unroll
            for (int h = 0; h < 2; ++h)
                ss[mt][h] += __shfl_xor_sync(0xffffffffu, ss[mt][h], m);
    if (tq == 0) {
        #pragma unroll
        for (int mt = 0; mt < 2; ++mt)
            #pragma unroll
            for (int h = 0; h < 2; ++h)
                sPrt[wn*128 + wm*32 + mt*16 + 8*h + g] = ss[mt][h];
    }
    __syncthreads();
    if (tid < 128)
        sInv[tid] = 1.f / (sqrtf(sPrt[tid] + sPrt[128+tid] +
                                 sPrt[256+tid] + sPrt[384+tid]) + 1e-6f);
    __syncthreads();

    #pragma unroll
    for (int mt = 0; mt < 2; ++mt)
        #pragma unroll
        for (int h = 0; h < 2; ++h) {
            const int row = wm*32 + mt*16 + 8*h + g;
            const float inv = sInv[row];
            float* dr = dst + (size_t)(tok0 + row) * FF;
            #pragma unroll
            for (int nt = 0; nt < 8; ++nt) {
                const int col = wn*64 + nt*8 + tq*2;
                dr[col]   = acc[mt][nt][h*2]   * inv;
                dr[col+1] = acc[mt][nt][h*2+1] * inv;
            }
        }
}

// ---------------------------------------------------------------------------
// Kernel 2: per head, K-split partials of kv[F,D] = phi_k^T @ v and ksum[F].
// (unchanged: R1-passing)
// ---------------------------------------------------------------------------
__global__ void __launch_bounds__(256) kv_kernel(const float* __restrict__ v)
{
    __shared__ float sP[16*128];
    __shared__ float sV[16*128];

    const int hh = blockIdx.x;
    const int f0 = blockIdx.y * 128;
    const int ks = blockIdx.z;
    const int tid = threadIdx.x;
    const int ty = tid >> 4;
    const int tx = tid & 15;

    const float* phik = g_phi_k + (size_t)hh * NSEQ * FF;
    const float* vv   = v       + (size_t)hh * NSEQ * DD;

    float acc[8][8] = {};
    float ksacc = 0.f;
    const int n0 = ks * 512;

    for (int nb = 0; nb < 512; nb += 16) {
        __syncthreads();
        #pragma unroll
        for (int l = 0; l < 2; ++l) {
            int id  = tid + l * 256;
            int row = id >> 5, c4 = id & 31;
            reinterpret_cast<float4*>(sP)[id] =
                reinterpret_cast<const float4*>(phik + (size_t)(n0+nb+row)*FF + f0)[c4];
            reinterpret_cast<float4*>(sV)[id] =
                reinterpret_cast<const float4*>(vv   + (size_t)(n0+nb+row)*DD)[c4];
        }
        __syncthreads();
        if (tid < 128) {
            #pragma unroll
            for (int kk = 0; kk < 16; ++kk) ksacc += sP[kk*128 + tid];
        }
        #pragma unroll
        for (int kk = 0; kk < 16; ++kk) {
            float a[8];
            float4 b0 = reinterpret_cast<float4*>(sV)[kk*32 + tx*2];
            float4 b1v = reinterpret_cast<float4*>(sV)[kk*32 + tx*2 + 1];
            float bb[8] = {b0.x, b0.y, b0.z, b0.w, b1v.x, b1v.y, b1v.z, b1v.w};
            #pragma unroll
            for (int i = 0; i < 8; ++i) a[i] = sP[kk*128 + ty*8 + i];
            #pragma unroll
            for (int i = 0; i < 8; ++i)
                #pragma unroll
                for (int j = 0; j < 8; ++j) acc[i][j] = fmaf(a[i], bb[j], acc[i][j]);
        }
    }

    float* outp = g_kvp + ((size_t)ks * BH + hh) * FF * DD;
    #pragma unroll
    for (int i = 0; i < 8; ++i) {
        float* r = outp + (size_t)(f0 + ty*8 + i) * DD + tx*8;
        *reinterpret_cast<float4*>(r)     = make_float4(acc[i][0], acc[i][1], acc[i][2], acc[i][3]);
        *reinterpret_cast<float4*>(r + 4) = make_float4(acc[i][4], acc[i][5], acc[i][6], acc[i][7]);
    }
    if (tid < 128)
        g_ksp[((size_t)ks * BH + hh) * FF + f0 + tid] = ksacc;
}

// ---------------------------------------------------------------------------
// Kernel 3: deterministic reduction of K-split partials. (unchanged)
// ---------------------------------------------------------------------------
__global__ void reduce_kernel()
{
    const int NKV = BH * FF * DD;
    const int NKS = BH * FF;
    int i = blockIdx.x * blockDim.x + threadIdx.x;
    if (i < NKV) {
        float s = 0.f;
        #pragma unroll
        for (int p = 0; p < KSPLIT; ++p) s += g_kvp[(size_t)p * NKV + i];
        g_kv[i] = s;
    } else {
        int j = i - NKV;
        if (j < NKS) {
            float s = 0.f;
            #pragma unroll
            for (int p = 0; p < KSPLIT; ++p) s += g_ksp[(size_t)p * NKS + j];
            g_ksum[j] = s;
        }
    }
}

// ---------------------------------------------------------------------------
// Kernel 4: out = (phi_q @ kv) / max(phi_q @ ksum, eps). (unchanged)
// ---------------------------------------------------------------------------
__global__ void __launch_bounds__(256) qkv_kernel(float* __restrict__ out)
{
    __shared__ float sA[16*128];
    __shared__ float sB[16*128];
    __shared__ float sKs[16];
    __shared__ float sDen[128];

    const int hh = blockIdx.x;
    const int m0 = blockIdx.y * 128;
    const int tid = threadIdx.x;
    const int ty = tid >> 4, tx = tid & 15;

    const float* phiq = g_phi_q + (size_t)hh * NSEQ * FF;
    const float* kvh  = g_kv    + (size_t)hh * FF * DD;

    float acc[8][8] = {};
    float den = 0.f;

    for (int kb = 0; kb < 256; kb += 16) {
        __syncthreads();
        #pragma unroll
        for (int l = 0; l < 2; ++l) {
            int id  = tid + l * 256;
            int row = id >> 2, c4 = id & 3;
            float4 a4 = reinterpret_cast<const float4*>(phiq + (size_t)(m0+row)*FF + kb)[c4];
            sA[(c4*4+0)*128 + row] = a4.x;
            sA[(c4*4+1)*128 + row] = a4.y;
            sA[(c4*4+2)*128 + row] = a4.z;
            sA[(c4*4+3)*128 + row] = a4.w;
            reinterpret_cast<float4*>(sB)[id] =
                reinterpret_cast<const float4*>(kvh + (size_t)kb * DD)[id];
        }
        if (tid < 16) sKs[tid] = g_ksum[hh*FF + kb + tid];
        __syncthreads();

        if (tid < 128) {
            #pragma unroll
            for (int kk = 0; kk < 16; ++kk) den = fmaf(sA[kk*128 + tid], sKs[kk], den);
        }
        #pragma unroll
        for (int kk = 0; kk < 16; ++kk) {
            float a[8];
            float4 b0 = reinterpret_cast<float4*>(sB)[kk*32 + tx*2];
            float4 b1v = reinterpret_cast<float4*>(sB)[kk*32 + tx*2 + 1];
            float bb[8] = {b0.x, b0.y, b0.z, b0.w, b1v.x, b1v.y, b1v.z, b1v.w};
            #pragma unroll
            for (int i = 0; i < 8; ++i) a[i] = sA[kk*128 + ty*8 + i];
            #pragma unroll
            for (int i = 0; i < 8; ++i)
                #pragma unroll
                for (int j = 0; j < 8; ++j) acc[i][j] = fmaf(a[i], bb[j], acc[i][j]);
        }
    }

    if (tid < 128) sDen[tid] = den;
    __syncthreads();

    float* op = out + ((size_t)hh * NSEQ + m0) * DD;
    #pragma unroll
    for (int i = 0; i < 8; ++i) {
        float invd = 1.f / fmaxf(sDen[ty*8 + i], 1e-6f);
        float* r = op + (size_t)(ty*8 + i) * DD + tx*8;
        *reinterpret_cast<float4*>(r) = make_float4(acc[i][0]*invd, acc[i][1]*invd,
                                                    acc[i][2]*invd, acc[i][3]*invd);
        *reinterpret_cast<float4*>(r + 4) = make_float4(acc[i][4]*invd, acc[i][5]*invd,
                                                        acc[i][6]*invd, acc[i][7]*invd);
    }
}

// ---------------------------------------------------------------------------
extern "C" void kernel_launch(void* const* d_in, const int* in_sizes, int n_in,
                              void* d_out, int out_size)
{
    (void)in_sizes; (void)n_in; (void)out_size;
    const float* q  = (const float*)d_in[0];
    const float* k  = (const float*)d_in[1];
    const float* v  = (const float*)d_in[2];
    const float* W1 = (const float*)d_in[3];
    const float* b1 = (const float*)d_in[4];
    const float* W2 = (const float*)d_in[5];
    const float* b2 = (const float*)d_in[6];
    float* out = (float*)d_out;

    cudaFuncSetAttribute(phi_mma_kernel, cudaFuncAttributeMaxDynamicSharedMemorySize, PHI_SMEM);

    phi_mma_kernel<<<2048, 512, PHI_SMEM>>>(q, k, W1, b1, W2, b2);
    kv_kernel<<<dim3(32, 2, KSPLIT), 256>>>(v);
    {
        const int total = BH*FF*DD + BH*FF;
        reduce_kernel<<<(total + 255) / 256, 256>>>();
    }
    qkv_kernel<<<dim3(32, 32), 256>>>(out);
}

// round 4
// speedup vs baseline: 2.3006x; 1.3802x over previous
#include <cuda_runtime.h>
#include <math.h>
#include <stdint.h>

// Problem constants
#define BH    32
#define NSEQ  4096
#define DD    128
#define FF    256
#define NTOK  (BH*NSEQ)
#define KSPLIT 8

// Scratch (device globals: allocation-free rule)
__device__ float g_phi_q[(size_t)NTOK*FF];
__device__ float g_phi_k[(size_t)NTOK*FF];
__device__ float g_kvp[(size_t)KSPLIT*BH*FF*DD];
__device__ float g_ksp[(size_t)KSPLIT*BH*FF];
__device__ float g_kv[(size_t)BH*FF*DD];
__device__ float g_ksum[(size_t)BH*FF];

// ---------------------------------------------------------------------------
// helpers
// ---------------------------------------------------------------------------
__device__ __forceinline__ uint32_t f2tf32(float f) {
    uint32_t r; asm("cvt.rna.tf32.f32 %0, %1;" : "=r"(r) : "f"(f)); return r;
}
__device__ __forceinline__ void mma_tf32(float* d, const uint32_t* a,
                                         uint32_t b0, uint32_t b1) {
    asm volatile("mma.sync.aligned.m16n8k8.row.col.f32.tf32.tf32.f32 "
                 "{%0,%1,%2,%3}, {%4,%5,%6,%7}, {%8,%9}, {%0,%1,%2,%3};"
                 : "+f"(d[0]), "+f"(d[1]), "+f"(d[2]), "+f"(d[3])
                 : "r"(a[0]), "r"(a[1]), "r"(a[2]), "r"(a[3]),
                   "r"(b0), "r"(b1));
}

// ---------------------------------------------------------------------------
// phi kernel (tf32 mma.sync): 128 tokens per CTA, 512 threads (16 warps).
// (unchanged from R3 — passing, ~530us)
// ---------------------------------------------------------------------------
#define XSTR 132
#define HSTR 260
#define WSTR 264
#define OFFW   33280
#define OFFB1  50176
#define OFFB2  50432
#define OFFPRT 50688
#define OFFINV 51200
#define PHI_SMEM (51328 * 4)

__global__ void __launch_bounds__(512) phi_mma_kernel(
    const float* __restrict__ q, const float* __restrict__ k,
    const float* __restrict__ W1, const float* __restrict__ b1,
    const float* __restrict__ W2, const float* __restrict__ b2)
{
    extern __shared__ float smf[];
    uint32_t* sA  = reinterpret_cast<uint32_t*>(smf);
    uint32_t* sW  = reinterpret_cast<uint32_t*>(smf + OFFW);
    float* sB1  = smf + OFFB1;
    float* sB2  = smf + OFFB2;
    float* sPrt = smf + OFFPRT;
    float* sInv = smf + OFFINV;

    const int tid  = threadIdx.x;
    const int wid  = tid >> 5;
    const int lane = tid & 31;
    const int g    = lane >> 2;
    const int tq   = lane & 3;
    const int wm   = wid & 3;
    const int wn   = wid >> 2;

    const int bid = blockIdx.x;
    const float* src = (bid < 1024) ? q : k;
    float*       dst = (bid < 1024) ? g_phi_q : g_phi_k;
    const int tok0 = (bid & 1023) * 128;

    {
        const float4* s4 = reinterpret_cast<const float4*>(src + (size_t)tok0 * DD);
        #pragma unroll
        for (int l = 0; l < 8; ++l) {
            int id  = tid + l * 512;
            int row = id >> 5, c4 = id & 31;
            float4 v = s4[row * 32 + c4];
            uint32_t* p = &sA[row * XSTR + c4 * 4];
            p[0] = f2tf32(v.x); p[1] = f2tf32(v.y);
            p[2] = f2tf32(v.z); p[3] = f2tf32(v.w);
        }
    }
    if (tid < 256) { sB1[tid] = b1[tid]; sB2[tid] = b2[tid]; }

    {
        const float4* wp = reinterpret_cast<const float4*>(W1);
        #pragma unroll
        for (int l = 0; l < 4; ++l) {
            int id  = tid + l * 512;
            int row = id >> 6, c4 = id & 63;
            float4 v = wp[id];
            uint32_t* p = &sW[row * WSTR + c4 * 4];
            p[0] = f2tf32(v.x); p[1] = f2tf32(v.y);
            p[2] = f2tf32(v.z); p[3] = f2tf32(v.w);
        }
    }

    float acc[2][8][4];
    #pragma unroll
    for (int mt = 0; mt < 2; ++mt)
        #pragma unroll
        for (int nt = 0; nt < 8; ++nt)
            #pragma unroll
            for (int e = 0; e < 4; ++e) acc[mt][nt][e] = 0.f;

    for (int kc = 0; kc < 12; ++kc) {
        if (kc == 4) {
            __syncthreads();
            #pragma unroll
            for (int mt = 0; mt < 2; ++mt)
                #pragma unroll
                for (int nt = 0; nt < 8; ++nt) {
                    const int col = wn*64 + nt*8 + tq*2;
                    #pragma unroll
                    for (int h = 0; h < 2; ++h) {
                        const int row = wm*32 + mt*16 + 8*h + g;
                        #pragma unroll
                        for (int pr = 0; pr < 2; ++pr) {
                            float x = acc[mt][nt][h*2+pr] + sB1[col+pr];
                            float s = x / (1.f + __expf(-x));
                            sA[row * HSTR + col + pr] = f2tf32(s);
                            acc[mt][nt][h*2+pr] = 0.f;
                        }
                    }
                }
        }
        __syncthreads();

        float4 wreg[4];
        if (kc < 11) {
            int nkc = kc + 1;
            const float4* wp = reinterpret_cast<const float4*>(
                (nkc < 4) ? (W1 + nkc*32*256) : (W2 + (nkc-4)*32*256));
            #pragma unroll
            for (int l = 0; l < 4; ++l) wreg[l] = wp[tid + l * 512];
        }

        {
            const bool s1 = (kc < 4);
            const uint32_t* Abase = s1
                ? (sA + (wm*32)*XSTR + kc*32)
                : (sA + (wm*32)*HSTR + (kc-4)*32);
            const int astr = s1 ? XSTR : HSTR;
            const uint32_t* Wbuf = sW + (kc & 1) * (32 * WSTR);

            #pragma unroll
            for (int k8 = 0; k8 < 4; ++k8) {
                uint32_t a[2][4];
                #pragma unroll
                for (int mt = 0; mt < 2; ++mt) {
                    const uint32_t* Ar = Abase + (mt*16 + g)*astr + k8*8 + tq;
                    a[mt][0] = Ar[0];
                    a[mt][1] = Ar[8*astr];
                    a[mt][2] = Ar[4];
                    a[mt][3] = Ar[8*astr + 4];
                }
                const uint32_t* Bc = Wbuf + (k8*8 + tq)*WSTR + wn*64 + g;
                #pragma unroll
                for (int nt = 0; nt < 8; ++nt) {
                    uint32_t b0 = Bc[nt*8];
                    uint32_t b1v = Bc[4*WSTR + nt*8];
                    mma_tf32(acc[0][nt], a[0], b0, b1v);
                    mma_tf32(acc[1][nt], a[1], b0, b1v);
                }
            }
        }

        if (kc < 11) {
            uint32_t* Wn = sW + ((kc+1) & 1) * (32 * WSTR);
            #pragma unroll
            for (int l = 0; l < 4; ++l) {
                int id  = tid + l * 512;
                int row = id >> 6, c4 = id & 63;
                uint32_t* p = &Wn[row * WSTR + c4 * 4];
                p[0] = f2tf32(wreg[l].x); p[1] = f2tf32(wreg[l].y);
                p[2] = f2tf32(wreg[l].z); p[3] = f2tf32(wreg[l].w);
            }
        }
    }

    float ss[2][2] = {};
    #pragma unroll
    for (int mt = 0; mt < 2; ++mt)
        #pragma unroll
        for (int nt = 0; nt < 8; ++nt) {
            const int col = wn*64 + nt*8 + tq*2;
            #pragma unroll
            for (int h = 0; h < 2; ++h)
                #pragma unroll
                for (int pr = 0; pr < 2; ++pr) {
                    float x = acc[mt][nt][h*2+pr] + sB2[col+pr];
                    float p = (x > 0.f) ? (x + 1.f) : __expf(x);
                    acc[mt][nt][h*2+pr] = p;
                    ss[mt][h] = fmaf(p, p, ss[mt][h]);
                }
        }
    #pragma unroll
    for (int m = 1; m <= 2; m <<= 1)
        #pragma unroll
        for (int mt = 0; mt < 2; ++mt)
            #pragma unroll
            for (int h = 0; h < 2; ++h)
                ss[mt][h] += __shfl_xor_sync(0xffffffffu, ss[mt][h], m);
    if (tq == 0) {
        #pragma unroll
        for (int mt = 0; mt < 2; ++mt)
            #pragma unroll
            for (int h = 0; h < 2; ++h)
                sPrt[wn*128 + wm*32 + mt*16 + 8*h + g] = ss[mt][h];
    }
    __syncthreads();
    if (tid < 128)
        sInv[tid] = 1.f / (sqrtf(sPrt[tid] + sPrt[128+tid] +
                                 sPrt[256+tid] + sPrt[384+tid]) + 1e-6f);
    __syncthreads();

    #pragma unroll
    for (int mt = 0; mt < 2; ++mt)
        #pragma unroll
        for (int h = 0; h < 2; ++h) {
            const int row = wm*32 + mt*16 + 8*h + g;
            const float inv = sInv[row];
            float* dr = dst + (size_t)(tok0 + row) * FF;
            #pragma unroll
            for (int nt = 0; nt < 8; ++nt) {
                const int col = wn*64 + nt*8 + tq*2;
                dr[col]   = acc[mt][nt][h*2]   * inv;
                dr[col+1] = acc[mt][nt][h*2+1] * inv;
            }
        }
}

// ---------------------------------------------------------------------------
// kv kernel (tf32 mma): per (head, ksplit) CTA, kvp[F=256, D=128] partial
// over 512 seq positions + ksum partial. 512 threads, warp grid 4M x 4N,
// warp tile 64x32 (mt=4, nt=4). A[m=f][k=seq] = sP[k][f] (transposed access).
// SMEM: sP[32][264] + sV[32][136] tf32 = 51200 B dynamic.
// ---------------------------------------------------------------------------
#define PSTR 264
#define VSTR 136
#define KV_SMEM ((32*PSTR + 32*VSTR) * 4)

__global__ void __launch_bounds__(512) kv_mma_kernel(const float* __restrict__ v)
{
    extern __shared__ uint32_t skv[];
    uint32_t* sP = skv;                 // [32][264]
    uint32_t* sV = skv + 32*PSTR;       // [32][136]

    const int hh = blockIdx.x;
    const int ks = blockIdx.y;
    const int tid  = threadIdx.x;
    const int lane = tid & 31;
    const int wid  = tid >> 5;
    const int g  = lane >> 2;
    const int tq = lane & 3;
    const int wm = wid & 3;      // F tiles of 64
    const int wn = wid >> 2;     // D tiles of 32

    const float4* phik4 = reinterpret_cast<const float4*>(
        g_phi_k + ((size_t)hh * NSEQ + (size_t)ks * 512) * FF);
    const float4* vv4 = reinterpret_cast<const float4*>(
        v + ((size_t)hh * NSEQ + (size_t)ks * 512) * DD);

    float acc[4][4][4];
    #pragma unroll
    for (int mt = 0; mt < 4; ++mt)
        #pragma unroll
        for (int nt = 0; nt < 4; ++nt)
            #pragma unroll
            for (int e = 0; e < 4; ++e) acc[mt][nt][e] = 0.f;
    float ksacc = 0.f;

    for (int nb = 0; nb < 512; nb += 32) {
        __syncthreads();
        // phi_k tile [32][256] -> sP tf32
        #pragma unroll
        for (int l = 0; l < 4; ++l) {
            int id = tid + l * 512;            // 0..2047
            int row = id >> 6, c4 = id & 63;
            float4 t = phik4[(nb + row) * 64 + c4];
            uint32_t* p = &sP[row * PSTR + c4 * 4];
            p[0] = f2tf32(t.x); p[1] = f2tf32(t.y);
            p[2] = f2tf32(t.z); p[3] = f2tf32(t.w);
        }
        // v tile [32][128] -> sV tf32
        #pragma unroll
        for (int l = 0; l < 2; ++l) {
            int id = tid + l * 512;            // 0..1023
            int row = id >> 5, c4 = id & 31;
            float4 t = vv4[(nb + row) * 32 + c4];
            uint32_t* p = &sV[row * VSTR + c4 * 4];
            p[0] = f2tf32(t.x); p[1] = f2tf32(t.y);
            p[2] = f2tf32(t.z); p[3] = f2tf32(t.w);
        }
        __syncthreads();

        // ksum partial (threads 0..255 own feature f=tid)
        if (tid < 256) {
            #pragma unroll
            for (int r = 0; r < 32; ++r)
                ksacc += __uint_as_float(sP[r * PSTR + tid]);
        }

        #pragma unroll
        for (int k8 = 0; k8 < 4; ++k8) {
            const int r0 = (k8*8 + tq) * PSTR;
            const int r1 = (k8*8 + tq + 4) * PSTR;
            uint32_t a[4][4];
            #pragma unroll
            for (int mt = 0; mt < 4; ++mt) {
                const int m = wm*64 + mt*16 + g;
                a[mt][0] = sP[r0 + m];
                a[mt][1] = sP[r0 + m + 8];
                a[mt][2] = sP[r1 + m];
                a[mt][3] = sP[r1 + m + 8];
            }
            const int v0 = (k8*8 + tq) * VSTR;
            const int v1 = (k8*8 + tq + 4) * VSTR;
            #pragma unroll
            for (int nt = 0; nt < 4; ++nt) {
                const int n = wn*32 + nt*8 + g;
                uint32_t b0 = sV[v0 + n];
                uint32_t b1 = sV[v1 + n];
                #pragma unroll
                for (int mt = 0; mt < 4; ++mt)
                    mma_tf32(acc[mt][nt], a[mt], b0, b1);
            }
        }
    }

    // write partials
    float* outp = g_kvp + ((size_t)ks * BH + hh) * FF * DD;
    #pragma unroll
    for (int mt = 0; mt < 4; ++mt)
        #pragma unroll
        for (int h = 0; h < 2; ++h) {
            const int f = wm*64 + mt*16 + 8*h + g;
            #pragma unroll
            for (int nt = 0; nt < 4; ++nt) {
                const int d = wn*32 + nt*8 + tq*2;
                *reinterpret_cast<float2*>(outp + (size_t)f * DD + d) =
                    make_float2(acc[mt][nt][h*2], acc[mt][nt][h*2+1]);
            }
        }
    if (tid < 256)
        g_ksp[((size_t)ks * BH + hh) * FF + tid] = ksacc;
}

// ---------------------------------------------------------------------------
// reduce kernel (unchanged)
// ---------------------------------------------------------------------------
__global__ void reduce_kernel()
{
    const int NKV = BH * FF * DD;
    const int NKS = BH * FF;
    int i = blockIdx.x * blockDim.x + threadIdx.x;
    if (i < NKV) {
        float s = 0.f;
        #pragma unroll
        for (int p = 0; p < KSPLIT; ++p) s += g_kvp[(size_t)p * NKV + i];
        g_kv[i] = s;
    } else {
        int j = i - NKV;
        if (j < NKS) {
            float s = 0.f;
            #pragma unroll
            for (int p = 0; p < KSPLIT; ++p) s += g_ksp[(size_t)p * NKS + j];
            g_ksum[j] = s;
        }
    }
}

// ---------------------------------------------------------------------------
// qkv kernel (tf32 mma): per (head, 128-token tile) CTA,
// out[128, D=128] = phi_q @ kv / max(phi_q @ ksum, eps). K=256 in 32-chunks.
// 512 threads, warp grid 4M x 4N, warp tile 32x32 (mt=2, nt=4).
// ---------------------------------------------------------------------------
#define QASTR 36
#define QBSTR 136

__global__ void __launch_bounds__(512) qkv_mma_kernel(float* __restrict__ out)
{
    __shared__ uint32_t sA[128*QASTR];   // phi_q chunk [128][32] (padded)
    __shared__ uint32_t sB[32*QBSTR];    // kv chunk [32][128] (padded)
    __shared__ float sKs[32];
    __shared__ float sDen[128];

    const int hh = blockIdx.x;
    const int m0 = blockIdx.y * 128;
    const int tid  = threadIdx.x;
    const int lane = tid & 31;
    const int wid  = tid >> 5;
    const int g  = lane >> 2;
    const int tq = lane & 3;
    const int wm = wid & 3;      // token tiles of 32
    const int wn = wid >> 2;     // D tiles of 32

    const float4* phiq4 = reinterpret_cast<const float4*>(
        g_phi_q + ((size_t)hh * NSEQ + m0) * FF);
    const float4* kv4 = reinterpret_cast<const float4*>(
        g_kv + (size_t)hh * FF * DD);

    float acc[2][4][4];
    #pragma unroll
    for (int mt = 0; mt < 2; ++mt)
        #pragma unroll
        for (int nt = 0; nt < 4; ++nt)
            #pragma unroll
            for (int e = 0; e < 4; ++e) acc[mt][nt][e] = 0.f;
    float den = 0.f;

    for (int kc = 0; kc < 8; ++kc) {
        __syncthreads();
        // phi_q chunk [128 tokens][32 f] -> sA tf32
        #pragma unroll
        for (int l = 0; l < 2; ++l) {
            int id = tid + l * 512;            // 0..1023
            int row = id >> 3, c4 = id & 7;
            float4 t = phiq4[row * 64 + kc * 8 + c4];
            uint32_t* p = &sA[row * QASTR + c4 * 4];
            p[0] = f2tf32(t.x); p[1] = f2tf32(t.y);
            p[2] = f2tf32(t.z); p[3] = f2tf32(t.w);
        }
        // kv chunk [32 f][128 d] -> sB tf32
        #pragma unroll
        for (int l = 0; l < 2; ++l) {
            int id = tid + l * 512;
            int row = id >> 5, c4 = id & 31;
            float4 t = kv4[(kc * 32 + row) * 32 + c4];
            uint32_t* p = &sB[row * QBSTR + c4 * 4];
            p[0] = f2tf32(t.x); p[1] = f2tf32(t.y);
            p[2] = f2tf32(t.z); p[3] = f2tf32(t.w);
        }
        if (tid < 32) sKs[tid] = g_ksum[(size_t)hh * FF + kc * 32 + tid];
        __syncthreads();

        // den partial (threads 0..127 own token = tid; sA values ARE fp32)
        if (tid < 128) {
            #pragma unroll
            for (int kk = 0; kk < 32; ++kk)
                den = fmaf(__uint_as_float(sA[tid * QASTR + kk]), sKs[kk], den);
        }

        #pragma unroll
        for (int k8 = 0; k8 < 4; ++k8) {
            uint32_t a[2][4];
            #pragma unroll
            for (int mt = 0; mt < 2; ++mt) {
                const uint32_t* Ar = sA + (wm*32 + mt*16 + g) * QASTR + k8*8 + tq;
                a[mt][0] = Ar[0];
                a[mt][1] = Ar[8*QASTR];
                a[mt][2] = Ar[4];
                a[mt][3] = Ar[8*QASTR + 4];
            }
            const int v0 = (k8*8 + tq) * QBSTR;
            const int v1 = (k8*8 + tq + 4) * QBSTR;
            #pragma unroll
            for (int nt = 0; nt < 4; ++nt) {
                const int n = wn*32 + nt*8 + g;
                uint32_t b0 = sB[v0 + n];
                uint32_t b1 = sB[v1 + n];
                mma_tf32(acc[0][nt], a[0], b0, b1);
                mma_tf32(acc[1][nt], a[1], b0, b1);
            }
        }
    }

    if (tid < 128) sDen[tid] = den;
    __syncthreads();

    float* op = out + ((size_t)hh * NSEQ + m0) * DD;
    #pragma unroll
    for (int mt = 0; mt < 2; ++mt)
        #pragma unroll
        for (int h = 0; h < 2; ++h) {
            const int row = wm*32 + mt*16 + 8*h + g;
            const float invd = 1.f / fmaxf(sDen[row], 1e-6f);
            #pragma unroll
            for (int nt = 0; nt < 4; ++nt) {
                const int d = wn*32 + nt*8 + tq*2;
                *reinterpret_cast<float2*>(op + (size_t)row * DD + d) =
                    make_float2(acc[mt][nt][h*2] * invd, acc[mt][nt][h*2+1] * invd);
            }
        }
}

// ---------------------------------------------------------------------------
extern "C" void kernel_launch(void* const* d_in, const int* in_sizes, int n_in,
                              void* d_out, int out_size)
{
    (void)in_sizes; (void)n_in; (void)out_size;
    const float* q  = (const float*)d_in[0];
    const float* k  = (const float*)d_in[1];
    const float* v  = (const float*)d_in[2];
    const float* W1 = (const float*)d_in[3];
    const float* b1 = (const float*)d_in[4];
    const float* W2 = (const float*)d_in[5];
    const float* b2 = (const float*)d_in[6];
    float* out = (float*)d_out;

    cudaFuncSetAttribute(phi_mma_kernel, cudaFuncAttributeMaxDynamicSharedMemorySize, PHI_SMEM);
    cudaFuncSetAttribute(kv_mma_kernel,  cudaFuncAttributeMaxDynamicSharedMemorySize, KV_SMEM);

    phi_mma_kernel<<<2048, 512, PHI_SMEM>>>(q, k, W1, b1, W2, b2);
    kv_mma_kernel<<<dim3(32, KSPLIT), 512, KV_SMEM>>>(v);
    {
        const int total = BH*FF*DD + BH*FF;
        reduce_kernel<<<(total + 255) / 256, 256>>>();
    }
    qkv_mma_kernel<<<dim3(32, 32), 512>>>(out);
}

// round 6
// speedup vs baseline: 2.3415x; 1.0178x over previous
#include <cuda_runtime.h>
#include <math.h>
#include <stdint.h>

// Problem constants
#define BH    32
#define NSEQ  4096
#define DD    128
#define FF    256
#define NTOK  (BH*NSEQ)
#define KSPLIT 8

// Scratch (device globals: allocation-free rule)
__device__ float g_phi_q[(size_t)NTOK*FF];
__device__ float g_phi_k[(size_t)NTOK*FF];
__device__ float g_kvp[(size_t)KSPLIT*BH*FF*DD];
__device__ float g_ksp[(size_t)KSPLIT*BH*FF];
__device__ float g_kv[(size_t)BH*FF*DD];
__device__ float g_ksum[(size_t)BH*FF];

// ---------------------------------------------------------------------------
// helpers
// ---------------------------------------------------------------------------
__device__ __forceinline__ uint32_t f2tf32(float f) {
    uint32_t r; asm("cvt.rna.tf32.f32 %0, %1;" : "=r"(r) : "f"(f)); return r;
}
__device__ __forceinline__ void mma_tf32(float* d, const uint32_t* a,
                                         uint32_t b0, uint32_t b1) {
    asm volatile("mma.sync.aligned.m16n8k8.row.col.f32.tf32.tf32.f32 "
                 "{%0,%1,%2,%3}, {%4,%5,%6,%7}, {%8,%9}, {%0,%1,%2,%3};"
                 : "+f"(d[0]), "+f"(d[1]), "+f"(d[2]), "+f"(d[3])
                 : "r"(a[0]), "r"(a[1]), "r"(a[2]), "r"(a[3]),
                   "r"(b0), "r"(b1));
}

// Fragment-major layouts (tile stride 132 floats to spread staging banks).
// A fragment slots: 0=A[g][tq] 1=A[g+8][tq] 2=A[g][tq+4] 3=A[g+8][tq+4]
__device__ __forceinline__ int afrag(int row, int col) {
    int tile = (col >> 5)*32 + (row >> 5)*8 + ((row >> 4) & 1)*4 + ((col >> 3) & 3);
    return tile*132 + ((row & 7)*4 + (col & 3))*4
         + (((row >> 3) & 1) + (((col >> 2) & 1) << 1));
}
// B fragment slots per lane(g*4+tq): {b0(nt even), b1(nt even), b0(nt odd), b1(nt odd)}
// b0 = W[k8*8+tq][n], b1 = W[k8*8+tq+4][n]
__device__ __forceinline__ int bfrag(int kk, int n) {   // kk 0..31 in chunk, n 0..255
    int tile = ((n >> 6)*4 + (kk >> 3))*4 + ((n >> 4) & 3);
    return tile*132 + ((n & 7)*4 + (kk & 3))*4
         + ((((n >> 3) & 1) << 1) | ((kk >> 2) & 1));
}

// ---------------------------------------------------------------------------
// phi kernel: fragment-major tf32 mma. 128 tokens/CTA, 512 threads.
// SMEM floats: sAfrag @0 (256 tiles * 132 = 33792), sWfrag @33792 (2 x 8448),
// sB1 @50688, sB2 @50944, sPrt @51200(512), sInv @51712(128). 207360 B.
// ---------------------------------------------------------------------------
#define WFRAG_FLOATS 8448
#define OFFW2   33792
#define OFFB1_2 50688
#define OFFB2_2 50944
#define OFFPRT2 51200
#define OFFINV2 51712
#define PHI_SMEM (51840 * 4)

__global__ void __launch_bounds__(512) phi_mma_kernel(
    const float* __restrict__ q, const float* __restrict__ k,
    const float* __restrict__ W1, const float* __restrict__ b1,
    const float* __restrict__ W2, const float* __restrict__ b2)
{
    extern __shared__ float smf[];
    uint32_t* sAu = reinterpret_cast<uint32_t*>(smf);
    uint32_t* sWu = reinterpret_cast<uint32_t*>(smf + OFFW2);
    float* sB1  = smf + OFFB1_2;
    float* sB2  = smf + OFFB2_2;
    float* sPrt = smf + OFFPRT2;
    float* sInv = smf + OFFINV2;

    const int tid  = threadIdx.x;
    const int wid  = tid >> 5;
    const int lane = tid & 31;
    const int g    = lane >> 2;
    const int tq   = lane & 3;
    const int wm   = wid & 3;
    const int wn   = wid >> 2;

    const int bid = blockIdx.x;
    const float* src = (bid < 1024) ? q : k;
    float*       dst = (bid < 1024) ? g_phi_q : g_phi_k;
    const int tok0 = (bid & 1023) * 128;

    // ---- stage X [128][128] into A-fragment layout (tf32) ----
    {
        const float4* s4 = reinterpret_cast<const float4*>(src + (size_t)tok0 * DD);
        #pragma unroll
        for (int l = 0; l < 8; ++l) {
            int id  = tid + l * 512;
            int row = id >> 5, c4 = id & 31;
            float4 v = s4[row * 32 + c4];
            int colb = c4 * 4;
            sAu[afrag(row, colb)]     = f2tf32(v.x);
            sAu[afrag(row, colb + 1)] = f2tf32(v.y);
            sAu[afrag(row, colb + 2)] = f2tf32(v.z);
            sAu[afrag(row, colb + 3)] = f2tf32(v.w);
        }
    }
    if (tid < 256) { sB1[tid] = b1[tid]; sB2[tid] = b2[tid]; }

    // ---- stage W chunk 0 (W1 rows 0..31) into B-fragment buf0 ----
    {
        const float4* wp = reinterpret_cast<const float4*>(W1);
        #pragma unroll
        for (int l = 0; l < 4; ++l) {
            int id = tid + l * 512;          // 0..2047: kk=id>>6, n4=id&63
            int kk = id >> 6, nb = (id & 63) * 4;
            float4 w = wp[id];
            sWu[bfrag(kk, nb)]     = f2tf32(w.x);
            sWu[bfrag(kk, nb + 1)] = f2tf32(w.y);
            sWu[bfrag(kk, nb + 2)] = f2tf32(w.z);
            sWu[bfrag(kk, nb + 3)] = f2tf32(w.w);
        }
    }

    float acc[2][8][4];
    #pragma unroll
    for (int mt = 0; mt < 2; ++mt)
        #pragma unroll
        for (int nt = 0; nt < 8; ++nt)
            #pragma unroll
            for (int e = 0; e < 4; ++e) acc[mt][nt][e] = 0.f;

    // ---- main chunk loop: kc 0..3 stage1, 4..11 stage2 ----
    for (int kc = 0; kc < 12; ++kc) {
        if (kc == 4) {
            // ===== epilogue 1: H = silu(acc + b1) -> A-fragment layout =====
            __syncthreads();   // kc=3 compute done reading X frags
            #pragma unroll
            for (int mt = 0; mt < 2; ++mt)
                #pragma unroll
                for (int nt = 0; nt < 8; ++nt) {
                    const int col = wn*64 + nt*8 + tq*2;
                    #pragma unroll
                    for (int h = 0; h < 2; ++h) {
                        const int row = wm*32 + mt*16 + 8*h + g;
                        #pragma unroll
                        for (int pr = 0; pr < 2; ++pr) {
                            float x = acc[mt][nt][h*2+pr] + sB1[col+pr];
                            float s = x / (1.f + __expf(-x));
                            sAu[afrag(row, col + pr)] = f2tf32(s);
                            acc[mt][nt][h*2+pr] = 0.f;
                        }
                    }
                }
        }
        __syncthreads();   // W buf(kc&1) stores visible; (kc==4) H visible

        // prefetch next W chunk into registers
        float4 wreg[4];
        if (kc < 11) {
            int nkc = kc + 1;
            const float4* wp = reinterpret_cast<const float4*>(
                (nkc < 4) ? (W1 + nkc*32*256) : (W2 + (nkc-4)*32*256));
            #pragma unroll
            for (int l = 0; l < 4; ++l) wreg[l] = wp[tid + l * 512];
        }

        // ---- compute on buf(kc&1): all operand loads are LDS.128 ----
        {
            const int tb = ((kc < 4) ? kc : (kc - 4)) * 32 + wm * 8;
            const uint32_t* wb = sWu + (kc & 1) * WFRAG_FLOATS;

            #pragma unroll
            for (int k8 = 0; k8 < 4; ++k8) {
                uint4 t0 = *reinterpret_cast<const uint4*>(
                    sAu + (tb + k8) * 132 + lane * 4);
                uint4 t1 = *reinterpret_cast<const uint4*>(
                    sAu + (tb + 4 + k8) * 132 + lane * 4);
                uint32_t a0[4] = {t0.x, t0.y, t0.z, t0.w};
                uint32_t a1[4] = {t1.x, t1.y, t1.z, t1.w};
                #pragma unroll
                for (int p = 0; p < 4; ++p) {
                    uint4 b = *reinterpret_cast<const uint4*>(
                        wb + ((wn*4 + k8)*4 + p) * 132 + lane * 4);
                    mma_tf32(acc[0][2*p],   a0, b.x, b.y);
                    mma_tf32(acc[0][2*p+1], a0, b.z, b.w);
                    mma_tf32(acc[1][2*p],   a1, b.x, b.y);
                    mma_tf32(acc[1][2*p+1], a1, b.z, b.w);
                }
            }
        }

        // store prefetched chunk into other buffer (fragment order)
        if (kc < 11) {
            uint32_t* Wn = sWu + ((kc+1) & 1) * WFRAG_FLOATS;
            #pragma unroll
            for (int l = 0; l < 4; ++l) {
                int id = tid + l * 512;
                int kk = id >> 6, nb = (id & 63) * 4;
                Wn[bfrag(kk, nb)]     = f2tf32(wreg[l].x);
                Wn[bfrag(kk, nb + 1)] = f2tf32(wreg[l].y);
                Wn[bfrag(kk, nb + 2)] = f2tf32(wreg[l].z);
                Wn[bfrag(kk, nb + 3)] = f2tf32(wreg[l].w);
            }
        }
    }

    // ===== epilogue 2: p = elu(acc + b2)+1, row L2 norm, write =====
    float ss[2][2] = {};
    #pragma unroll
    for (int mt = 0; mt < 2; ++mt)
        #pragma unroll
        for (int nt = 0; nt < 8; ++nt) {
            const int col = wn*64 + nt*8 + tq*2;
            #pragma unroll
            for (int h = 0; h < 2; ++h)
                #pragma unroll
                for (int pr = 0; pr < 2; ++pr) {
                    float x = acc[mt][nt][h*2+pr] + sB2[col+pr];
                    float p = (x > 0.f) ? (x + 1.f) : __expf(x);
                    acc[mt][nt][h*2+pr] = p;
                    ss[mt][h] = fmaf(p, p, ss[mt][h]);
                }
        }
    #pragma unroll
    for (int m = 1; m <= 2; m <<= 1)
        #pragma unroll
        for (int mt = 0; mt < 2; ++mt)
            #pragma unroll
            for (int h = 0; h < 2; ++h)
                ss[mt][h] += __shfl_xor_sync(0xffffffffu, ss[mt][h], m);
    if (tq == 0) {
        #pragma unroll
        for (int mt = 0; mt < 2; ++mt)
            #pragma unroll
            for (int h = 0; h < 2; ++h)
                sPrt[wn*128 + wm*32 + mt*16 + 8*h + g] = ss[mt][h];
    }
    __syncthreads();
    if (tid < 128)
        sInv[tid] = 1.f / (sqrtf(sPrt[tid] + sPrt[128+tid] +
                                 sPrt[256+tid] + sPrt[384+tid]) + 1e-6f);
    __syncthreads();

    #pragma unroll
    for (int mt = 0; mt < 2; ++mt)
        #pragma unroll
        for (int h = 0; h < 2; ++h) {
            const int row = wm*32 + mt*16 + 8*h + g;
            const float inv = sInv[row];
            float* dr = dst + (size_t)(tok0 + row) * FF;
            #pragma unroll
            for (int nt = 0; nt < 8; ++nt) {
                const int col = wn*64 + nt*8 + tq*2;
                dr[col]   = acc[mt][nt][h*2]   * inv;
                dr[col+1] = acc[mt][nt][h*2+1] * inv;
            }
        }
}

// ---------------------------------------------------------------------------
// kv kernel (tf32 mma, unchanged from R4 — passing, ~105us)
// ---------------------------------------------------------------------------
#define PSTR 264
#define VSTR 136
#define KV_SMEM ((32*PSTR + 32*VSTR) * 4)

__global__ void __launch_bounds__(512) kv_mma_kernel(const float* __restrict__ v)
{
    extern __shared__ uint32_t skv[];
    uint32_t* sP = skv;
    uint32_t* sV = skv + 32*PSTR;

    const int hh = blockIdx.x;
    const int ks = blockIdx.y;
    const int tid  = threadIdx.x;
    const int lane = tid & 31;
    const int wid  = tid >> 5;
    const int g  = lane >> 2;
    const int tq = lane & 3;
    const int wm = wid & 3;
    const int wn = wid >> 2;

    const float4* phik4 = reinterpret_cast<const float4*>(
        g_phi_k + ((size_t)hh * NSEQ + (size_t)ks * 512) * FF);
    const float4* vv4 = reinterpret_cast<const float4*>(
        v + ((size_t)hh * NSEQ + (size_t)ks * 512) * DD);

    float acc[4][4][4];
    #pragma unroll
    for (int mt = 0; mt < 4; ++mt)
        #pragma unroll
        for (int nt = 0; nt < 4; ++nt)
            #pragma unroll
            for (int e = 0; e < 4; ++e) acc[mt][nt][e] = 0.f;
    float ksacc = 0.f;

    for (int nb = 0; nb < 512; nb += 32) {
        __syncthreads();
        #pragma unroll
        for (int l = 0; l < 4; ++l) {
            int id = tid + l * 512;
            int row = id >> 6, c4 = id & 63;
            float4 t = phik4[(nb + row) * 64 + c4];
            uint32_t* p = &sP[row * PSTR + c4 * 4];
            p[0] = f2tf32(t.x); p[1] = f2tf32(t.y);
            p[2] = f2tf32(t.z); p[3] = f2tf32(t.w);
        }
        #pragma unroll
        for (int l = 0; l < 2; ++l) {
            int id = tid + l * 512;
            int row = id >> 5, c4 = id & 31;
            float4 t = vv4[(nb + row) * 32 + c4];
            uint32_t* p = &sV[row * VSTR + c4 * 4];
            p[0] = f2tf32(t.x); p[1] = f2tf32(t.y);
            p[2] = f2tf32(t.z); p[3] = f2tf32(t.w);
        }
        __syncthreads();

        if (tid < 256) {
            #pragma unroll
            for (int r = 0; r < 32; ++r)
                ksacc += __uint_as_float(sP[r * PSTR + tid]);
        }

        #pragma unroll
        for (int k8 = 0; k8 < 4; ++k8) {
            const int r0 = (k8*8 + tq) * PSTR;
            const int r1 = (k8*8 + tq + 4) * PSTR;
            uint32_t a[4][4];
            #pragma unroll
            for (int mt = 0; mt < 4; ++mt) {
                const int m = wm*64 + mt*16 + g;
                a[mt][0] = sP[r0 + m];
                a[mt][1] = sP[r0 + m + 8];
                a[mt][2] = sP[r1 + m];
                a[mt][3] = sP[r1 + m + 8];
            }
            const int v0 = (k8*8 + tq) * VSTR;
            const int v1 = (k8*8 + tq + 4) * VSTR;
            #pragma unroll
            for (int nt = 0; nt < 4; ++nt) {
                const int n = wn*32 + nt*8 + g;
                uint32_t b0 = sV[v0 + n];
                uint32_t b1 = sV[v1 + n];
                #pragma unroll
                for (int mt = 0; mt < 4; ++mt)
                    mma_tf32(acc[mt][nt], a[mt], b0, b1);
            }
        }
    }

    float* outp = g_kvp + ((size_t)ks * BH + hh) * FF * DD;
    #pragma unroll
    for (int mt = 0; mt < 4; ++mt)
        #pragma unroll
        for (int h = 0; h < 2; ++h) {
            const int f = wm*64 + mt*16 + 8*h + g;
            #pragma unroll
            for (int nt = 0; nt < 4; ++nt) {
                const int d = wn*32 + nt*8 + tq*2;
                *reinterpret_cast<float2*>(outp + (size_t)f * DD + d) =
                    make_float2(acc[mt][nt][h*2], acc[mt][nt][h*2+1]);
            }
        }
    if (tid < 256)
        g_ksp[((size_t)ks * BH + hh) * FF + tid] = ksacc;
}

// ---------------------------------------------------------------------------
// reduce kernel (unchanged)
// ---------------------------------------------------------------------------
__global__ void reduce_kernel()
{
    const int NKV = BH * FF * DD;
    const int NKS = BH * FF;
    int i = blockIdx.x * blockDim.x + threadIdx.x;
    if (i < NKV) {
        float s = 0.f;
        #pragma unroll
        for (int p = 0; p < KSPLIT; ++p) s += g_kvp[(size_t)p * NKV + i];
        g_kv[i] = s;
    } else {
        int j = i - NKV;
        if (j < NKS) {
            float s = 0.f;
            #pragma unroll
            for (int p = 0; p < KSPLIT; ++p) s += g_ksp[(size_t)p * NKS + j];
            g_ksum[j] = s;
        }
    }
}

// ---------------------------------------------------------------------------
// qkv kernel (tf32 mma, unchanged from R4 — passing, 114us)
// ---------------------------------------------------------------------------
#define QASTR 36
#define QBSTR 136

__global__ void __launch_bounds__(512) qkv_mma_kernel(float* __restrict__ out)
{
    __shared__ uint32_t sA[128*QASTR];
    __shared__ uint32_t sB[32*QBSTR];
    __shared__ float sKs[32];
    __shared__ float sDen[128];

    const int hh = blockIdx.x;
    const int m0 = blockIdx.y * 128;
    const int tid  = threadIdx.x;
    const int lane = tid & 31;
    const int wid  = tid >> 5;
    const int g  = lane >> 2;
    const int tq = lane & 3;
    const int wm = wid & 3;
    const int wn = wid >> 2;

    const float4* phiq4 = reinterpret_cast<const float4*>(
        g_phi_q + ((size_t)hh * NSEQ + m0) * FF);
    const float4* kv4 = reinterpret_cast<const float4*>(
        g_kv + (size_t)hh * FF * DD);

    float acc[2][4][4];
    #pragma unroll
    for (int mt = 0; mt < 2; ++mt)
        #pragma unroll
        for (int nt = 0; nt < 4; ++nt)
            #pragma unroll
            for (int e = 0; e < 4; ++e) acc[mt][nt][e] = 0.f;
    float den = 0.f;

    for (int kc = 0; kc < 8; ++kc) {
        __syncthreads();
        #pragma unroll
        for (int l = 0; l < 2; ++l) {
            int id = tid + l * 512;
            int row = id >> 3, c4 = id & 7;
            float4 t = phiq4[row * 64 + kc * 8 + c4];
            uint32_t* p = &sA[row * QASTR + c4 * 4];
            p[0] = f2tf32(t.x); p[1] = f2tf32(t.y);
            p[2] = f2tf32(t.z); p[3] = f2tf32(t.w);
        }
        #pragma unroll
        for (int l = 0; l < 2; ++l) {
            int id = tid + l * 512;
            int row = id >> 5, c4 = id & 31;
            float4 t = kv4[(kc * 32 + row) * 32 + c4];
            uint32_t* p = &sB[row * QBSTR + c4 * 4];
            p[0] = f2tf32(t.x); p[1] = f2tf32(t.y);
            p[2] = f2tf32(t.z); p[3] = f2tf32(t.w);
        }
        if (tid < 32) sKs[tid] = g_ksum[(size_t)hh * FF + kc * 32 + tid];
        __syncthreads();

        if (tid < 128) {
            #pragma unroll
            for (int kk = 0; kk < 32; ++kk)
                den = fmaf(__uint_as_float(sA[tid * QASTR + kk]), sKs[kk], den);
        }

        #pragma unroll
        for (int k8 = 0; k8 < 4; ++k8) {
            uint32_t a[2][4];
            #pragma unroll
            for (int mt = 0; mt < 2; ++mt) {
                const uint32_t* Ar = sA + (wm*32 + mt*16 + g) * QASTR + k8*8 + tq;
                a[mt][0] = Ar[0];
                a[mt][1] = Ar[8*QASTR];
                a[mt][2] = Ar[4];
                a[mt][3] = Ar[8*QASTR + 4];
            }
            const int v0 = (k8*8 + tq) * QBSTR;
            const int v1 = (k8*8 + tq + 4) * QBSTR;
            #pragma unroll
            for (int nt = 0; nt < 4; ++nt) {
                const int n = wn*32 + nt*8 + g;
                uint32_t b0 = sB[v0 + n];
                uint32_t b1 = sB[v1 + n];
                mma_tf32(acc[0][nt], a[0], b0, b1);
                mma_tf32(acc[1][nt], a[1], b0, b1);
            }
        }
    }

    if (tid < 128) sDen[tid] = den;
    __syncthreads();

    float* op = out + ((size_t)hh * NSEQ + m0) * DD;
    #pragma unroll
    for (int mt = 0; mt < 2; ++mt)
        #pragma unroll
        for (int h = 0; h < 2; ++h) {
            const int row = wm*32 + mt*16 + 8*h + g;
            const float invd = 1.f / fmaxf(sDen[row], 1e-6f);
            #pragma unroll
            for (int nt = 0; nt < 4; ++nt) {
                const int d = wn*32 + nt*8 + tq*2;
                *reinterpret_cast<float2*>(op + (size_t)row * DD + d) =
                    make_float2(acc[mt][nt][h*2] * invd, acc[mt][nt][h*2+1] * invd);
            }
        }
}

// ---------------------------------------------------------------------------
extern "C" void kernel_launch(void* const* d_in, const int* in_sizes, int n_in,
                              void* d_out, int out_size)
{
    (void)in_sizes; (void)n_in; (void)out_size;
    const float* q  = (const float*)d_in[0];
    const float* k  = (const float*)d_in[1];
    const float* v  = (const float*)d_in[2];
    const float* W1 = (const float*)d_in[3];
    const float* b1 = (const float*)d_in[4];
    const float* W2 = (const float*)d_in[5];
    const float* b2 = (const float*)d_in[6];
    float* out = (float*)d_out;

    cudaFuncSetAttribute(phi_mma_kernel, cudaFuncAttributeMaxDynamicSharedMemorySize, PHI_SMEM);
    cudaFuncSetAttribute(kv_mma_kernel,  cudaFuncAttributeMaxDynamicSharedMemorySize, KV_SMEM);

    phi_mma_kernel<<<2048, 512, PHI_SMEM>>>(q, k, W1, b1, W2, b2);
    kv_mma_kernel<<<dim3(32, KSPLIT), 512, KV_SMEM>>>(v);
    {
        const int total = BH*FF*DD + BH*FF;
        reduce_kernel<<<(total + 255) / 256, 256>>>();
    }
    qkv_mma_kernel<<<dim3(32, 32), 512>>>(out);
}

// round 8
// speedup vs baseline: 2.8054x; 1.1981x over previous
#include <cuda_runtime.h>
#include <math.h>
#include <stdint.h>

// Problem constants
#define BH    32
#define NSEQ  4096
#define DD    128
#define FF    256
#define NTOK  (BH*NSEQ)
#define KSPLIT 8

// Scratch (device globals: allocation-free rule)
__device__ float g_phi_q[(size_t)NTOK*FF];
__device__ float g_phi_k[(size_t)NTOK*FF];
__device__ float g_kvp[(size_t)KSPLIT*BH*FF*DD];
__device__ float g_ksp[(size_t)KSPLIT*BH*FF];
__device__ float g_kv[(size_t)BH*FF*DD];
__device__ float g_ksum[(size_t)BH*FF];
__device__ float g_Wfrag[12*8192];       // pre-converted, fragment-layout W chunks
__device__ float g_vr[(size_t)NTOK*DD];  // tf32-rna-rounded v

// ---------------------------------------------------------------------------
// helpers
// ---------------------------------------------------------------------------
__device__ __forceinline__ uint32_t f2tf32(float f) {
    uint32_t r; asm("cvt.rna.tf32.f32 %0, %1;" : "=r"(r) : "f"(f)); return r;
}
__device__ __forceinline__ void mma_tf32(float* d, const uint32_t* a,
                                         uint32_t b0, uint32_t b1) {
    asm volatile("mma.sync.aligned.m16n8k8.row.col.f32.tf32.tf32.f32 "
                 "{%0,%1,%2,%3}, {%4,%5,%6,%7}, {%8,%9}, {%0,%1,%2,%3};"
                 : "+f"(d[0]), "+f"(d[1]), "+f"(d[2]), "+f"(d[3])
                 : "r"(a[0]), "r"(a[1]), "r"(a[2]), "r"(a[3]),
                   "r"(b0), "r"(b1));
}
__device__ __forceinline__ uint32_t smem_u32(const void* p) {
    return (uint32_t)__cvta_generic_to_shared(p);
}
__device__ __forceinline__ void cp_async16(uint32_t dst, const void* src) {
    asm volatile("cp.async.cg.shared.global [%0], [%1], 16;"
                 :: "r"(dst), "l"(src) : "memory");
}
#define CP_COMMIT() asm volatile("cp.async.commit_group;" ::: "memory")
#define CP_WAIT0()  asm volatile("cp.async.wait_group 0;" ::: "memory")

// A fragment layout (tile stride 132 floats; R6-passing).
// slots: 0=A[g][tq] 1=A[g+8][tq] 2=A[g][tq+4] 3=A[g+8][tq+4]
__device__ __forceinline__ int afrag(int row, int col) {
    int tile = (col >> 5)*32 + (row >> 5)*8 + ((row >> 4) & 1)*4 + ((col >> 3) & 3);
    return tile*132 + ((row & 7)*4 + (col & 3))*4
         + (((row >> 3) & 1) + (((col >> 2) & 1) << 1));
}
// B fragment layout, UNPADDED (tile stride 128) for contiguous cp.async images.
__device__ __forceinline__ int bfrag(int kk, int n) {   // kk 0..31, n 0..255
    int tile = ((n >> 6)*4 + (kk >> 3))*4 + ((n >> 4) & 3);
    return tile*128 + ((n & 7)*4 + (kk & 3))*4
         + ((((n >> 3) & 1) << 1) | ((kk >> 2) & 1));
}

// ---------------------------------------------------------------------------
// prep: W1/W2 -> tf32(rna) -> fragment-layout chunk images in gmem.
// ---------------------------------------------------------------------------
__global__ void prep_kernel(const float* __restrict__ W1, const float* __restrict__ W2)
{
    int i = blockIdx.x * blockDim.x + threadIdx.x;
    if (i >= 12*8192) return;
    int kc = i >> 13, r = i & 8191;
    int kk = r >> 8, n = r & 255;
    float w = (kc < 4) ? W1[(kc*32 + kk)*256 + n] : W2[((kc-4)*32 + kk)*256 + n];
    reinterpret_cast<uint32_t*>(g_Wfrag)[kc*8192 + bfrag(kk, n)] = f2tf32(w);
}

// vprep: round v to tf32-rna once (so kv's HW truncation is lossless).
__global__ void vprep_kernel(const float* __restrict__ v)
{
    int i = blockIdx.x * blockDim.x + threadIdx.x;   // float4 index
    if (i >= NTOK*DD/4) return;
    float4 t = reinterpret_cast<const float4*>(v)[i];
    uint4 r = make_uint4(f2tf32(t.x), f2tf32(t.y), f2tf32(t.z), f2tf32(t.w));
    reinterpret_cast<uint4*>(g_vr)[i] = r;
}

// ---------------------------------------------------------------------------
// phi kernel: fragment-major tf32 mma + cp.async W pipeline.
// 128 tokens/CTA, 512 threads. SMEM floats:
//   sA @0 (33792), sW @33792 (2 x 8192), sB1 @50176, sB2 @50432,
//   sPrt @50688 (512), sInv @51200 (128). 205312 B.
// Output values are tf32-rna rounded (downstream A-operands pre-rounded).
// ---------------------------------------------------------------------------
#define OFFW2   33792
#define OFFB1_2 50176
#define OFFB2_2 50432
#define OFFPRT2 50688
#define OFFINV2 51200
#define PHI_SMEM (51328 * 4)

__global__ void __launch_bounds__(512) phi_mma_kernel(
    const float* __restrict__ q, const float* __restrict__ k,
    const float* __restrict__ b1, const float* __restrict__ b2)
{
    extern __shared__ float smf[];
    uint32_t* sAu = reinterpret_cast<uint32_t*>(smf);
    uint32_t* sWu = reinterpret_cast<uint32_t*>(smf + OFFW2);
    float* sB1  = smf + OFFB1_2;
    float* sB2  = smf + OFFB2_2;
    float* sPrt = smf + OFFPRT2;
    float* sInv = smf + OFFINV2;
    const uint32_t wbase = smem_u32(sWu);

    const int tid  = threadIdx.x;
    const int wid  = tid >> 5;
    const int lane = tid & 31;
    const int g    = lane >> 2;
    const int tq   = lane & 3;
    const int wm   = wid & 3;
    const int wn   = wid >> 2;

    const int bid = blockIdx.x;
    const float* src = (bid < 1024) ? q : k;
    float*       dst = (bid < 1024) ? g_phi_q : g_phi_k;
    const int tok0 = (bid & 1023) * 128;

    // prologue: issue W chunk 0 -> buf0 (overlaps X staging below)
    {
        const float* img = g_Wfrag;
        #pragma unroll
        for (int l = 0; l < 4; ++l) {
            int id = tid + l * 512;
            cp_async16(wbase + id * 16, img + id * 4);
        }
        CP_COMMIT();
    }

    // stage X [128][128] into A-fragment layout (tf32 rna)
    {
        const float4* s4 = reinterpret_cast<const float4*>(src + (size_t)tok0 * DD);
        #pragma unroll
        for (int l = 0; l < 8; ++l) {
            int id  = tid + l * 512;
            int row = id >> 5, c4 = id & 31;
            float4 v = s4[row * 32 + c4];
            int colb = c4 * 4;
            sAu[afrag(row, colb)]     = f2tf32(v.x);
            sAu[afrag(row, colb + 1)] = f2tf32(v.y);
            sAu[afrag(row, colb + 2)] = f2tf32(v.z);
            sAu[afrag(row, colb + 3)] = f2tf32(v.w);
        }
    }
    if (tid < 256) { sB1[tid] = b1[tid]; sB2[tid] = b2[tid]; }

    float acc[2][8][4];
    #pragma unroll
    for (int mt = 0; mt < 2; ++mt)
        #pragma unroll
        for (int nt = 0; nt < 8; ++nt)
            #pragma unroll
            for (int e = 0; e < 4; ++e) acc[mt][nt][e] = 0.f;

    // ---- main chunk loop: kc 0..3 stage1, 4..11 stage2 ----
    for (int kc = 0; kc < 12; ++kc) {
        CP_WAIT0();
        __syncthreads();   // buf kc&1 ready & visible; all compute kc-1 done

        if (kc < 11) {     // issue chunk kc+1 into the just-freed buffer
            const float* img = g_Wfrag + (kc + 1) * 8192;
            uint32_t dstb = wbase + (uint32_t)((kc + 1) & 1) * 32768u;
            #pragma unroll
            for (int l = 0; l < 4; ++l) {
                int id = tid + l * 512;
                cp_async16(dstb + id * 16, img + id * 4);
            }
            CP_COMMIT();
        }

        if (kc == 4) {
            // ===== epilogue 1: H = silu(acc + b1) -> A-fragment layout =====
            #pragma unroll
            for (int mt = 0; mt < 2; ++mt)
                #pragma unroll
                for (int nt = 0; nt < 8; ++nt) {
                    const int col = wn*64 + nt*8 + tq*2;
                    #pragma unroll
                    for (int h = 0; h < 2; ++h) {
                        const int row = wm*32 + mt*16 + 8*h + g;
                        #pragma unroll
                        for (int pr = 0; pr < 2; ++pr) {
                            float x = acc[mt][nt][h*2+pr] + sB1[col+pr];
                            float s = x / (1.f + __expf(-x));
                            sAu[afrag(row, col + pr)] = f2tf32(s);
                            acc[mt][nt][h*2+pr] = 0.f;
                        }
                    }
                }
            __syncthreads();   // H visible
        }

        // ---- compute on buf kc&1: all operand loads LDS.128 ----
        {
            const int tb = ((kc < 4) ? kc : (kc - 4)) * 32 + wm * 8;
            const uint32_t* wb = sWu + (kc & 1) * 8192;

            #pragma unroll
            for (int k8 = 0; k8 < 4; ++k8) {
                uint4 t0 = *reinterpret_cast<const uint4*>(
                    sAu + (tb + k8) * 132 + lane * 4);
                uint4 t1 = *reinterpret_cast<const uint4*>(
                    sAu + (tb + 4 + k8) * 132 + lane * 4);
                uint32_t a0[4] = {t0.x, t0.y, t0.z, t0.w};
                uint32_t a1[4] = {t1.x, t1.y, t1.z, t1.w};
                #pragma unroll
                for (int p = 0; p < 4; ++p) {
                    uint4 b = *reinterpret_cast<const uint4*>(
                        wb + ((wn*4 + k8)*4 + p) * 128 + lane * 4);
                    mma_tf32(acc[0][2*p],   a0, b.x, b.y);
                    mma_tf32(acc[0][2*p+1], a0, b.z, b.w);
                    mma_tf32(acc[1][2*p],   a1, b.x, b.y);
                    mma_tf32(acc[1][2*p+1], a1, b.z, b.w);
                }
            }
        }
    }

    // ===== epilogue 2: p = elu(acc + b2)+1, row L2 norm, write (tf32-rounded)
    float ss[2][2] = {};
    #pragma unroll
    for (int mt = 0; mt < 2; ++mt)
        #pragma unroll
        for (int nt = 0; nt < 8; ++nt) {
            const int col = wn*64 + nt*8 + tq*2;
            #pragma unroll
            for (int h = 0; h < 2; ++h)
                #pragma unroll
                for (int pr = 0; pr < 2; ++pr) {
                    float x = acc[mt][nt][h*2+pr] + sB2[col+pr];
                    float p = (x > 0.f) ? (x + 1.f) : __expf(x);
                    acc[mt][nt][h*2+pr] = p;
                    ss[mt][h] = fmaf(p, p, ss[mt][h]);
                }
        }
    #pragma unroll
    for (int m = 1; m <= 2; m <<= 1)
        #pragma unroll
        for (int mt = 0; mt < 2; ++mt)
            #pragma unroll
            for (int h = 0; h < 2; ++h)
                ss[mt][h] += __shfl_xor_sync(0xffffffffu, ss[mt][h], m);
    if (tq == 0) {
        #pragma unroll
        for (int mt = 0; mt < 2; ++mt)
            #pragma unroll
            for (int h = 0; h < 2; ++h)
                sPrt[wn*128 + wm*32 + mt*16 + 8*h + g] = ss[mt][h];
    }
    __syncthreads();
    if (tid < 128)
        sInv[tid] = 1.f / (sqrtf(sPrt[tid] + sPrt[128+tid] +
                                 sPrt[256+tid] + sPrt[384+tid]) + 1e-6f);
    __syncthreads();

    #pragma unroll
    for (int mt = 0; mt < 2; ++mt)
        #pragma unroll
        for (int h = 0; h < 2; ++h) {
            const int row = wm*32 + mt*16 + 8*h + g;
            const float inv = sInv[row];
            float* dr = dst + (size_t)(tok0 + row) * FF;
            #pragma unroll
            for (int nt = 0; nt < 8; ++nt) {
                const int col = wn*64 + nt*8 + tq*2;
                *reinterpret_cast<float2*>(dr + col) = make_float2(
                    __uint_as_float(f2tf32(acc[mt][nt][h*2]   * inv)),
                    __uint_as_float(f2tf32(acc[mt][nt][h*2+1] * inv)));
            }
        }
}

// ---------------------------------------------------------------------------
// kv kernel: grid (32 heads, 2 F-halves, 8 ksplits). 512 threads.
// kvp[f0+128, D=128] partial over 512 seq + ksum partial. cp.async S=2.
// Operands pre-rounded (phi outputs + g_vr) -> HW truncation lossless.
// SMEM: 2 x (sP[32][136] + sV[32][136]) = 69632 B dynamic.
// ---------------------------------------------------------------------------
#define KVSTR 136
#define KV_BUF (32*KVSTR)
#define KV_SMEM (4 * KV_BUF * 4)

__global__ void __launch_bounds__(512) kv_mma_kernel()
{
    extern __shared__ uint32_t skv[];
    const uint32_t sbase = smem_u32(skv);

    const int hh = blockIdx.x;
    const int f0 = blockIdx.y * 128;
    const int ks = blockIdx.z;
    const int tid  = threadIdx.x;
    const int lane = tid & 31;
    const int wid  = tid >> 5;
    const int g  = lane >> 2;
    const int tq = lane & 3;
    const int wm = wid & 3;
    const int wn = wid >> 2;

    const float* pbase = g_phi_k + ((size_t)hh * NSEQ + (size_t)ks * 512) * FF + f0;
    const float* vbase = g_vr    + ((size_t)hh * NSEQ + (size_t)ks * 512) * DD;

    auto issue = [&](int b, int slot) {
        uint32_t pdst = sbase + (uint32_t)slot * (2*KV_BUF*4);
        uint32_t vdst = pdst + KV_BUF*4;
        #pragma unroll
        for (int l = 0; l < 2; ++l) {
            int id = tid + l * 512;
            int row = id >> 5, c4 = id & 31;
            cp_async16(pdst + (row*KVSTR + c4*4)*4,
                       pbase + (size_t)(b*32 + row)*FF + c4*4);
            cp_async16(vdst + (row*KVSTR + c4*4)*4,
                       vbase + (size_t)(b*32 + row)*DD + c4*4);
        }
        CP_COMMIT();
    };

    issue(0, 0);

    float acc[2][4][4];
    #pragma unroll
    for (int mt = 0; mt < 2; ++mt)
        #pragma unroll
        for (int nt = 0; nt < 4; ++nt)
            #pragma unroll
            for (int e = 0; e < 4; ++e) acc[mt][nt][e] = 0.f;
    float ksacc = 0.f;

    for (int b = 0; b < 16; ++b) {
        CP_WAIT0();
        __syncthreads();
        if (b < 15) issue(b + 1, (b + 1) & 1);

        const uint32_t* sP = skv + (b & 1) * (2*KV_BUF);
        const uint32_t* sV = sP + KV_BUF;

        if (tid < 128) {
            #pragma unroll
            for (int r = 0; r < 32; ++r)
                ksacc += __uint_as_float(sP[r*KVSTR + tid]);
        }

        #pragma unroll
        for (int k8 = 0; k8 < 4; ++k8) {
            const int r0 = (k8*8 + tq) * KVSTR;
            const int r1 = (k8*8 + tq + 4) * KVSTR;
            uint32_t a[2][4];
            #pragma unroll
            for (int mt = 0; mt < 2; ++mt) {
                const int m = wm*32 + mt*16 + g;
                a[mt][0] = sP[r0 + m];
                a[mt][1] = sP[r0 + m + 8];
                a[mt][2] = sP[r1 + m];
                a[mt][3] = sP[r1 + m + 8];
            }
            #pragma unroll
            for (int nt = 0; nt < 4; ++nt) {
                const int n = wn*32 + nt*8 + g;
                uint32_t b0 = sV[r0 + n];
                uint32_t b1 = sV[r1 + n];
                mma_tf32(acc[0][nt], a[0], b0, b1);
                mma_tf32(acc[1][nt], a[1], b0, b1);
            }
        }
    }

    float* outp = g_kvp + ((size_t)ks * BH + hh) * FF * DD;
    #pragma unroll
    for (int mt = 0; mt < 2; ++mt)
        #pragma unroll
        for (int h = 0; h < 2; ++h) {
            const int f = f0 + wm*32 + mt*16 + 8*h + g;
            #pragma unroll
            for (int nt = 0; nt < 4; ++nt) {
                const int d = wn*32 + nt*8 + tq*2;
                *reinterpret_cast<float2*>(outp + (size_t)f * DD + d) =
                    make_float2(acc[mt][nt][h*2], acc[mt][nt][h*2+1]);
            }
        }
    if (tid < 128)
        g_ksp[((size_t)ks * BH + hh) * FF + f0 + tid] = ksacc;
}

// ---------------------------------------------------------------------------
// reduce kernel: fold K-split partials; round g_kv to tf32-rna (qkv B-operand).
// ---------------------------------------------------------------------------
__global__ void reduce_kernel()
{
    const int NKV = BH * FF * DD;
    const int NKS = BH * FF;
    int i = blockIdx.x * blockDim.x + threadIdx.x;
    if (i < NKV) {
        float s = 0.f;
        #pragma unroll
        for (int p = 0; p < KSPLIT; ++p) s += g_kvp[(size_t)p * NKV + i];
        reinterpret_cast<uint32_t*>(g_kv)[i] = f2tf32(s);
    } else {
        int j = i - NKV;
        if (j < NKS) {
            float s = 0.f;
            #pragma unroll
            for (int p = 0; p < KSPLIT; ++p) s += g_ksp[(size_t)p * NKS + j];
            g_ksum[j] = s;
        }
    }
}

// ---------------------------------------------------------------------------
// qkv kernel: cp.async S=2; operands pre-rounded. grid (32, 32), 512 threads.
// ---------------------------------------------------------------------------
#define QASTR 36
#define QBSTR 136
#define QA_BUF (128*QASTR)
#define QB_BUF (32*QBSTR)
#define QKV_SMEM ((QA_BUF + QB_BUF) * 2 * 4)

__global__ void __launch_bounds__(512) qkv_mma_kernel(float* __restrict__ out)
{
    extern __shared__ uint32_t sq[];
    __shared__ float sKs[2][32];
    __shared__ float sDen[128];
    const uint32_t sbase = smem_u32(sq);

    const int hh = blockIdx.x;
    const int m0 = blockIdx.y * 128;
    const int tid  = threadIdx.x;
    const int lane = tid & 31;
    const int wid  = tid >> 5;
    const int g  = lane >> 2;
    const int tq = lane & 3;
    const int wm = wid & 3;
    const int wn = wid >> 2;

    const float* abase = g_phi_q + ((size_t)hh * NSEQ + m0) * FF;
    const float* bbase = g_kv + (size_t)hh * FF * DD;

    auto issue = [&](int kc, int slot) {
        uint32_t adst = sbase + (uint32_t)slot * ((QA_BUF + QB_BUF)*4);
        uint32_t bdst = adst + QA_BUF*4;
        #pragma unroll
        for (int l = 0; l < 2; ++l) {
            int id = tid + l * 512;
            int ar = id >> 3, ac4 = id & 7;
            cp_async16(adst + (ar*QASTR + ac4*4)*4,
                       abase + (size_t)ar*FF + kc*32 + ac4*4);
            int br = id >> 5, bc4 = id & 31;
            cp_async16(bdst + (br*QBSTR + bc4*4)*4,
                       bbase + (size_t)(kc*32 + br)*DD + bc4*4);
        }
        CP_COMMIT();
    };

    issue(0, 0);
    if (tid < 32) sKs[0][tid] = g_ksum[(size_t)hh * FF + tid];

    float acc[2][4][4];
    #pragma unroll
    for (int mt = 0; mt < 2; ++mt)
        #pragma unroll
        for (int nt = 0; nt < 4; ++nt)
            #pragma unroll
            for (int e = 0; e < 4; ++e) acc[mt][nt][e] = 0.f;
    float den = 0.f;

    for (int kc = 0; kc < 8; ++kc) {
        CP_WAIT0();
        __syncthreads();
        if (kc < 7) {
            issue(kc + 1, (kc + 1) & 1);
            if (tid < 32)
                sKs[(kc+1) & 1][tid] = g_ksum[(size_t)hh * FF + (kc+1)*32 + tid];
        }

        const uint32_t* sA = sq + (kc & 1) * (QA_BUF + QB_BUF);
        const uint32_t* sB = sA + QA_BUF;
        const float* ks = sKs[kc & 1];

        if (tid < 128) {
            #pragma unroll
            for (int kk = 0; kk < 32; ++kk)
                den = fmaf(__uint_as_float(sA[tid * QASTR + kk]), ks[kk], den);
        }

        #pragma unroll
        for (int k8 = 0; k8 < 4; ++k8) {
            uint32_t a[2][4];
            #pragma unroll
            for (int mt = 0; mt < 2; ++mt) {
                const uint32_t* Ar = sA + (wm*32 + mt*16 + g) * QASTR + k8*8 + tq;
                a[mt][0] = Ar[0];
                a[mt][1] = Ar[8*QASTR];
                a[mt][2] = Ar[4];
                a[mt][3] = Ar[8*QASTR + 4];
            }
            const int v0 = (k8*8 + tq) * QBSTR;
            const int v1 = (k8*8 + tq + 4) * QBSTR;
            #pragma unroll
            for (int nt = 0; nt < 4; ++nt) {
                const int n = wn*32 + nt*8 + g;
                uint32_t b0 = sB[v0 + n];
                uint32_t b1 = sB[v1 + n];
                mma_tf32(acc[0][nt], a[0], b0, b1);
                mma_tf32(acc[1][nt], a[1], b0, b1);
            }
        }
    }

    if (tid < 128) sDen[tid] = den;
    __syncthreads();

    float* op = out + ((size_t)hh * NSEQ + m0) * DD;
    #pragma unroll
    for (int mt = 0; mt < 2; ++mt)
        #pragma unroll
        for (int h = 0; h < 2; ++h) {
            const int row = wm*32 + mt*16 + 8*h + g;
            const float invd = 1.f / fmaxf(sDen[row], 1e-6f);
            #pragma unroll
            for (int nt = 0; nt < 4; ++nt) {
                const int d = wn*32 + nt*8 + tq*2;
                *reinterpret_cast<float2*>(op + (size_t)row * DD + d) =
                    make_float2(acc[mt][nt][h*2] * invd, acc[mt][nt][h*2+1] * invd);
            }
        }
}

// ---------------------------------------------------------------------------
extern "C" void kernel_launch(void* const* d_in, const int* in_sizes, int n_in,
                              void* d_out, int out_size)
{
    (void)in_sizes; (void)n_in; (void)out_size;
    const float* q  = (const float*)d_in[0];
    const float* k  = (const float*)d_in[1];
    const float* v  = (const float*)d_in[2];
    const float* W1 = (const float*)d_in[3];
    const float* b1 = (const float*)d_in[4];
    const float* W2 = (const float*)d_in[5];
    const float* b2 = (const float*)d_in[6];
    float* out = (float*)d_out;

    cudaFuncSetAttribute(phi_mma_kernel, cudaFuncAttributeMaxDynamicSharedMemorySize, PHI_SMEM);
    cudaFuncSetAttribute(kv_mma_kernel,  cudaFuncAttributeMaxDynamicSharedMemorySize, KV_SMEM);
    cudaFuncSetAttribute(qkv_mma_kernel, cudaFuncAttributeMaxDynamicSharedMemorySize, QKV_SMEM);

    prep_kernel<<<(12*8192 + 255) / 256, 256>>>(W1, W2);
    vprep_kernel<<<(NTOK*DD/4 + 255) / 256, 256>>>(v);
    phi_mma_kernel<<<2048, 512, PHI_SMEM>>>(q, k, b1, b2);
    kv_mma_kernel<<<dim3(32, 2, KSPLIT), 512, KV_SMEM>>>();
    {
        const int total = BH*FF*DD + BH*FF;
        reduce_kernel<<<(total + 255) / 256, 256>>>();
    }
    qkv_mma_kernel<<<dim3(32, 32), 512, QKV_SMEM>>>(out);
}

// round 9
// speedup vs baseline: 3.8515x; 1.3729x over previous
#include <cuda_runtime.h>
#include <cuda_fp16.h>
#include <math.h>
#include <stdint.h>

// Problem constants
#define BH    32
#define NSEQ  4096
#define DD    128
#define FF    256
#define NTOK  (BH*NSEQ)
#define KSPLIT 8

// Scratch (device globals: allocation-free rule)
__device__ __half g_phi_q[(size_t)NTOK*FF];
__device__ __half g_phi_k[(size_t)NTOK*FF];
__device__ float  g_kvp[(size_t)KSPLIT*BH*FF*DD];
__device__ float  g_ksp[(size_t)KSPLIT*BH*FF];
__device__ __half g_kvh[(size_t)BH*FF*DD];
__device__ float  g_ksum[(size_t)BH*FF];
__device__ __half g_Wh[12*8192];          // W chunks [kc][n=256][k=32] fp16
__device__ __half g_vh[(size_t)NTOK*DD];  // fp16-rounded v

// ---------------------------------------------------------------------------
// helpers
// ---------------------------------------------------------------------------
__device__ __forceinline__ uint32_t smem_u32(const void* p) {
    return (uint32_t)__cvta_generic_to_shared(p);
}
__device__ __forceinline__ void cp_async16(uint32_t dst, const void* src) {
    asm volatile("cp.async.cg.shared.global [%0], [%1], 16;"
                 :: "r"(dst), "l"(src) : "memory");
}
#define CP_COMMIT() asm volatile("cp.async.commit_group;" ::: "memory")
#define CP_WAIT0()  asm volatile("cp.async.wait_group 0;" ::: "memory")

__device__ __forceinline__ void ldsm_x4(uint32_t& r0, uint32_t& r1,
                                        uint32_t& r2, uint32_t& r3, uint32_t a) {
    asm volatile("ldmatrix.sync.aligned.m8n8.x4.shared.b16 {%0,%1,%2,%3}, [%4];"
                 : "=r"(r0), "=r"(r1), "=r"(r2), "=r"(r3) : "r"(a));
}
__device__ __forceinline__ void ldsm_x4t(uint32_t& r0, uint32_t& r1,
                                         uint32_t& r2, uint32_t& r3, uint32_t a) {
    asm volatile("ldmatrix.sync.aligned.m8n8.x4.trans.shared.b16 {%0,%1,%2,%3}, [%4];"
                 : "=r"(r0), "=r"(r1), "=r"(r2), "=r"(r3) : "r"(a));
}
__device__ __forceinline__ void mma_fp16(float* d, const uint32_t* a,
                                         uint32_t b0, uint32_t b1) {
    asm volatile("mma.sync.aligned.m16n8k16.row.col.f32.f16.f16.f32 "
                 "{%0,%1,%2,%3}, {%4,%5,%6,%7}, {%8,%9}, {%0,%1,%2,%3};"
                 : "+f"(d[0]), "+f"(d[1]), "+f"(d[2]), "+f"(d[3])
                 : "r"(a[0]), "r"(a[1]), "r"(a[2]), "r"(a[3]),
                   "r"(b0), "r"(b1));
}

// ---------------------------------------------------------------------------
// prep: W1/W2 -> fp16 chunk images [kc][n][kk]; vprep: v -> fp16.
// ---------------------------------------------------------------------------
__global__ void prep_kernel(const float* __restrict__ W1, const float* __restrict__ W2)
{
    int i = blockIdx.x * blockDim.x + threadIdx.x;
    if (i >= 12*8192) return;
    int kc = i >> 13, r = i & 8191;
    int n = r >> 5, kk = r & 31;
    float w = (kc < 4) ? W1[(kc*32 + kk)*256 + n] : W2[((kc-4)*32 + kk)*256 + n];
    g_Wh[kc*8192 + n*32 + kk] = __float2half_rn(w);
}

__global__ void vprep_kernel(const float* __restrict__ v)
{
    int i = blockIdx.x * blockDim.x + threadIdx.x;   // float4 index
    if (i >= NTOK*DD/4) return;
    float4 t = reinterpret_cast<const float4*>(v)[i];
    __half2* o = reinterpret_cast<__half2*>(g_vh + (size_t)i*4);
    o[0] = __floats2half2_rn(t.x, t.y);
    o[1] = __floats2half2_rn(t.z, t.w);
}

// ---------------------------------------------------------------------------
// phi kernel (fp16 mma m16n8k16 + ldmatrix + cp.async S=2 W pipeline).
// 128 tokens/CTA, 512 threads (16 warps, 4M x 4N, warp tile 32x64).
// SMEM bytes:
//   A @0       : X [128][136]h (stage1) overlaid by H [128][264]h -> 67584
//   W @67584   : 2 x [256][40]h = 40960
//   B1 @108544, B2 @109568 (f32 x256), PRT @110592 (f32 x512), INV @112640
// total 113152 B
// ---------------------------------------------------------------------------
#define PHI_SMEM 113152

__global__ void __launch_bounds__(512) phi_mma_kernel(
    const float* __restrict__ q, const float* __restrict__ k,
    const float* __restrict__ b1, const float* __restrict__ b2)
{
    extern __shared__ char smc[];
    __half* sAh = reinterpret_cast<__half*>(smc);
    float* sB1  = reinterpret_cast<float*>(smc + 108544);
    float* sB2  = reinterpret_cast<float*>(smc + 109568);
    float* sPrt = reinterpret_cast<float*>(smc + 110592);
    float* sInv = reinterpret_cast<float*>(smc + 112640);
    const uint32_t abase = smem_u32(smc);
    const uint32_t wbase = abase + 67584u;

    const int tid  = threadIdx.x;
    const int wid  = tid >> 5;
    const int lane = tid & 31;
    const int g    = lane >> 2;
    const int tq   = lane & 3;
    const int wm   = wid & 3;
    const int wn   = wid >> 2;

    const int bid = blockIdx.x;
    const float* src = (bid < 1024) ? q : k;
    __half*      dst = (bid < 1024) ? g_phi_q : g_phi_k;
    const int tok0 = (bid & 1023) * 128;

    // prologue: issue W chunk 0 -> buf0
    {
        #pragma unroll
        for (int l = 0; l < 2; ++l) {
            int u = tid + l * 512;          // 0..1023
            int n = u >> 2, seg = u & 3;
            cp_async16(wbase + n*80 + seg*16, g_Wh + n*32 + seg*8);
        }
        CP_COMMIT();
    }

    // stage X [128][128] -> fp16 smem, stride 136 halfs
    {
        const float4* s4 = reinterpret_cast<const float4*>(src + (size_t)tok0 * DD);
        #pragma unroll
        for (int l = 0; l < 8; ++l) {
            int id  = tid + l * 512;
            int row = id >> 5, c4 = id & 31;
            float4 v = s4[row * 32 + c4];
            __half2* p = reinterpret_cast<__half2*>(sAh + row*136 + c4*4);
            p[0] = __floats2half2_rn(v.x, v.y);
            p[1] = __floats2half2_rn(v.z, v.w);
        }
    }
    if (tid < 256) { sB1[tid] = b1[tid]; sB2[tid] = b2[tid]; }

    float acc[2][8][4];
    #pragma unroll
    for (int mt = 0; mt < 2; ++mt)
        #pragma unroll
        for (int nt = 0; nt < 8; ++nt)
            #pragma unroll
            for (int e = 0; e < 4; ++e) acc[mt][nt][e] = 0.f;

    // ldmatrix lane address components
    const int amrow   = wm*32 + (lane & 15);       // A row (token/f)
    const int acoladd = ((lane >> 4) << 3);        // A k offset (+8 for hi half)
    const int bnrow   = wn*64 + ((lane >> 4) << 3) + (lane & 7);  // B n row
    const int bcoladd = ((lane >> 3) & 1) * 8;     // B k offset

    // ---- main chunk loop: kc 0..3 stage1, 4..11 stage2 ----
    for (int kc = 0; kc < 12; ++kc) {
        CP_WAIT0();
        __syncthreads();   // buf kc&1 ready & visible; compute kc-1 done

        if (kc < 11) {     // issue chunk kc+1
            const __half* img = g_Wh + (kc + 1) * 8192;
            uint32_t dstb = wbase + (uint32_t)((kc + 1) & 1) * 20480u;
            #pragma unroll
            for (int l = 0; l < 2; ++l) {
                int u = tid + l * 512;
                int n = u >> 2, seg = u & 3;
                cp_async16(dstb + n*80 + seg*16, img + n*32 + seg*8);
            }
            CP_COMMIT();
        }

        if (kc == 4) {
            // ===== epilogue 1: H = silu(acc + b1) -> fp16 smem stride 264 ====
            #pragma unroll
            for (int mt = 0; mt < 2; ++mt)
                #pragma unroll
                for (int nt = 0; nt < 8; ++nt) {
                    const int col = wn*64 + nt*8 + tq*2;
                    #pragma unroll
                    for (int h = 0; h < 2; ++h) {
                        const int row = wm*32 + mt*16 + 8*h + g;
                        float x0 = acc[mt][nt][h*2]   + sB1[col];
                        float x1 = acc[mt][nt][h*2+1] + sB1[col+1];
                        float s0 = x0 / (1.f + __expf(-x0));
                        float s1 = x1 / (1.f + __expf(-x1));
                        *reinterpret_cast<__half2*>(sAh + row*264 + col) =
                            __floats2half2_rn(s0, s1);
                        acc[mt][nt][h*2] = 0.f;
                        acc[mt][nt][h*2+1] = 0.f;
                    }
                }
            __syncthreads();   // H visible
        }

        // ---- compute on W buf kc&1 ----
        {
            const bool s1s = (kc < 4);
            const int astr = s1s ? 136 : 264;
            const int k0   = (s1s ? kc : (kc - 4)) * 32;
            const uint32_t wb = wbase + (uint32_t)(kc & 1) * 20480u;

            uint32_t a[2][2][4];   // [mt][s][reg]
            #pragma unroll
            for (int s = 0; s < 2; ++s)
                #pragma unroll
                for (int mt = 0; mt < 2; ++mt) {
                    uint32_t ad = abase +
                        (uint32_t)(((amrow + mt*16) * astr) + k0 + s*16 + acoladd) * 2u;
                    ldsm_x4(a[mt][s][0], a[mt][s][1], a[mt][s][2], a[mt][s][3], ad);
                }

            #pragma unroll
            for (int s = 0; s < 2; ++s)
                #pragma unroll
                for (int p = 0; p < 4; ++p) {
                    uint32_t b0, b1v, b2, b3;
                    uint32_t bd = wb +
                        (uint32_t)(((bnrow + p*16) * 40) + s*16 + bcoladd) * 2u;
                    ldsm_x4(b0, b1v, b2, b3, bd);
                    mma_fp16(acc[0][2*p],   a[0][s], b0, b1v);
                    mma_fp16(acc[0][2*p+1], a[0][s], b2, b3);
                    mma_fp16(acc[1][2*p],   a[1][s], b0, b1v);
                    mma_fp16(acc[1][2*p+1], a[1][s], b2, b3);
                }
        }
    }

    // ===== epilogue 2: p = elu(acc + b2)+1, row L2 norm, write fp16 =====
    float ss[2][2] = {};
    #pragma unroll
    for (int mt = 0; mt < 2; ++mt)
        #pragma unroll
        for (int nt = 0; nt < 8; ++nt) {
            const int col = wn*64 + nt*8 + tq*2;
            #pragma unroll
            for (int h = 0; h < 2; ++h)
                #pragma unroll
                for (int pr = 0; pr < 2; ++pr) {
                    float x = acc[mt][nt][h*2+pr] + sB2[col+pr];
                    float p = (x > 0.f) ? (x + 1.f) : __expf(x);
                    acc[mt][nt][h*2+pr] = p;
                    ss[mt][h] = fmaf(p, p, ss[mt][h]);
                }
        }
    #pragma unroll
    for (int m = 1; m <= 2; m <<= 1)
        #pragma unroll
        for (int mt = 0; mt < 2; ++mt)
            #pragma unroll
            for (int h = 0; h < 2; ++h)
                ss[mt][h] += __shfl_xor_sync(0xffffffffu, ss[mt][h], m);
    if (tq == 0) {
        #pragma unroll
        for (int mt = 0; mt < 2; ++mt)
            #pragma unroll
            for (int h = 0; h < 2; ++h)
                sPrt[wn*128 + wm*32 + mt*16 + 8*h + g] = ss[mt][h];
    }
    __syncthreads();
    if (tid < 128)
        sInv[tid] = 1.f / (sqrtf(sPrt[tid] + sPrt[128+tid] +
                                 sPrt[256+tid] + sPrt[384+tid]) + 1e-6f);
    __syncthreads();

    #pragma unroll
    for (int mt = 0; mt < 2; ++mt)
        #pragma unroll
        for (int h = 0; h < 2; ++h) {
            const int row = wm*32 + mt*16 + 8*h + g;
            const float inv = sInv[row];
            __half* dr = dst + (size_t)(tok0 + row) * FF;
            #pragma unroll
            for (int nt = 0; nt < 8; ++nt) {
                const int col = wn*64 + nt*8 + tq*2;
                *reinterpret_cast<__half2*>(dr + col) =
                    __floats2half2_rn(acc[mt][nt][h*2] * inv,
                                      acc[mt][nt][h*2+1] * inv);
            }
        }
}

// ---------------------------------------------------------------------------
// kv kernel: grid (32, 2, 8), 512 threads. kvp[f0+128, 128] over 512 seq.
// A = phi_k^T via ldmatrix.trans; B = v via ldmatrix.trans. cp.async S=2.
// SMEM: 2 x (P [32][136]h + V [32][136]h) = 34816 B.
// ---------------------------------------------------------------------------
#define KV_SMEM 34816

__global__ void __launch_bounds__(512) kv_mma_kernel()
{
    extern __shared__ char kvc[];
    const uint32_t sbase = smem_u32(kvc);

    const int hh = blockIdx.x;
    const int f0 = blockIdx.y * 128;
    const int ks = blockIdx.z;
    const int tid  = threadIdx.x;
    const int lane = tid & 31;
    const int wid  = tid >> 5;
    const int g  = lane >> 2;
    const int tq = lane & 3;
    const int wm = wid & 3;
    const int wn = wid >> 2;

    const __half* pbase = g_phi_k + ((size_t)hh * NSEQ + (size_t)ks * 512) * FF + f0;
    const __half* vbase = g_vh    + ((size_t)hh * NSEQ + (size_t)ks * 512) * DD;

    auto issue = [&](int b, int slot) {
        uint32_t base = sbase + (uint32_t)slot * 17408u;
        #pragma unroll
        for (int l = 0; l < 2; ++l) {
            int u = tid + l * 512;          // 0..1023
            int row = (u >> 4) & 31, seg = u & 15;
            if (u < 512)
                cp_async16(base + row*272 + seg*16,
                           pbase + (size_t)(b*32 + row)*FF + seg*8);
            else
                cp_async16(base + 8704u + row*272 + seg*16,
                           vbase + (size_t)(b*32 + row)*DD + seg*8);
        }
        CP_COMMIT();
    };

    issue(0, 0);

    float acc[2][4][4];
    #pragma unroll
    for (int mt = 0; mt < 2; ++mt)
        #pragma unroll
        for (int nt = 0; nt < 4; ++nt)
            #pragma unroll
            for (int e = 0; e < 4; ++e) acc[mt][nt][e] = 0.f;
    float ksacc = 0.f;

    // ldmatrix lane address components
    const int aseq = ((lane >> 4) << 3) + (lane & 7);      // A: seq row
    const int afc  = wm*32 + ((lane >> 3) & 1) * 8;        // A: f col
    const int bseq = ((lane >> 3) & 1) * 8 + (lane & 7);   // B: seq row
    const int bdc  = wn*32 + ((lane >> 4) << 3);           // B: d col

    for (int b = 0; b < 16; ++b) {
        CP_WAIT0();
        __syncthreads();
        if (b < 15) issue(b + 1, (b + 1) & 1);

        const uint32_t pb = sbase + (uint32_t)(b & 1) * 17408u;
        const uint32_t vb = pb + 8704u;
        const __half* sP = reinterpret_cast<const __half*>(kvc + (b & 1) * 17408);

        if (tid < 128) {
            #pragma unroll
            for (int r = 0; r < 32; ++r)
                ksacc += __half2float(sP[r*136 + tid]);
        }

        uint32_t a[2][2][4];
        #pragma unroll
        for (int s = 0; s < 2; ++s)
            #pragma unroll
            for (int mt = 0; mt < 2; ++mt) {
                uint32_t ad = pb + (uint32_t)(((s*16 + aseq) * 136) + afc + mt*16) * 2u;
                ldsm_x4t(a[mt][s][0], a[mt][s][1], a[mt][s][2], a[mt][s][3], ad);
            }
        #pragma unroll
        for (int s = 0; s < 2; ++s)
            #pragma unroll
            for (int p = 0; p < 2; ++p) {
                uint32_t b0, b1v, b2, b3;
                uint32_t bd = vb + (uint32_t)(((s*16 + bseq) * 136) + bdc + p*16) * 2u;
                ldsm_x4t(b0, b1v, b2, b3, bd);
                mma_fp16(acc[0][2*p],   a[0][s], b0, b1v);
                mma_fp16(acc[0][2*p+1], a[0][s], b2, b3);
                mma_fp16(acc[1][2*p],   a[1][s], b0, b1v);
                mma_fp16(acc[1][2*p+1], a[1][s], b2, b3);
            }
    }

    float* outp = g_kvp + ((size_t)ks * BH + hh) * FF * DD;
    #pragma unroll
    for (int mt = 0; mt < 2; ++mt)
        #pragma unroll
        for (int h = 0; h < 2; ++h) {
            const int f = f0 + wm*32 + mt*16 + 8*h + g;
            #pragma unroll
            for (int nt = 0; nt < 4; ++nt) {
                const int d = wn*32 + nt*8 + tq*2;
                *reinterpret_cast<float2*>(outp + (size_t)f * DD + d) =
                    make_float2(acc[mt][nt][h*2], acc[mt][nt][h*2+1]);
            }
        }
    if (tid < 128)
        g_ksp[((size_t)ks * BH + hh) * FF + f0 + tid] = ksacc;
}

// ---------------------------------------------------------------------------
// reduce kernel: fold K-split partials; g_kvh fp16, g_ksum fp32.
// ---------------------------------------------------------------------------
__global__ void reduce_kernel()
{
    const int NKV = BH * FF * DD;
    const int NKS = BH * FF;
    int i = blockIdx.x * blockDim.x + threadIdx.x;
    if (i < NKV) {
        float s = 0.f;
        #pragma unroll
        for (int p = 0; p < KSPLIT; ++p) s += g_kvp[(size_t)p * NKV + i];
        g_kvh[i] = __float2half_rn(s);
    } else {
        int j = i - NKV;
        if (j < NKS) {
            float s = 0.f;
            #pragma unroll
            for (int p = 0; p < KSPLIT; ++p) s += g_ksp[(size_t)p * NKS + j];
            g_ksum[j] = s;
        }
    }
}

// ---------------------------------------------------------------------------
// qkv kernel: grid (32, 32), 512 threads. out = phi_q @ kv / max(den, eps).
// A = phi_q (non-trans), B = kv (trans). cp.async S=2.
// SMEM: 2 x (A [128][40]h + B [32][136]h) = 37888 B dynamic.
// ---------------------------------------------------------------------------
#define QKV_SMEM 37888

__global__ void __launch_bounds__(512) qkv_mma_kernel(float* __restrict__ out)
{
    extern __shared__ char qc[];
    __shared__ float sKs[2][32];
    __shared__ float sDen[128];
    const uint32_t sbase = smem_u32(qc);

    const int hh = blockIdx.x;
    const int m0 = blockIdx.y * 128;
    const int tid  = threadIdx.x;
    const int lane = tid & 31;
    const int wid  = tid >> 5;
    const int g  = lane >> 2;
    const int tq = lane & 3;
    const int wm = wid & 3;
    const int wn = wid >> 2;

    const __half* agb = g_phi_q + ((size_t)hh * NSEQ + m0) * FF;
    const __half* bgb = g_kvh + (size_t)hh * FF * DD;

    auto issue = [&](int kc, int slot) {
        uint32_t base = sbase + (uint32_t)slot * 18944u;
        #pragma unroll
        for (int l = 0; l < 2; ++l) {
            int u = tid + l * 512;
            if (u < 512) {                  // A: 128 rows x 4 segs
                int row = u >> 2, seg = u & 3;
                cp_async16(base + row*80 + seg*16,
                           agb + (size_t)row*FF + kc*32 + seg*8);
            } else {                        // B: 32 rows x 16 segs
                int w = u - 512;
                int row = w >> 4, seg = w & 15;
                cp_async16(base + 10240u + row*272 + seg*16,
                           bgb + (size_t)(kc*32 + row)*DD + seg*8);
            }
        }
        CP_COMMIT();
    };

    issue(0, 0);
    if (tid < 32) sKs[0][tid] = g_ksum[(size_t)hh * FF + tid];

    float acc[2][2][4];
    #pragma unroll
    for (int mt = 0; mt < 2; ++mt)
        #pragma unroll
        for (int nt = 0; nt < 2; ++nt)
            #pragma unroll
            for (int e = 0; e < 4; ++e) acc[mt][nt][e] = 0.f;
    // full nt=4: acc2
    float acc2[2][2][4];
    #pragma unroll
    for (int mt = 0; mt < 2; ++mt)
        #pragma unroll
        for (int nt = 0; nt < 2; ++nt)
            #pragma unroll
            for (int e = 0; e < 4; ++e) acc2[mt][nt][e] = 0.f;
    float den = 0.f;

    const int amrow   = wm*32 + (lane & 15);
    const int acoladd = ((lane >> 4) << 3);
    const int bseq = ((lane >> 3) & 1) * 8 + (lane & 7);
    const int bdc  = wn*32 + ((lane >> 4) << 3);

    for (int kc = 0; kc < 8; ++kc) {
        CP_WAIT0();
        __syncthreads();
        if (kc < 7) {
            issue(kc + 1, (kc + 1) & 1);
            if (tid < 32)
                sKs[(kc+1) & 1][tid] = g_ksum[(size_t)hh * FF + (kc+1)*32 + tid];
        }

        const uint32_t ab = sbase + (uint32_t)(kc & 1) * 18944u;
        const uint32_t bb = ab + 10240u;
        const __half* sAhp = reinterpret_cast<const __half*>(qc + (kc & 1) * 18944);
        const float* ks = sKs[kc & 1];

        if (tid < 128) {
            #pragma unroll
            for (int kk = 0; kk < 32; ++kk)
                den = fmaf(__half2float(sAhp[tid*40 + kk]), ks[kk], den);
        }

        uint32_t a[2][2][4];
        #pragma unroll
        for (int s = 0; s < 2; ++s)
            #pragma unroll
            for (int mt = 0; mt < 2; ++mt) {
                uint32_t ad = ab + (uint32_t)(((amrow + mt*16) * 40) + s*16 + acoladd) * 2u;
                ldsm_x4(a[mt][s][0], a[mt][s][1], a[mt][s][2], a[mt][s][3], ad);
            }
        #pragma unroll
        for (int s = 0; s < 2; ++s)
            #pragma unroll
            for (int p = 0; p < 2; ++p) {
                uint32_t b0, b1v, b2, b3;
                uint32_t bd = bb + (uint32_t)(((s*16 + bseq) * 136) + bdc + p*16) * 2u;
                ldsm_x4t(b0, b1v, b2, b3, bd);
                if (p == 0) {
                    mma_fp16(acc[0][0], a[0][s], b0, b1v);
                    mma_fp16(acc[0][1], a[0][s], b2, b3);
                    mma_fp16(acc[1][0], a[1][s], b0, b1v);
                    mma_fp16(acc[1][1], a[1][s], b2, b3);
                } else {
                    mma_fp16(acc2[0][0], a[0][s], b0, b1v);
                    mma_fp16(acc2[0][1], a[0][s], b2, b3);
                    mma_fp16(acc2[1][0], a[1][s], b0, b1v);
                    mma_fp16(acc2[1][1], a[1][s], b2, b3);
                }
            }
    }

    if (tid < 128) sDen[tid] = den;
    __syncthreads();

    float* op = out + ((size_t)hh * NSEQ + m0) * DD;
    #pragma unroll
    for (int mt = 0; mt < 2; ++mt)
        #pragma unroll
        for (int h = 0; h < 2; ++h) {
            const int row = wm*32 + mt*16 + 8*h + g;
            const float invd = 1.f / fmaxf(sDen[row], 1e-6f);
            #pragma unroll
            for (int nt = 0; nt < 4; ++nt) {
                const int d = wn*32 + nt*8 + tq*2;
                const float* av = (nt < 2) ? acc[mt][nt] : acc2[mt][nt-2];
                *reinterpret_cast<float2*>(op + (size_t)row * DD + d) =
                    make_float2(av[h*2] * invd, av[h*2+1] * invd);
            }
        }
}

// ---------------------------------------------------------------------------
extern "C" void kernel_launch(void* const* d_in, const int* in_sizes, int n_in,
                              void* d_out, int out_size)
{
    (void)in_sizes; (void)n_in; (void)out_size;
    const float* q  = (const float*)d_in[0];
    const float* k  = (const float*)d_in[1];
    const float* v  = (const float*)d_in[2];
    const float* W1 = (const float*)d_in[3];
    const float* b1 = (const float*)d_in[4];
    const float* W2 = (const float*)d_in[5];
    const float* b2 = (const float*)d_in[6];
    float* out = (float*)d_out;

    cudaFuncSetAttribute(phi_mma_kernel, cudaFuncAttributeMaxDynamicSharedMemorySize, PHI_SMEM);
    cudaFuncSetAttribute(kv_mma_kernel,  cudaFuncAttributeMaxDynamicSharedMemorySize, KV_SMEM);
    cudaFuncSetAttribute(qkv_mma_kernel, cudaFuncAttributeMaxDynamicSharedMemorySize, QKV_SMEM);

    prep_kernel<<<(12*8192 + 255) / 256, 256>>>(W1, W2);
    vprep_kernel<<<(NTOK*DD/4 + 255) / 256, 256>>>(v);
    phi_mma_kernel<<<2048, 512, PHI_SMEM>>>(q, k, b1, b2);
    kv_mma_kernel<<<dim3(32, 2, KSPLIT), 512, KV_SMEM>>>();
    {
        const int total = BH*FF*DD + BH*FF;
        reduce_kernel<<<(total + 255) / 256, 256>>>();
    }
    qkv_mma_kernel<<<dim3(32, 32), 512, QKV_SMEM>>>(out);
}

// round 10
// speedup vs baseline: 3.9550x; 1.0269x over previous
#include <cuda_runtime.h>
#include <cuda_fp16.h>
#include <math.h>
#include <stdint.h>

// Problem constants
#define BH    32
#define NSEQ  4096
#define DD    128
#define FF    256
#define NTOK  (BH*NSEQ)
#define KSPLIT 4

// Scratch (device globals: allocation-free rule)
__device__ __half g_phi_q[(size_t)NTOK*FF];
__device__ __half g_phi_k[(size_t)NTOK*FF];
__device__ float  g_kvp[(size_t)KSPLIT*BH*FF*DD];
__device__ float  g_ksp[(size_t)KSPLIT*BH*FF];
__device__ __half g_kvh[(size_t)BH*FF*DD];
__device__ float  g_ksum[(size_t)BH*FF];
__device__ __half g_Wh[6*16384];          // W chunks [kc6][n=256][k=64] fp16
__device__ __half g_vh[(size_t)NTOK*DD];  // fp16-rounded v

// ---------------------------------------------------------------------------
// helpers
// ---------------------------------------------------------------------------
__device__ __forceinline__ uint32_t smem_u32(const void* p) {
    return (uint32_t)__cvta_generic_to_shared(p);
}
__device__ __forceinline__ void cp_async16(uint32_t dst, const void* src) {
    asm volatile("cp.async.cg.shared.global [%0], [%1], 16;"
                 :: "r"(dst), "l"(src) : "memory");
}
#define CP_COMMIT() asm volatile("cp.async.commit_group;" ::: "memory")
#define CP_WAIT0()  asm volatile("cp.async.wait_group 0;" ::: "memory")

__device__ __forceinline__ void ldsm_x4(uint32_t& r0, uint32_t& r1,
                                        uint32_t& r2, uint32_t& r3, uint32_t a) {
    asm volatile("ldmatrix.sync.aligned.m8n8.x4.shared.b16 {%0,%1,%2,%3}, [%4];"
                 : "=r"(r0), "=r"(r1), "=r"(r2), "=r"(r3) : "r"(a));
}
__device__ __forceinline__ void ldsm_x4t(uint32_t& r0, uint32_t& r1,
                                         uint32_t& r2, uint32_t& r3, uint32_t a) {
    asm volatile("ldmatrix.sync.aligned.m8n8.x4.trans.shared.b16 {%0,%1,%2,%3}, [%4];"
                 : "=r"(r0), "=r"(r1), "=r"(r2), "=r"(r3) : "r"(a));
}
__device__ __forceinline__ void mma_fp16(float* d, const uint32_t* a,
                                         uint32_t b0, uint32_t b1) {
    asm volatile("mma.sync.aligned.m16n8k16.row.col.f32.f16.f16.f32 "
                 "{%0,%1,%2,%3}, {%4,%5,%6,%7}, {%8,%9}, {%0,%1,%2,%3};"
                 : "+f"(d[0]), "+f"(d[1]), "+f"(d[2]), "+f"(d[3])
                 : "r"(a[0]), "r"(a[1]), "r"(a[2]), "r"(a[3]),
                   "r"(b0), "r"(b1));
}

// ---------------------------------------------------------------------------
// prep: W1/W2 -> fp16 chunk images [kc6][n=256][k=64]; vprep: v -> fp16.
// ---------------------------------------------------------------------------
__global__ void prep_kernel(const float* __restrict__ W1, const float* __restrict__ W2)
{
    int i = blockIdx.x * blockDim.x + threadIdx.x;
    if (i >= 6*16384) return;
    int kc = i >> 14, r = i & 16383;
    int n = r >> 6, kk = r & 63;
    float w = (kc < 2) ? W1[(kc*64 + kk)*256 + n] : W2[((kc-2)*64 + kk)*256 + n];
    g_Wh[kc*16384 + n*64 + kk] = __float2half_rn(w);
}

__global__ void vprep_kernel(const float* __restrict__ v)
{
    int i = blockIdx.x * blockDim.x + threadIdx.x;   // float4 index
    if (i >= NTOK*DD/4) return;
    float4 t = reinterpret_cast<const float4*>(v)[i];
    __half2* o = reinterpret_cast<__half2*>(g_vh + (size_t)i*4);
    o[0] = __floats2half2_rn(t.x, t.y);
    o[1] = __floats2half2_rn(t.z, t.w);
}

// ---------------------------------------------------------------------------
// phi kernel (fp16 mma m16n8k16, 64-wide K chunks, cp.async S=2).
// 128 tokens/CTA, 512 threads (16 warps, 4M x 4N, warp tile 32x64).
// SMEM bytes:
//   A @0       : X [128][136]h (stage1) overlaid by H [128][264]h -> 67584
//   W @67584   : 2 x [256][72]h = 73728
//   B1 @141312, B2 @142336 (f32 x256), PRT @143360 (f32 x512), INV @145408
// total 145920 B
// ---------------------------------------------------------------------------
#define PHI_SMEM 145920
#define WBUF_B   36864u

__global__ void __launch_bounds__(512) phi_mma_kernel(
    const float* __restrict__ q, const float* __restrict__ k,
    const float* __restrict__ b1, const float* __restrict__ b2)
{
    extern __shared__ char smc[];
    __half* sAh = reinterpret_cast<__half*>(smc);
    float* sB1  = reinterpret_cast<float*>(smc + 141312);
    float* sB2  = reinterpret_cast<float*>(smc + 142336);
    float* sPrt = reinterpret_cast<float*>(smc + 143360);
    float* sInv = reinterpret_cast<float*>(smc + 145408);
    const uint32_t abase = smem_u32(smc);
    const uint32_t wbase = abase + 67584u;

    const int tid  = threadIdx.x;
    const int wid  = tid >> 5;
    const int lane = tid & 31;
    const int g    = lane >> 2;
    const int tq   = lane & 3;
    const int wm   = wid & 3;
    const int wn   = wid >> 2;

    const int bid = blockIdx.x;
    const float* src = (bid < 1024) ? q : k;
    __half*      dst = (bid < 1024) ? g_phi_q : g_phi_k;
    const int tok0 = (bid & 1023) * 128;

    // prologue: issue W chunk 0 -> buf0 (256 rows x 8 segs of 16B)
    {
        #pragma unroll
        for (int l = 0; l < 4; ++l) {
            int u = tid + l * 512;          // 0..2047
            int n = u >> 3, seg = u & 7;
            cp_async16(wbase + n*144 + seg*16, g_Wh + n*64 + seg*8);
        }
        CP_COMMIT();
    }

    // stage X [128][128] -> fp16 smem, stride 136 halfs
    {
        const float4* s4 = reinterpret_cast<const float4*>(src + (size_t)tok0 * DD);
        #pragma unroll
        for (int l = 0; l < 8; ++l) {
            int id  = tid + l * 512;
            int row = id >> 5, c4 = id & 31;
            float4 v = s4[row * 32 + c4];
            __half2* p = reinterpret_cast<__half2*>(sAh + row*136 + c4*4);
            p[0] = __floats2half2_rn(v.x, v.y);
            p[1] = __floats2half2_rn(v.z, v.w);
        }
    }
    if (tid < 256) { sB1[tid] = b1[tid]; sB2[tid] = b2[tid]; }

    float acc[2][8][4];
    #pragma unroll
    for (int mt = 0; mt < 2; ++mt)
        #pragma unroll
        for (int nt = 0; nt < 8; ++nt)
            #pragma unroll
            for (int e = 0; e < 4; ++e) acc[mt][nt][e] = 0.f;

    // ldmatrix lane address components
    const int amrow   = wm*32 + (lane & 15);       // A row (token)
    const int acoladd = ((lane >> 4) << 3);        // A k offset
    const int bnrow   = wn*64 + ((lane >> 4) << 3) + (lane & 7);  // B n row
    const int bcoladd = ((lane >> 3) & 1) * 8;     // B k offset

    // ---- main chunk loop: kc 0..1 stage1 (K=128), 2..5 stage2 (K=256) ----
    for (int kc = 0; kc < 6; ++kc) {
        CP_WAIT0();
        __syncthreads();   // buf kc&1 ready & visible; compute kc-1 done

        if (kc < 5) {      // issue chunk kc+1
            const __half* img = g_Wh + (kc + 1) * 16384;
            uint32_t dstb = wbase + (uint32_t)((kc + 1) & 1) * WBUF_B;
            #pragma unroll
            for (int l = 0; l < 4; ++l) {
                int u = tid + l * 512;
                int n = u >> 3, seg = u & 7;
                cp_async16(dstb + n*144 + seg*16, img + n*64 + seg*8);
            }
            CP_COMMIT();
        }

        if (kc == 2) {
            // ===== epilogue 1: H = silu(acc + b1) -> fp16 smem stride 264 ====
            #pragma unroll
            for (int mt = 0; mt < 2; ++mt)
                #pragma unroll
                for (int nt = 0; nt < 8; ++nt) {
                    const int col = wn*64 + nt*8 + tq*2;
                    #pragma unroll
                    for (int h = 0; h < 2; ++h) {
                        const int row = wm*32 + mt*16 + 8*h + g;
                        float x0 = acc[mt][nt][h*2]   + sB1[col];
                        float x1 = acc[mt][nt][h*2+1] + sB1[col+1];
                        float s0 = x0 / (1.f + __expf(-x0));
                        float s1 = x1 / (1.f + __expf(-x1));
                        *reinterpret_cast<__half2*>(sAh + row*264 + col) =
                            __floats2half2_rn(s0, s1);
                        acc[mt][nt][h*2] = 0.f;
                        acc[mt][nt][h*2+1] = 0.f;
                    }
                }
            __syncthreads();   // H visible
        }

        // ---- compute on W buf kc&1 (4 k16-steps of the 64-wide chunk) ----
        {
            const bool s1s = (kc < 2);
            const int astr = s1s ? 136 : 264;
            const int k0   = (s1s ? kc : (kc - 2)) * 64;
            const uint32_t wb = wbase + (uint32_t)(kc & 1) * WBUF_B;

            #pragma unroll
            for (int s = 0; s < 4; ++s) {
                uint32_t a[2][4];
                #pragma unroll
                for (int mt = 0; mt < 2; ++mt) {
                    uint32_t ad = abase +
                        (uint32_t)(((amrow + mt*16) * astr) + k0 + s*16 + acoladd) * 2u;
                    ldsm_x4(a[mt][0], a[mt][1], a[mt][2], a[mt][3], ad);
                }
                #pragma unroll
                for (int p = 0; p < 4; ++p) {
                    uint32_t b0, b1v, b2, b3;
                    uint32_t bd = wb +
                        (uint32_t)(((bnrow + p*16) * 72) + s*16 + bcoladd) * 2u;
                    ldsm_x4(b0, b1v, b2, b3, bd);
                    mma_fp16(acc[0][2*p],   a[0], b0, b1v);
                    mma_fp16(acc[0][2*p+1], a[0], b2, b3);
                    mma_fp16(acc[1][2*p],   a[1], b0, b1v);
                    mma_fp16(acc[1][2*p+1], a[1], b2, b3);
                }
            }
        }
    }

    // ===== epilogue 2: p = elu(acc + b2)+1, row L2 norm, write fp16 =====
    float ss[2][2] = {};
    #pragma unroll
    for (int mt = 0; mt < 2; ++mt)
        #pragma unroll
        for (int nt = 0; nt < 8; ++nt) {
            const int col = wn*64 + nt*8 + tq*2;
            #pragma unroll
            for (int h = 0; h < 2; ++h)
                #pragma unroll
                for (int pr = 0; pr < 2; ++pr) {
                    float x = acc[mt][nt][h*2+pr] + sB2[col+pr];
                    float p = (x > 0.f) ? (x + 1.f) : __expf(x);
                    acc[mt][nt][h*2+pr] = p;
                    ss[mt][h] = fmaf(p, p, ss[mt][h]);
                }
        }
    #pragma unroll
    for (int m = 1; m <= 2; m <<= 1)
        #pragma unroll
        for (int mt = 0; mt < 2; ++mt)
            #pragma unroll
            for (int h = 0; h < 2; ++h)
                ss[mt][h] += __shfl_xor_sync(0xffffffffu, ss[mt][h], m);
    if (tq == 0) {
        #pragma unroll
        for (int mt = 0; mt < 2; ++mt)
            #pragma unroll
            for (int h = 0; h < 2; ++h)
                sPrt[wn*128 + wm*32 + mt*16 + 8*h + g] = ss[mt][h];
    }
    __syncthreads();
    if (tid < 128)
        sInv[tid] = 1.f / (sqrtf(sPrt[tid] + sPrt[128+tid] +
                                 sPrt[256+tid] + sPrt[384+tid]) + 1e-6f);
    __syncthreads();

    #pragma unroll
    for (int mt = 0; mt < 2; ++mt)
        #pragma unroll
        for (int h = 0; h < 2; ++h) {
            const int row = wm*32 + mt*16 + 8*h + g;
            const float inv = sInv[row];
            __half* dr = dst + (size_t)(tok0 + row) * FF;
            #pragma unroll
            for (int nt = 0; nt < 8; ++nt) {
                const int col = wn*64 + nt*8 + tq*2;
                *reinterpret_cast<__half2*>(dr + col) =
                    __floats2half2_rn(acc[mt][nt][h*2] * inv,
                                      acc[mt][nt][h*2+1] * inv);
            }
        }
}

// ---------------------------------------------------------------------------
// kv kernel: grid (32, 2, KSPLIT=4), 512 threads, 2 CTAs/SM (one wave).
// kvp[f0+128, 128] over 1024 seq. ldmatrix.trans both sides. cp.async S=2.
// SMEM: 2 x (P [32][136]h + V [32][136]h) = 34816 B.
// ---------------------------------------------------------------------------
#define KV_SMEM 34816

__global__ void __launch_bounds__(512, 2) kv_mma_kernel()
{
    extern __shared__ char kvc[];
    const uint32_t sbase = smem_u32(kvc);

    const int hh = blockIdx.x;
    const int f0 = blockIdx.y * 128;
    const int ks = blockIdx.z;
    const int tid  = threadIdx.x;
    const int lane = tid & 31;
    const int wid  = tid >> 5;
    const int g  = lane >> 2;
    const int tq = lane & 3;
    const int wm = wid & 3;
    const int wn = wid >> 2;

    const __half* pbase = g_phi_k + ((size_t)hh * NSEQ + (size_t)ks * 1024) * FF + f0;
    const __half* vbase = g_vh    + ((size_t)hh * NSEQ + (size_t)ks * 1024) * DD;

    auto issue = [&](int b, int slot) {
        uint32_t base = sbase + (uint32_t)slot * 17408u;
        #pragma unroll
        for (int l = 0; l < 2; ++l) {
            int u = tid + l * 512;          // 0..1023
            int row = (u >> 4) & 31, seg = u & 15;
            if (u < 512)
                cp_async16(base + row*272 + seg*16,
                           pbase + (size_t)(b*32 + row)*FF + seg*8);
            else
                cp_async16(base + 8704u + row*272 + seg*16,
                           vbase + (size_t)(b*32 + row)*DD + seg*8);
        }
        CP_COMMIT();
    };

    issue(0, 0);

    float acc[2][4][4];
    #pragma unroll
    for (int mt = 0; mt < 2; ++mt)
        #pragma unroll
        for (int nt = 0; nt < 4; ++nt)
            #pragma unroll
            for (int e = 0; e < 4; ++e) acc[mt][nt][e] = 0.f;
    float ksacc = 0.f;

    const int aseq = ((lane >> 4) << 3) + (lane & 7);      // A: seq row
    const int afc  = wm*32 + ((lane >> 3) & 1) * 8;        // A: f col
    const int bseq = ((lane >> 3) & 1) * 8 + (lane & 7);   // B: seq row
    const int bdc  = wn*32 + ((lane >> 4) << 3);           // B: d col

    for (int b = 0; b < 32; ++b) {
        CP_WAIT0();
        __syncthreads();
        if (b < 31) issue(b + 1, (b + 1) & 1);

        const uint32_t pb = sbase + (uint32_t)(b & 1) * 17408u;
        const uint32_t vb = pb + 8704u;
        const __half* sP = reinterpret_cast<const __half*>(kvc + (b & 1) * 17408);

        if (tid < 128) {
            #pragma unroll
            for (int r = 0; r < 32; ++r)
                ksacc += __half2float(sP[r*136 + tid]);
        }

        uint32_t a[2][2][4];
        #pragma unroll
        for (int s = 0; s < 2; ++s)
            #pragma unroll
            for (int mt = 0; mt < 2; ++mt) {
                uint32_t ad = pb + (uint32_t)(((s*16 + aseq) * 136) + afc + mt*16) * 2u;
                ldsm_x4t(a[mt][s][0], a[mt][s][1], a[mt][s][2], a[mt][s][3], ad);
            }
        #pragma unroll
        for (int s = 0; s < 2; ++s)
            #pragma unroll
            for (int p = 0; p < 2; ++p) {
                uint32_t b0, b1v, b2, b3;
                uint32_t bd = vb + (uint32_t)(((s*16 + bseq) * 136) + bdc + p*16) * 2u;
                ldsm_x4t(b0, b1v, b2, b3, bd);
                mma_fp16(acc[0][2*p],   a[0][s], b0, b1v);
                mma_fp16(acc[0][2*p+1], a[0][s], b2, b3);
                mma_fp16(acc[1][2*p],   a[1][s], b0, b1v);
                mma_fp16(acc[1][2*p+1], a[1][s], b2, b3);
            }
    }

    float* outp = g_kvp + ((size_t)ks * BH + hh) * FF * DD;
    #pragma unroll
    for (int mt = 0; mt < 2; ++mt)
        #pragma unroll
        for (int h = 0; h < 2; ++h) {
            const int f = f0 + wm*32 + mt*16 + 8*h + g;
            #pragma unroll
            for (int nt = 0; nt < 4; ++nt) {
                const int d = wn*32 + nt*8 + tq*2;
                *reinterpret_cast<float2*>(outp + (size_t)f * DD + d) =
                    make_float2(acc[mt][nt][h*2], acc[mt][nt][h*2+1]);
            }
        }
    if (tid < 128)
        g_ksp[((size_t)ks * BH + hh) * FF + f0 + tid] = ksacc;
}

// ---------------------------------------------------------------------------
// reduce kernel: fold KSPLIT partials (float4), write g_kvh fp16 + g_ksum.
// ---------------------------------------------------------------------------
__global__ void reduce_kernel()
{
    const int NKV4 = BH * FF * DD / 4;    // 262144
    const int NKS  = BH * FF;             // 8192
    int i = blockIdx.x * blockDim.x + threadIdx.x;
    if (i < NKV4) {
        float4 s = make_float4(0.f, 0.f, 0.f, 0.f);
        #pragma unroll
        for (int p = 0; p < KSPLIT; ++p) {
            float4 t = reinterpret_cast<const float4*>(g_kvp)[(size_t)p * NKV4 + i];
            s.x += t.x; s.y += t.y; s.z += t.z; s.w += t.w;
        }
        __half2* o = reinterpret_cast<__half2*>(g_kvh + (size_t)i*4);
        o[0] = __floats2half2_rn(s.x, s.y);
        o[1] = __floats2half2_rn(s.z, s.w);
    } else {
        int j = i - NKV4;
        if (j < NKS) {
            float s = 0.f;
            #pragma unroll
            for (int p = 0; p < KSPLIT; ++p) s += g_ksp[(size_t)p * NKS + j];
            g_ksum[j] = s;
        }
    }
}

// ---------------------------------------------------------------------------
// qkv kernel: grid (32, 32), 512 threads. out = phi_q @ kv / max(den, eps).
// A = phi_q (non-trans), B = kv (trans). cp.async S=2.
// SMEM: 2 x (A [128][40]h + B [32][136]h) = 37888 B dynamic.
// ---------------------------------------------------------------------------
#define QKV_SMEM 37888

__global__ void __launch_bounds__(512) qkv_mma_kernel(float* __restrict__ out)
{
    extern __shared__ char qc[];
    __shared__ float sKs[2][32];
    __shared__ float sDen[128];
    const uint32_t sbase = smem_u32(qc);

    const int hh = blockIdx.x;
    const int m0 = blockIdx.y * 128;
    const int tid  = threadIdx.x;
    const int lane = tid & 31;
    const int wid  = tid >> 5;
    const int g  = lane >> 2;
    const int tq = lane & 3;
    const int wm = wid & 3;
    const int wn = wid >> 2;

    const __half* agb = g_phi_q + ((size_t)hh * NSEQ + m0) * FF;
    const __half* bgb = g_kvh + (size_t)hh * FF * DD;

    auto issue = [&](int kc, int slot) {
        uint32_t base = sbase + (uint32_t)slot * 18944u;
        #pragma unroll
        for (int l = 0; l < 2; ++l) {
            int u = tid + l * 512;
            if (u < 512) {                  // A: 128 rows x 4 segs
                int row = u >> 2, seg = u & 3;
                cp_async16(base + row*80 + seg*16,
                           agb + (size_t)row*FF + kc*32 + seg*8);
            } else {                        // B: 32 rows x 16 segs
                int w = u - 512;
                int row = w >> 4, seg = w & 15;
                cp_async16(base + 10240u + row*272 + seg*16,
                           bgb + (size_t)(kc*32 + row)*DD + seg*8);
            }
        }
        CP_COMMIT();
    };

    issue(0, 0);
    if (tid < 32) sKs[0][tid] = g_ksum[(size_t)hh * FF + tid];

    float acc[2][2][4];
    float acc2[2][2][4];
    #pragma unroll
    for (int mt = 0; mt < 2; ++mt)
        #pragma unroll
        for (int nt = 0; nt < 2; ++nt)
            #pragma unroll
            for (int e = 0; e < 4; ++e) { acc[mt][nt][e] = 0.f; acc2[mt][nt][e] = 0.f; }
    float den = 0.f;

    const int amrow   = wm*32 + (lane & 15);
    const int acoladd = ((lane >> 4) << 3);
    const int bseq = ((lane >> 3) & 1) * 8 + (lane & 7);
    const int bdc  = wn*32 + ((lane >> 4) << 3);

    for (int kc = 0; kc < 8; ++kc) {
        CP_WAIT0();
        __syncthreads();
        if (kc < 7) {
            issue(kc + 1, (kc + 1) & 1);
            if (tid < 32)
                sKs[(kc+1) & 1][tid] = g_ksum[(size_t)hh * FF + (kc+1)*32 + tid];
        }

        const uint32_t ab = sbase + (uint32_t)(kc & 1) * 18944u;
        const uint32_t bb = ab + 10240u;
        const __half* sAhp = reinterpret_cast<const __half*>(qc + (kc & 1) * 18944);
        const float* ks = sKs[kc & 1];

        if (tid < 128) {
            #pragma unroll
            for (int kk = 0; kk < 32; ++kk)
                den = fmaf(__half2float(sAhp[tid*40 + kk]), ks[kk], den);
        }

        uint32_t a[2][2][4];
        #pragma unroll
        for (int s = 0; s < 2; ++s)
            #pragma unroll
            for (int mt = 0; mt < 2; ++mt) {
                uint32_t ad = ab + (uint32_t)(((amrow + mt*16) * 40) + s*16 + acoladd) * 2u;
                ldsm_x4(a[mt][s][0], a[mt][s][1], a[mt][s][2], a[mt][s][3], ad);
            }
        #pragma unroll
        for (int s = 0; s < 2; ++s)
            #pragma unroll
            for (int p = 0; p < 2; ++p) {
                uint32_t b0, b1v, b2, b3;
                uint32_t bd = bb + (uint32_t)(((s*16 + bseq) * 136) + bdc + p*16) * 2u;
                ldsm_x4t(b0, b1v, b2, b3, bd);
                if (p == 0) {
                    mma_fp16(acc[0][0], a[0][s], b0, b1v);
                    mma_fp16(acc[0][1], a[0][s], b2, b3);
                    mma_fp16(acc[1][0], a[1][s], b0, b1v);
                    mma_fp16(acc[1][1], a[1][s], b2, b3);
                } else {
                    mma_fp16(acc2[0][0], a[0][s], b0, b1v);
                    mma_fp16(acc2[0][1], a[0][s], b2, b3);
                    mma_fp16(acc2[1][0], a[1][s], b0, b1v);
                    mma_fp16(acc2[1][1], a[1][s], b2, b3);
                }
            }
    }

    if (tid < 128) sDen[tid] = den;
    __syncthreads();

    float* op = out + ((size_t)hh * NSEQ + m0) * DD;
    #pragma unroll
    for (int mt = 0; mt < 2; ++mt)
        #pragma unroll
        for (int h = 0; h < 2; ++h) {
            const int row = wm*32 + mt*16 + 8*h + g;
            const float invd = 1.f / fmaxf(sDen[row], 1e-6f);
            #pragma unroll
            for (int nt = 0; nt < 4; ++nt) {
                const int d = wn*32 + nt*8 + tq*2;
                const float* av = (nt < 2) ? acc[mt][nt] : acc2[mt][nt-2];
                *reinterpret_cast<float2*>(op + (size_t)row * DD + d) =
                    make_float2(av[h*2] * invd, av[h*2+1] * invd);
            }
        }
}

// ---------------------------------------------------------------------------
extern "C" void kernel_launch(void* const* d_in, const int* in_sizes, int n_in,
                              void* d_out, int out_size)
{
    (void)in_sizes; (void)n_in; (void)out_size;
    const float* q  = (const float*)d_in[0];
    const float* k  = (const float*)d_in[1];
    const float* v  = (const float*)d_in[2];
    const float* W1 = (const float*)d_in[3];
    const float* b1 = (const float*)d_in[4];
    const float* W2 = (const float*)d_in[5];
    const float* b2 = (const float*)d_in[6];
    float* out = (float*)d_out;

    cudaFuncSetAttribute(phi_mma_kernel, cudaFuncAttributeMaxDynamicSharedMemorySize, PHI_SMEM);
    cudaFuncSetAttribute(kv_mma_kernel,  cudaFuncAttributeMaxDynamicSharedMemorySize, KV_SMEM);
    cudaFuncSetAttribute(qkv_mma_kernel, cudaFuncAttributeMaxDynamicSharedMemorySize, QKV_SMEM);

    prep_kernel<<<(6*16384 + 255) / 256, 256>>>(W1, W2);
    vprep_kernel<<<(NTOK*DD/4 + 255) / 256, 256>>>(v);
    phi_mma_kernel<<<2048, 512, PHI_SMEM>>>(q, k, b1, b2);
    kv_mma_kernel<<<dim3(32, 2, KSPLIT), 512, KV_SMEM>>>();
    {
        const int total = BH*FF*DD/4 + BH*FF;
        reduce_kernel<<<(total + 255) / 256, 256>>>();
    }
    qkv_mma_kernel<<<dim3(32, 32), 512, QKV_SMEM>>>(out);
}

// round 11
// speedup vs baseline: 4.2355x; 1.0709x over previous
#include <cuda_runtime.h>
#include <cuda_fp16.h>
#include <math.h>
#include <stdint.h>

// Problem constants
#define BH    32
#define NSEQ  4096
#define DD    128
#define FF    256
#define NTOK  (BH*NSEQ)
#define KSPLIT 4

// Scratch (device globals: allocation-free rule)
__device__ __half g_phi_q[(size_t)NTOK*FF];
__device__ __half g_phi_k[(size_t)NTOK*FF];
__device__ float  g_kvp[(size_t)KSPLIT*BH*FF*DD];
__device__ float  g_ksp[(size_t)KSPLIT*BH*FF];
__device__ __half g_kvh[(size_t)BH*FF*DD];
__device__ float  g_ksum[(size_t)BH*FF];
__device__ __half g_Wh[6*16384];          // W chunks [kc6][n=256][k=64] fp16
__device__ __half g_vh[(size_t)NTOK*DD];  // fp16-rounded v

// ---------------------------------------------------------------------------
// helpers
// ---------------------------------------------------------------------------
__device__ __forceinline__ uint32_t smem_u32(const void* p) {
    return (uint32_t)__cvta_generic_to_shared(p);
}
__device__ __forceinline__ void cp_async16(uint32_t dst, const void* src) {
    asm volatile("cp.async.cg.shared.global [%0], [%1], 16;"
                 :: "r"(dst), "l"(src) : "memory");
}
#define CP_COMMIT() asm volatile("cp.async.commit_group;" ::: "memory")
#define CP_WAIT0()  asm volatile("cp.async.wait_group 0;" ::: "memory")

__device__ __forceinline__ void ldsm_x4(uint32_t& r0, uint32_t& r1,
                                        uint32_t& r2, uint32_t& r3, uint32_t a) {
    asm volatile("ldmatrix.sync.aligned.m8n8.x4.shared.b16 {%0,%1,%2,%3}, [%4];"
                 : "=r"(r0), "=r"(r1), "=r"(r2), "=r"(r3) : "r"(a));
}
__device__ __forceinline__ void ldsm_x4t(uint32_t& r0, uint32_t& r1,
                                         uint32_t& r2, uint32_t& r3, uint32_t a) {
    asm volatile("ldmatrix.sync.aligned.m8n8.x4.trans.shared.b16 {%0,%1,%2,%3}, [%4];"
                 : "=r"(r0), "=r"(r1), "=r"(r2), "=r"(r3) : "r"(a));
}
__device__ __forceinline__ void mma_fp16(float* d, const uint32_t* a,
                                         uint32_t b0, uint32_t b1) {
    asm volatile("mma.sync.aligned.m16n8k16.row.col.f32.f16.f16.f32 "
                 "{%0,%1,%2,%3}, {%4,%5,%6,%7}, {%8,%9}, {%0,%1,%2,%3};"
                 : "+f"(d[0]), "+f"(d[1]), "+f"(d[2]), "+f"(d[3])
                 : "r"(a[0]), "r"(a[1]), "r"(a[2]), "r"(a[3]),
                   "r"(b0), "r"(b1));
}

// ---------------------------------------------------------------------------
// prep: W1/W2 -> fp16 chunk images [kc6][n=256][k=64]; vprep: v -> fp16.
// ---------------------------------------------------------------------------
__global__ void prep_kernel(const float* __restrict__ W1, const float* __restrict__ W2)
{
    int i = blockIdx.x * blockDim.x + threadIdx.x;
    if (i >= 6*16384) return;
    int kc = i >> 14, r = i & 16383;
    int n = r >> 6, kk = r & 63;
    float w = (kc < 2) ? W1[(kc*64 + kk)*256 + n] : W2[((kc-2)*64 + kk)*256 + n];
    g_Wh[kc*16384 + n*64 + kk] = __float2half_rn(w);
}

__global__ void vprep_kernel(const float* __restrict__ v)
{
    int i = blockIdx.x * blockDim.x + threadIdx.x;   // float4 index
    if (i >= NTOK*DD/4) return;
    float4 t = reinterpret_cast<const float4*>(v)[i];
    __half2* o = reinterpret_cast<__half2*>(g_vh + (size_t)i*4);
    o[0] = __floats2half2_rn(t.x, t.y);
    o[1] = __floats2half2_rn(t.z, t.w);
}

// ---------------------------------------------------------------------------
// phi kernel (fp16 mma m16n8k16, 64-wide K chunks, cp.async S=2).
// 64 tokens/CTA, 256 threads (8 warps, 2M x 4N, warp tile 32x64),
// 2 CTAs/SM for cross-CTA latency hiding. grid 4096.
// SMEM bytes:
//   A @0       : X [64][136]h (stage1) overlaid by H [64][264]h -> 33792
//   W @33792   : 2 x [256][72]h = 73728  (ends 107520)
//   B1 @107520, B2 @108544 (f32 x256), PRT @109568 (f32 x256), INV @110592 (64)
// total 110848 B -> 2 CTAs/SM (221696 <= 228KB)
// ---------------------------------------------------------------------------
#define PHI_SMEM 110848
#define WBUF_B   36864u

__global__ void __launch_bounds__(256, 2) phi_mma_kernel(
    const float* __restrict__ q, const float* __restrict__ k,
    const float* __restrict__ b1, const float* __restrict__ b2)
{
    extern __shared__ char smc[];
    __half* sAh = reinterpret_cast<__half*>(smc);
    float* sB1  = reinterpret_cast<float*>(smc + 107520);
    float* sB2  = reinterpret_cast<float*>(smc + 108544);
    float* sPrt = reinterpret_cast<float*>(smc + 109568);
    float* sInv = reinterpret_cast<float*>(smc + 110592);
    const uint32_t abase = smem_u32(smc);
    const uint32_t wbase = abase + 33792u;

    const int tid  = threadIdx.x;
    const int wid  = tid >> 5;
    const int lane = tid & 31;
    const int g    = lane >> 2;
    const int tq   = lane & 3;
    const int wm   = wid & 1;    // 2 M tiles of 32 tokens
    const int wn   = wid >> 1;   // 4 N tiles of 64 cols

    const int bid = blockIdx.x;
    const float* src = (bid < 2048) ? q : k;
    __half*      dst = (bid < 2048) ? g_phi_q : g_phi_k;
    const int tok0 = (bid & 2047) * 64;

    // prologue: issue W chunk 0 -> buf0 (256 rows x 8 segs of 16B)
    {
        #pragma unroll
        for (int l = 0; l < 8; ++l) {
            int u = tid + l * 256;          // 0..2047
            int n = u >> 3, seg = u & 7;
            cp_async16(wbase + n*144 + seg*16, g_Wh + n*64 + seg*8);
        }
        CP_COMMIT();
    }

    // stage X [64][128] -> fp16 smem, stride 136 halfs
    {
        const float4* s4 = reinterpret_cast<const float4*>(src + (size_t)tok0 * DD);
        #pragma unroll
        for (int l = 0; l < 8; ++l) {
            int id  = tid + l * 256;        // 0..2047 float4
            int row = id >> 5, c4 = id & 31;
            float4 v = s4[row * 32 + c4];
            __half2* p = reinterpret_cast<__half2*>(sAh + row*136 + c4*4);
            p[0] = __floats2half2_rn(v.x, v.y);
            p[1] = __floats2half2_rn(v.z, v.w);
        }
    }
    sB1[tid] = b1[tid];
    sB2[tid] = b2[tid];

    float acc[2][8][4];
    #pragma unroll
    for (int mt = 0; mt < 2; ++mt)
        #pragma unroll
        for (int nt = 0; nt < 8; ++nt)
            #pragma unroll
            for (int e = 0; e < 4; ++e) acc[mt][nt][e] = 0.f;

    // ldmatrix lane address components
    const int amrow   = wm*32 + (lane & 15);       // A row (token)
    const int acoladd = ((lane >> 4) << 3);        // A k offset
    const int bnrow   = wn*64 + ((lane >> 4) << 3) + (lane & 7);  // B n row
    const int bcoladd = ((lane >> 3) & 1) * 8;     // B k offset

    // ---- main chunk loop: kc 0..1 stage1 (K=128), 2..5 stage2 (K=256) ----
    for (int kc = 0; kc < 6; ++kc) {
        CP_WAIT0();
        __syncthreads();   // buf kc&1 ready & visible; compute kc-1 done

        if (kc < 5) {      // issue chunk kc+1
            const __half* img = g_Wh + (kc + 1) * 16384;
            uint32_t dstb = wbase + (uint32_t)((kc + 1) & 1) * WBUF_B;
            #pragma unroll
            for (int l = 0; l < 8; ++l) {
                int u = tid + l * 256;
                int n = u >> 3, seg = u & 7;
                cp_async16(dstb + n*144 + seg*16, img + n*64 + seg*8);
            }
            CP_COMMIT();
        }

        if (kc == 2) {
            // ===== epilogue 1: H = silu(acc + b1) -> fp16 smem stride 264 ====
            #pragma unroll
            for (int mt = 0; mt < 2; ++mt)
                #pragma unroll
                for (int nt = 0; nt < 8; ++nt) {
                    const int col = wn*64 + nt*8 + tq*2;
                    #pragma unroll
                    for (int h = 0; h < 2; ++h) {
                        const int row = wm*32 + mt*16 + 8*h + g;
                        float x0 = acc[mt][nt][h*2]   + sB1[col];
                        float x1 = acc[mt][nt][h*2+1] + sB1[col+1];
                        float s0 = x0 / (1.f + __expf(-x0));
                        float s1 = x1 / (1.f + __expf(-x1));
                        *reinterpret_cast<__half2*>(sAh + row*264 + col) =
                            __floats2half2_rn(s0, s1);
                        acc[mt][nt][h*2] = 0.f;
                        acc[mt][nt][h*2+1] = 0.f;
                    }
                }
            __syncthreads();   // H visible
        }

        // ---- compute on W buf kc&1 (4 k16-steps of the 64-wide chunk) ----
        {
            const bool s1s = (kc < 2);
            const int astr = s1s ? 136 : 264;
            const int k0   = (s1s ? kc : (kc - 2)) * 64;
            const uint32_t wb = wbase + (uint32_t)(kc & 1) * WBUF_B;

            #pragma unroll
            for (int s = 0; s < 4; ++s) {
                uint32_t a[2][4];
                #pragma unroll
                for (int mt = 0; mt < 2; ++mt) {
                    uint32_t ad = abase +
                        (uint32_t)(((amrow + mt*16) * astr) + k0 + s*16 + acoladd) * 2u;
                    ldsm_x4(a[mt][0], a[mt][1], a[mt][2], a[mt][3], ad);
                }
                #pragma unroll
                for (int p = 0; p < 4; ++p) {
                    uint32_t b0, b1v, b2, b3;
                    uint32_t bd = wb +
                        (uint32_t)(((bnrow + p*16) * 72) + s*16 + bcoladd) * 2u;
                    ldsm_x4(b0, b1v, b2, b3, bd);
                    mma_fp16(acc[0][2*p],   a[0], b0, b1v);
                    mma_fp16(acc[0][2*p+1], a[0], b2, b3);
                    mma_fp16(acc[1][2*p],   a[1], b0, b1v);
                    mma_fp16(acc[1][2*p+1], a[1], b2, b3);
                }
            }
        }
    }

    // ===== epilogue 2: p = elu(acc + b2)+1, row L2 norm, write fp16 =====
    float ss[2][2] = {};
    #pragma unroll
    for (int mt = 0; mt < 2; ++mt)
        #pragma unroll
        for (int nt = 0; nt < 8; ++nt) {
            const int col = wn*64 + nt*8 + tq*2;
            #pragma unroll
            for (int h = 0; h < 2; ++h)
                #pragma unroll
                for (int pr = 0; pr < 2; ++pr) {
                    float x = acc[mt][nt][h*2+pr] + sB2[col+pr];
                    float p = (x > 0.f) ? (x + 1.f) : __expf(x);
                    acc[mt][nt][h*2+pr] = p;
                    ss[mt][h] = fmaf(p, p, ss[mt][h]);
                }
        }
    #pragma unroll
    for (int m = 1; m <= 2; m <<= 1)
        #pragma unroll
        for (int mt = 0; mt < 2; ++mt)
            #pragma unroll
            for (int h = 0; h < 2; ++h)
                ss[mt][h] += __shfl_xor_sync(0xffffffffu, ss[mt][h], m);
    if (tq == 0) {
        #pragma unroll
        for (int mt = 0; mt < 2; ++mt)
            #pragma unroll
            for (int h = 0; h < 2; ++h)
                sPrt[wn*64 + wm*32 + mt*16 + 8*h + g] = ss[mt][h];
    }
    __syncthreads();
    if (tid < 64)
        sInv[tid] = 1.f / (sqrtf(sPrt[tid] + sPrt[64+tid] +
                                 sPrt[128+tid] + sPrt[192+tid]) + 1e-6f);
    __syncthreads();

    #pragma unroll
    for (int mt = 0; mt < 2; ++mt)
        #pragma unroll
        for (int h = 0; h < 2; ++h) {
            const int row = wm*32 + mt*16 + 8*h + g;
            const float inv = sInv[row];
            __half* dr = dst + (size_t)(tok0 + row) * FF;
            #pragma unroll
            for (int nt = 0; nt < 8; ++nt) {
                const int col = wn*64 + nt*8 + tq*2;
                *reinterpret_cast<__half2*>(dr + col) =
                    __floats2half2_rn(acc[mt][nt][h*2] * inv,
                                      acc[mt][nt][h*2+1] * inv);
            }
        }
}

// ---------------------------------------------------------------------------
// kv kernel: grid (32, 2, KSPLIT=4), 512 threads, 2 CTAs/SM (one wave).
// (unchanged from R10 — 44us)
// ---------------------------------------------------------------------------
#define KV_SMEM 34816

__global__ void __launch_bounds__(512, 2) kv_mma_kernel()
{
    extern __shared__ char kvc[];
    const uint32_t sbase = smem_u32(kvc);

    const int hh = blockIdx.x;
    const int f0 = blockIdx.y * 128;
    const int ks = blockIdx.z;
    const int tid  = threadIdx.x;
    const int lane = tid & 31;
    const int wid  = tid >> 5;
    const int g  = lane >> 2;
    const int tq = lane & 3;
    const int wm = wid & 3;
    const int wn = wid >> 2;

    const __half* pbase = g_phi_k + ((size_t)hh * NSEQ + (size_t)ks * 1024) * FF + f0;
    const __half* vbase = g_vh    + ((size_t)hh * NSEQ + (size_t)ks * 1024) * DD;

    auto issue = [&](int b, int slot) {
        uint32_t base = sbase + (uint32_t)slot * 17408u;
        #pragma unroll
        for (int l = 0; l < 2; ++l) {
            int u = tid + l * 512;          // 0..1023
            int row = (u >> 4) & 31, seg = u & 15;
            if (u < 512)
                cp_async16(base + row*272 + seg*16,
                           pbase + (size_t)(b*32 + row)*FF + seg*8);
            else
                cp_async16(base + 8704u + row*272 + seg*16,
                           vbase + (size_t)(b*32 + row)*DD + seg*8);
        }
        CP_COMMIT();
    };

    issue(0, 0);

    float acc[2][4][4];
    #pragma unroll
    for (int mt = 0; mt < 2; ++mt)
        #pragma unroll
        for (int nt = 0; nt < 4; ++nt)
            #pragma unroll
            for (int e = 0; e < 4; ++e) acc[mt][nt][e] = 0.f;
    float ksacc = 0.f;

    const int aseq = ((lane >> 4) << 3) + (lane & 7);      // A: seq row
    const int afc  = wm*32 + ((lane >> 3) & 1) * 8;        // A: f col
    const int bseq = ((lane >> 3) & 1) * 8 + (lane & 7);   // B: seq row
    const int bdc  = wn*32 + ((lane >> 4) << 3);           // B: d col

    for (int b = 0; b < 32; ++b) {
        CP_WAIT0();
        __syncthreads();
        if (b < 31) issue(b + 1, (b + 1) & 1);

        const uint32_t pb = sbase + (uint32_t)(b & 1) * 17408u;
        const uint32_t vb = pb + 8704u;
        const __half* sP = reinterpret_cast<const __half*>(kvc + (b & 1) * 17408);

        if (tid < 128) {
            #pragma unroll
            for (int r = 0; r < 32; ++r)
                ksacc += __half2float(sP[r*136 + tid]);
        }

        uint32_t a[2][2][4];
        #pragma unroll
        for (int s = 0; s < 2; ++s)
            #pragma unroll
            for (int mt = 0; mt < 2; ++mt) {
                uint32_t ad = pb + (uint32_t)(((s*16 + aseq) * 136) + afc + mt*16) * 2u;
                ldsm_x4t(a[mt][s][0], a[mt][s][1], a[mt][s][2], a[mt][s][3], ad);
            }
        #pragma unroll
        for (int s = 0; s < 2; ++s)
            #pragma unroll
            for (int p = 0; p < 2; ++p) {
                uint32_t b0, b1v, b2, b3;
                uint32_t bd = vb + (uint32_t)(((s*16 + bseq) * 136) + bdc + p*16) * 2u;
                ldsm_x4t(b0, b1v, b2, b3, bd);
                mma_fp16(acc[0][2*p],   a[0][s], b0, b1v);
                mma_fp16(acc[0][2*p+1], a[0][s], b2, b3);
                mma_fp16(acc[1][2*p],   a[1][s], b0, b1v);
                mma_fp16(acc[1][2*p+1], a[1][s], b2, b3);
            }
    }

    float* outp = g_kvp + ((size_t)ks * BH + hh) * FF * DD;
    #pragma unroll
    for (int mt = 0; mt < 2; ++mt)
        #pragma unroll
        for (int h = 0; h < 2; ++h) {
            const int f = f0 + wm*32 + mt*16 + 8*h + g;
            #pragma unroll
            for (int nt = 0; nt < 4; ++nt) {
                const int d = wn*32 + nt*8 + tq*2;
                *reinterpret_cast<float2*>(outp + (size_t)f * DD + d) =
                    make_float2(acc[mt][nt][h*2], acc[mt][nt][h*2+1]);
            }
        }
    if (tid < 128)
        g_ksp[((size_t)ks * BH + hh) * FF + f0 + tid] = ksacc;
}

// ---------------------------------------------------------------------------
// reduce kernel: fold KSPLIT partials (float4), write g_kvh fp16 + g_ksum.
// ---------------------------------------------------------------------------
__global__ void reduce_kernel()
{
    const int NKV4 = BH * FF * DD / 4;    // 262144
    const int NKS  = BH * FF;             // 8192
    int i = blockIdx.x * blockDim.x + threadIdx.x;
    if (i < NKV4) {
        float4 s = make_float4(0.f, 0.f, 0.f, 0.f);
        #pragma unroll
        for (int p = 0; p < KSPLIT; ++p) {
            float4 t = reinterpret_cast<const float4*>(g_kvp)[(size_t)p * NKV4 + i];
            s.x += t.x; s.y += t.y; s.z += t.z; s.w += t.w;
        }
        __half2* o = reinterpret_cast<__half2*>(g_kvh + (size_t)i*4);
        o[0] = __floats2half2_rn(s.x, s.y);
        o[1] = __floats2half2_rn(s.z, s.w);
    } else {
        int j = i - NKV4;
        if (j < NKS) {
            float s = 0.f;
            #pragma unroll
            for (int p = 0; p < KSPLIT; ++p) s += g_ksp[(size_t)p * NKS + j];
            g_ksum[j] = s;
        }
    }
}

// ---------------------------------------------------------------------------
// qkv kernel: grid (32, 32), 512 threads. (unchanged from R10 — ~55us)
// ---------------------------------------------------------------------------
#define QKV_SMEM 37888

__global__ void __launch_bounds__(512) qkv_mma_kernel(float* __restrict__ out)
{
    extern __shared__ char qc[];
    __shared__ float sKs[2][32];
    __shared__ float sDen[128];
    const uint32_t sbase = smem_u32(qc);

    const int hh = blockIdx.x;
    const int m0 = blockIdx.y * 128;
    const int tid  = threadIdx.x;
    const int lane = tid & 31;
    const int wid  = tid >> 5;
    const int g  = lane >> 2;
    const int tq = lane & 3;
    const int wm = wid & 3;
    const int wn = wid >> 2;

    const __half* agb = g_phi_q + ((size_t)hh * NSEQ + m0) * FF;
    const __half* bgb = g_kvh + (size_t)hh * FF * DD;

    auto issue = [&](int kc, int slot) {
        uint32_t base = sbase + (uint32_t)slot * 18944u;
        #pragma unroll
        for (int l = 0; l < 2; ++l) {
            int u = tid + l * 512;
            if (u < 512) {                  // A: 128 rows x 4 segs
                int row = u >> 2, seg = u & 3;
                cp_async16(base + row*80 + seg*16,
                           agb + (size_t)row*FF + kc*32 + seg*8);
            } else {                        // B: 32 rows x 16 segs
                int w = u - 512;
                int row = w >> 4, seg = w & 15;
                cp_async16(base + 10240u + row*272 + seg*16,
                           bgb + (size_t)(kc*32 + row)*DD + seg*8);
            }
        }
        CP_COMMIT();
    };

    issue(0, 0);
    if (tid < 32) sKs[0][tid] = g_ksum[(size_t)hh * FF + tid];

    float acc[2][2][4];
    float acc2[2][2][4];
    #pragma unroll
    for (int mt = 0; mt < 2; ++mt)
        #pragma unroll
        for (int nt = 0; nt < 2; ++nt)
            #pragma unroll
            for (int e = 0; e < 4; ++e) { acc[mt][nt][e] = 0.f; acc2[mt][nt][e] = 0.f; }
    float den = 0.f;

    const int amrow   = wm*32 + (lane & 15);
    const int acoladd = ((lane >> 4) << 3);
    const int bseq = ((lane >> 3) & 1) * 8 + (lane & 7);
    const int bdc  = wn*32 + ((lane >> 4) << 3);

    for (int kc = 0; kc < 8; ++kc) {
        CP_WAIT0();
        __syncthreads();
        if (kc < 7) {
            issue(kc + 1, (kc + 1) & 1);
            if (tid < 32)
                sKs[(kc+1) & 1][tid] = g_ksum[(size_t)hh * FF + (kc+1)*32 + tid];
        }

        const uint32_t ab = sbase + (uint32_t)(kc & 1) * 18944u;
        const uint32_t bb = ab + 10240u;
        const __half* sAhp = reinterpret_cast<const __half*>(qc + (kc & 1) * 18944);
        const float* ks = sKs[kc & 1];

        if (tid < 128) {
            #pragma unroll
            for (int kk = 0; kk < 32; ++kk)
                den = fmaf(__half2float(sAhp[tid*40 + kk]), ks[kk], den);
        }

        uint32_t a[2][2][4];
        #pragma unroll
        for (int s = 0; s < 2; ++s)
            #pragma unroll
            for (int mt = 0; mt < 2; ++mt) {
                uint32_t ad = ab + (uint32_t)(((amrow + mt*16) * 40) + s*16 + acoladd) * 2u;
                ldsm_x4(a[mt][s][0], a[mt][s][1], a[mt][s][2], a[mt][s][3], ad);
            }
        #pragma unroll
        for (int s = 0; s < 2; ++s)
            #pragma unroll
            for (int p = 0; p < 2; ++p) {
                uint32_t b0, b1v, b2, b3;
                uint32_t bd = bb + (uint32_t)(((s*16 + bseq) * 136) + bdc + p*16) * 2u;
                ldsm_x4t(b0, b1v, b2, b3, bd);
                if (p == 0) {
                    mma_fp16(acc[0][0], a[0][s], b0, b1v);
                    mma_fp16(acc[0][1], a[0][s], b2, b3);
                    mma_fp16(acc[1][0], a[1][s], b0, b1v);
                    mma_fp16(acc[1][1], a[1][s], b2, b3);
                } else {
                    mma_fp16(acc2[0][0], a[0][s], b0, b1v);
                    mma_fp16(acc2[0][1], a[0][s], b2, b3);
                    mma_fp16(acc2[1][0], a[1][s], b0, b1v);
                    mma_fp16(acc2[1][1], a[1][s], b2, b3);
                }
            }
    }

    if (tid < 128) sDen[tid] = den;
    __syncthreads();

    float* op = out + ((size_t)hh * NSEQ + m0) * DD;
    #pragma unroll
    for (int mt = 0; mt < 2; ++mt)
        #pragma unroll
        for (int h = 0; h < 2; ++h) {
            const int row = wm*32 + mt*16 + 8*h + g;
            const float invd = 1.f / fmaxf(sDen[row], 1e-6f);
            #pragma unroll
            for (int nt = 0; nt < 4; ++nt) {
                const int d = wn*32 + nt*8 + tq*2;
                const float* av = (nt < 2) ? acc[mt][nt] : acc2[mt][nt-2];
                *reinterpret_cast<float2*>(op + (size_t)row * DD + d) =
                    make_float2(av[h*2] * invd, av[h*2+1] * invd);
            }
        }
}

// ---------------------------------------------------------------------------
extern "C" void kernel_launch(void* const* d_in, const int* in_sizes, int n_in,
                              void* d_out, int out_size)
{
    (void)in_sizes; (void)n_in; (void)out_size;
    const float* q  = (const float*)d_in[0];
    const float* k  = (const float*)d_in[1];
    const float* v  = (const float*)d_in[2];
    const float* W1 = (const float*)d_in[3];
    const float* b1 = (const float*)d_in[4];
    const float* W2 = (const float*)d_in[5];
    const float* b2 = (const float*)d_in[6];
    float* out = (float*)d_out;

    cudaFuncSetAttribute(phi_mma_kernel, cudaFuncAttributeMaxDynamicSharedMemorySize, PHI_SMEM);
    cudaFuncSetAttribute(kv_mma_kernel,  cudaFuncAttributeMaxDynamicSharedMemorySize, KV_SMEM);
    cudaFuncSetAttribute(qkv_mma_kernel, cudaFuncAttributeMaxDynamicSharedMemorySize, QKV_SMEM);

    prep_kernel<<<(6*16384 + 255) / 256, 256>>>(W1, W2);
    vprep_kernel<<<(NTOK*DD/4 + 255) / 256, 256>>>(v);
    phi_mma_kernel<<<4096, 256, PHI_SMEM>>>(q, k, b1, b2);
    kv_mma_kernel<<<dim3(32, 2, KSPLIT), 512, KV_SMEM>>>();
    {
        const int total = BH*FF*DD/4 + BH*FF;
        reduce_kernel<<<(total + 255) / 256, 256>>>();
    }
    qkv_mma_kernel<<<dim3(32, 32), 512, QKV_SMEM>>>(out);
}

// round 12
// speedup vs baseline: 4.5262x; 1.0686x over previous
#include <cuda_runtime.h>
#include <cuda_fp16.h>
#include <math.h>
#include <stdint.h>

// Problem constants
#define BH    32
#define NSEQ  4096
#define DD    128
#define FF    256
#define NTOK  (BH*NSEQ)
#define KSPLIT 4

// Scratch (device globals: allocation-free rule)
__device__ __half g_phi_q[(size_t)NTOK*FF];
__device__ __half g_phi_k[(size_t)NTOK*FF];
__device__ float  g_kvp[(size_t)KSPLIT*BH*FF*DD];
__device__ float  g_ksp[(size_t)KSPLIT*BH*FF];
__device__ __half g_kvh[(size_t)BH*FF*DD];
__device__ float  g_ksum[(size_t)BH*FF];
__device__ uint4  g_Wf[12288];            // W in mma B-fragment order (192KB, L2-resident)
__device__ __half g_vh[(size_t)NTOK*DD];  // fp16-rounded v

// ---------------------------------------------------------------------------
// helpers
// ---------------------------------------------------------------------------
__device__ __forceinline__ uint32_t smem_u32(const void* p) {
    return (uint32_t)__cvta_generic_to_shared(p);
}
__device__ __forceinline__ void cp_async16(uint32_t dst, const void* src) {
    asm volatile("cp.async.cg.shared.global [%0], [%1], 16;"
                 :: "r"(dst), "l"(src) : "memory");
}
#define CP_COMMIT() asm volatile("cp.async.commit_group;" ::: "memory")
#define CP_WAIT0()  asm volatile("cp.async.wait_group 0;" ::: "memory")

__device__ __forceinline__ void ldsm_x4(uint32_t& r0, uint32_t& r1,
                                        uint32_t& r2, uint32_t& r3, uint32_t a) {
    asm volatile("ldmatrix.sync.aligned.m8n8.x4.shared.b16 {%0,%1,%2,%3}, [%4];"
                 : "=r"(r0), "=r"(r1), "=r"(r2), "=r"(r3) : "r"(a));
}
__device__ __forceinline__ void ldsm_x4t(uint32_t& r0, uint32_t& r1,
                                         uint32_t& r2, uint32_t& r3, uint32_t a) {
    asm volatile("ldmatrix.sync.aligned.m8n8.x4.trans.shared.b16 {%0,%1,%2,%3}, [%4];"
                 : "=r"(r0), "=r"(r1), "=r"(r2), "=r"(r3) : "r"(a));
}
__device__ __forceinline__ void mma_fp16(float* d, const uint32_t* a,
                                         uint32_t b0, uint32_t b1) {
    asm volatile("mma.sync.aligned.m16n8k16.row.col.f32.f16.f16.f32 "
                 "{%0,%1,%2,%3}, {%4,%5,%6,%7}, {%8,%9}, {%0,%1,%2,%3};"
                 : "+f"(d[0]), "+f"(d[1]), "+f"(d[2]), "+f"(d[3])
                 : "r"(a[0]), "r"(a[1]), "r"(a[2]), "r"(a[3]),
                   "r"(b0), "r"(b1));
}

// ---------------------------------------------------------------------------
// prep: W1/W2 -> fp16 B-fragment images.
// Index: ((kc*4 + wn)*16 + s*4 + p)*32 + lane. Per lane uint4 = {b0,b1,b2,b3}:
//   b0 = {W[n0][k], W[n0][k+1]}        n0 = wn*64 + p*16 + g,  k = k0 + s*16 + 2*tq
//   b1 = {W[n0][k+8], W[n0][k+9]}
//   b2 = {W[n0+8][k], W[n0+8][k+1]}
//   b3 = {W[n0+8][k+8], W[n0+8][k+9]}
// (mapping derived from the R9-R11-proven ldsm_x4 address scheme)
// ---------------------------------------------------------------------------
__global__ void prep_kernel(const float* __restrict__ W1, const float* __restrict__ W2)
{
    int i = blockIdx.x * blockDim.x + threadIdx.x;
    if (i >= 12288) return;
    int lane = i & 31, p = (i >> 5) & 3, s = (i >> 7) & 3, wn = (i >> 9) & 3, kc = i >> 11;
    int g = lane >> 2, tq = lane & 3;
    int n0 = wn*64 + p*16 + g;
    int kk = s*16 + 2*tq;
    const float* W = (kc < 2) ? W1 : W2;     // [K][256] row-major
    int k0 = (kc < 2) ? kc*64 : (kc - 2)*64;

    __half2 w0 = __floats2half2_rn(W[(size_t)(k0+kk  )*256 + n0],   W[(size_t)(k0+kk+1)*256 + n0]);
    __half2 w1 = __floats2half2_rn(W[(size_t)(k0+kk+8)*256 + n0],   W[(size_t)(k0+kk+9)*256 + n0]);
    __half2 w2 = __floats2half2_rn(W[(size_t)(k0+kk  )*256 + n0+8], W[(size_t)(k0+kk+1)*256 + n0+8]);
    __half2 w3 = __floats2half2_rn(W[(size_t)(k0+kk+8)*256 + n0+8], W[(size_t)(k0+kk+9)*256 + n0+8]);
    uint4 o;
    o.x = *reinterpret_cast<uint32_t*>(&w0);
    o.y = *reinterpret_cast<uint32_t*>(&w1);
    o.z = *reinterpret_cast<uint32_t*>(&w2);
    o.w = *reinterpret_cast<uint32_t*>(&w3);
    g_Wf[i] = o;
}

__global__ void vprep_kernel(const float* __restrict__ v)
{
    int i = blockIdx.x * blockDim.x + threadIdx.x;   // float4 index
    if (i >= NTOK*DD/4) return;
    float4 t = reinterpret_cast<const float4*>(v)[i];
    __half2* o = reinterpret_cast<__half2*>(g_vh + (size_t)i*4);
    o[0] = __floats2half2_rn(t.x, t.y);
    o[1] = __floats2half2_rn(t.z, t.w);
}

// ---------------------------------------------------------------------------
// phi kernel: fp16 mma; B operands LDG.128'd directly from fragment-ordered
// gmem (L2-resident) with 1-step register double buffer. No W smem, no W
// syncs. 64 tokens/CTA, 256 threads (8 warps, 2M x 4N), 2 CTAs/SM.
// SMEM: A @0: X [64][136]h overlaid by H [64][264]h (33792 B);
//       B1 @33792, B2 @34816 (f32 x256); PRT @35840 (f32 x256); INV @36864.
// total 37120 B.
// ---------------------------------------------------------------------------
#define PHI_SMEM 37120

__global__ void __launch_bounds__(256, 2) phi_mma_kernel(
    const float* __restrict__ q, const float* __restrict__ k,
    const float* __restrict__ b1, const float* __restrict__ b2)
{
    extern __shared__ char smc[];
    __half* sAh = reinterpret_cast<__half*>(smc);
    float* sB1  = reinterpret_cast<float*>(smc + 33792);
    float* sB2  = reinterpret_cast<float*>(smc + 34816);
    float* sPrt = reinterpret_cast<float*>(smc + 35840);
    float* sInv = reinterpret_cast<float*>(smc + 36864);
    const uint32_t abase = smem_u32(smc);

    const int tid  = threadIdx.x;
    const int wid  = tid >> 5;
    const int lane = tid & 31;
    const int g    = lane >> 2;
    const int tq   = lane & 3;
    const int wm   = wid & 1;    // 2 M tiles of 32 tokens
    const int wn   = wid >> 1;   // 4 N tiles of 64 cols

    const int bid = blockIdx.x;
    const float* src = (bid < 2048) ? q : k;
    __half*      dst = (bid < 2048) ? g_phi_q : g_phi_k;
    const int tok0 = (bid & 2047) * 64;

    // stage X [64][128] -> fp16 smem, stride 136 halfs
    {
        const float4* s4 = reinterpret_cast<const float4*>(src + (size_t)tok0 * DD);
        #pragma unroll
        for (int l = 0; l < 8; ++l) {
            int id  = tid + l * 256;        // 0..2047 float4
            int row = id >> 5, c4 = id & 31;
            float4 v = s4[row * 32 + c4];
            __half2* p = reinterpret_cast<__half2*>(sAh + row*136 + c4*4);
            p[0] = __floats2half2_rn(v.x, v.y);
            p[1] = __floats2half2_rn(v.z, v.w);
        }
    }
    sB1[tid] = b1[tid];
    sB2[tid] = b2[tid];
    __syncthreads();   // X + biases visible

    float acc[2][8][4];
    #pragma unroll
    for (int mt = 0; mt < 2; ++mt)
        #pragma unroll
        for (int nt = 0; nt < 8; ++nt)
            #pragma unroll
            for (int e = 0; e < 4; ++e) acc[mt][nt][e] = 0.f;

    // ldmatrix lane address components for A
    const int amrow   = wm*32 + (lane & 15);
    const int acoladd = ((lane >> 4) << 3);

    // B fragment base index (per warp): kc*2048 + wn*512 + s*128 + p*32 + lane
    const int wfbase = wn*512 + lane;

    // register double buffer for B fragments
    uint4 bv[2][4];
    #pragma unroll
    for (int p = 0; p < 4; ++p) bv[0][p] = g_Wf[wfbase + p*32];   // step 0

    // ---- main loop: kc 0..1 stage1 (K=128), 2..5 stage2 (K=256) ----
    #pragma unroll
    for (int kc = 0; kc < 6; ++kc) {
        if (kc == 2) {
            // ===== epilogue 1: H = silu(acc + b1) -> fp16 smem stride 264 ====
            __syncthreads();   // all stage-1 A reads done before overlay
            #pragma unroll
            for (int mt = 0; mt < 2; ++mt)
                #pragma unroll
                for (int nt = 0; nt < 8; ++nt) {
                    const int col = wn*64 + nt*8 + tq*2;
                    #pragma unroll
                    for (int h = 0; h < 2; ++h) {
                        const int row = wm*32 + mt*16 + 8*h + g;
                        float x0 = acc[mt][nt][h*2]   + sB1[col];
                        float x1 = acc[mt][nt][h*2+1] + sB1[col+1];
                        float s0 = x0 / (1.f + __expf(-x0));
                        float s1 = x1 / (1.f + __expf(-x1));
                        *reinterpret_cast<__half2*>(sAh + row*264 + col) =
                            __floats2half2_rn(s0, s1);
                        acc[mt][nt][h*2] = 0.f;
                        acc[mt][nt][h*2+1] = 0.f;
                    }
                }
            __syncthreads();   // H visible
        }

        #pragma unroll
        for (int s = 0; s < 4; ++s) {
            const int step = kc*4 + s;
            const int cur  = step & 1;

            // prefetch next step's B fragments (gmem/L2 -> regs)
            if (step < 23) {
                const int ns = step + 1;
                const int nbase = (ns >> 2) * 2048 + ((ns & 3) * 128) + wfbase;
                #pragma unroll
                for (int p = 0; p < 4; ++p)
                    bv[cur ^ 1][p] = g_Wf[nbase + p*32];
            }

            // A fragments via ldmatrix
            const bool s1s = (kc < 2);
            const int astr = s1s ? 136 : 264;
            const int kbase = (s1s ? kc*64 : (kc - 2)*64) + s*16;
            uint32_t a[2][4];
            #pragma unroll
            for (int mt = 0; mt < 2; ++mt) {
                uint32_t ad = abase +
                    (uint32_t)(((amrow + mt*16) * astr) + kbase + acoladd) * 2u;
                ldsm_x4(a[mt][0], a[mt][1], a[mt][2], a[mt][3], ad);
            }

            #pragma unroll
            for (int p = 0; p < 4; ++p) {
                const uint4 b = bv[cur][p];
                mma_fp16(acc[0][2*p],   a[0], b.x, b.y);
                mma_fp16(acc[0][2*p+1], a[0], b.z, b.w);
                mma_fp16(acc[1][2*p],   a[1], b.x, b.y);
                mma_fp16(acc[1][2*p+1], a[1], b.z, b.w);
            }
        }
    }

    // ===== epilogue 2: p = elu(acc + b2)+1, row L2 norm, write fp16 =====
    float ss[2][2] = {};
    #pragma unroll
    for (int mt = 0; mt < 2; ++mt)
        #pragma unroll
        for (int nt = 0; nt < 8; ++nt) {
            const int col = wn*64 + nt*8 + tq*2;
            #pragma unroll
            for (int h = 0; h < 2; ++h)
                #pragma unroll
                for (int pr = 0; pr < 2; ++pr) {
                    float x = acc[mt][nt][h*2+pr] + sB2[col+pr];
                    float p = (x > 0.f) ? (x + 1.f) : __expf(x);
                    acc[mt][nt][h*2+pr] = p;
                    ss[mt][h] = fmaf(p, p, ss[mt][h]);
                }
        }
    #pragma unroll
    for (int m = 1; m <= 2; m <<= 1)
        #pragma unroll
        for (int mt = 0; mt < 2; ++mt)
            #pragma unroll
            for (int h = 0; h < 2; ++h)
                ss[mt][h] += __shfl_xor_sync(0xffffffffu, ss[mt][h], m);
    if (tq == 0) {
        #pragma unroll
        for (int mt = 0; mt < 2; ++mt)
            #pragma unroll
            for (int h = 0; h < 2; ++h)
                sPrt[wn*64 + wm*32 + mt*16 + 8*h + g] = ss[mt][h];
    }
    __syncthreads();
    if (tid < 64)
        sInv[tid] = 1.f / (sqrtf(sPrt[tid] + sPrt[64+tid] +
                                 sPrt[128+tid] + sPrt[192+tid]) + 1e-6f);
    __syncthreads();

    #pragma unroll
    for (int mt = 0; mt < 2; ++mt)
        #pragma unroll
        for (int h = 0; h < 2; ++h) {
            const int row = wm*32 + mt*16 + 8*h + g;
            const float inv = sInv[row];
            __half* dr = dst + (size_t)(tok0 + row) * FF;
            #pragma unroll
            for (int nt = 0; nt < 8; ++nt) {
                const int col = wn*64 + nt*8 + tq*2;
                *reinterpret_cast<__half2*>(dr + col) =
                    __floats2half2_rn(acc[mt][nt][h*2] * inv,
                                      acc[mt][nt][h*2+1] * inv);
            }
        }
}

// ---------------------------------------------------------------------------
// kv kernel: grid (32, 2, KSPLIT=4), 512 threads, 2 CTAs/SM.
// (unchanged from R11 — 44.9us)
// ---------------------------------------------------------------------------
#define KV_SMEM 34816

__global__ void __launch_bounds__(512, 2) kv_mma_kernel()
{
    extern __shared__ char kvc[];
    const uint32_t sbase = smem_u32(kvc);

    const int hh = blockIdx.x;
    const int f0 = blockIdx.y * 128;
    const int ks = blockIdx.z;
    const int tid  = threadIdx.x;
    const int lane = tid & 31;
    const int wid  = tid >> 5;
    const int g  = lane >> 2;
    const int tq = lane & 3;
    const int wm = wid & 3;
    const int wn = wid >> 2;

    const __half* pbase = g_phi_k + ((size_t)hh * NSEQ + (size_t)ks * 1024) * FF + f0;
    const __half* vbase = g_vh    + ((size_t)hh * NSEQ + (size_t)ks * 1024) * DD;

    auto issue = [&](int b, int slot) {
        uint32_t base = sbase + (uint32_t)slot * 17408u;
        #pragma unroll
        for (int l = 0; l < 2; ++l) {
            int u = tid + l * 512;
            int row = (u >> 4) & 31, seg = u & 15;
            if (u < 512)
                cp_async16(base + row*272 + seg*16,
                           pbase + (size_t)(b*32 + row)*FF + seg*8);
            else
                cp_async16(base + 8704u + row*272 + seg*16,
                           vbase + (size_t)(b*32 + row)*DD + seg*8);
        }
        CP_COMMIT();
    };

    issue(0, 0);

    float acc[2][4][4];
    #pragma unroll
    for (int mt = 0; mt < 2; ++mt)
        #pragma unroll
        for (int nt = 0; nt < 4; ++nt)
            #pragma unroll
            for (int e = 0; e < 4; ++e) acc[mt][nt][e] = 0.f;
    float ksacc = 0.f;

    const int aseq = ((lane >> 4) << 3) + (lane & 7);
    const int afc  = wm*32 + ((lane >> 3) & 1) * 8;
    const int bseq = ((lane >> 3) & 1) * 8 + (lane & 7);
    const int bdc  = wn*32 + ((lane >> 4) << 3);

    for (int b = 0; b < 32; ++b) {
        CP_WAIT0();
        __syncthreads();
        if (b < 31) issue(b + 1, (b + 1) & 1);

        const uint32_t pb = sbase + (uint32_t)(b & 1) * 17408u;
        const uint32_t vb = pb + 8704u;
        const __half* sP = reinterpret_cast<const __half*>(kvc + (b & 1) * 17408);

        if (tid < 128) {
            #pragma unroll
            for (int r = 0; r < 32; ++r)
                ksacc += __half2float(sP[r*136 + tid]);
        }

        uint32_t a[2][2][4];
        #pragma unroll
        for (int s = 0; s < 2; ++s)
            #pragma unroll
            for (int mt = 0; mt < 2; ++mt) {
                uint32_t ad = pb + (uint32_t)(((s*16 + aseq) * 136) + afc + mt*16) * 2u;
                ldsm_x4t(a[mt][s][0], a[mt][s][1], a[mt][s][2], a[mt][s][3], ad);
            }
        #pragma unroll
        for (int s = 0; s < 2; ++s)
            #pragma unroll
            for (int p = 0; p < 2; ++p) {
                uint32_t b0, b1v, b2, b3;
                uint32_t bd = vb + (uint32_t)(((s*16 + bseq) * 136) + bdc + p*16) * 2u;
                ldsm_x4t(b0, b1v, b2, b3, bd);
                mma_fp16(acc[0][2*p],   a[0][s], b0, b1v);
                mma_fp16(acc[0][2*p+1], a[0][s], b2, b3);
                mma_fp16(acc[1][2*p],   a[1][s], b0, b1v);
                mma_fp16(acc[1][2*p+1], a[1][s], b2, b3);
            }
    }

    float* outp = g_kvp + ((size_t)ks * BH + hh) * FF * DD;
    #pragma unroll
    for (int mt = 0; mt < 2; ++mt)
        #pragma unroll
        for (int h = 0; h < 2; ++h) {
            const int f = f0 + wm*32 + mt*16 + 8*h + g;
            #pragma unroll
            for (int nt = 0; nt < 4; ++nt) {
                const int d = wn*32 + nt*8 + tq*2;
                *reinterpret_cast<float2*>(outp + (size_t)f * DD + d) =
                    make_float2(acc[mt][nt][h*2], acc[mt][nt][h*2+1]);
            }
        }
    if (tid < 128)
        g_ksp[((size_t)ks * BH + hh) * FF + f0 + tid] = ksacc;
}

// ---------------------------------------------------------------------------
// reduce kernel: fold KSPLIT partials (float4), write g_kvh fp16 + g_ksum.
// ---------------------------------------------------------------------------
__global__ void reduce_kernel()
{
    const int NKV4 = BH * FF * DD / 4;
    const int NKS  = BH * FF;
    int i = blockIdx.x * blockDim.x + threadIdx.x;
    if (i < NKV4) {
        float4 s = make_float4(0.f, 0.f, 0.f, 0.f);
        #pragma unroll
        for (int p = 0; p < KSPLIT; ++p) {
            float4 t = reinterpret_cast<const float4*>(g_kvp)[(size_t)p * NKV4 + i];
            s.x += t.x; s.y += t.y; s.z += t.z; s.w += t.w;
        }
        __half2* o = reinterpret_cast<__half2*>(g_kvh + (size_t)i*4);
        o[0] = __floats2half2_rn(s.x, s.y);
        o[1] = __floats2half2_rn(s.z, s.w);
    } else {
        int j = i - NKV4;
        if (j < NKS) {
            float s = 0.f;
            #pragma unroll
            for (int p = 0; p < KSPLIT; ++p) s += g_ksp[(size_t)p * NKS + j];
            g_ksum[j] = s;
        }
    }
}

// ---------------------------------------------------------------------------
// qkv kernel: grid (32, 32), 512 threads. (unchanged from R11 — ~55us)
// ---------------------------------------------------------------------------
#define QKV_SMEM 37888

__global__ void __launch_bounds__(512) qkv_mma_kernel(float* __restrict__ out)
{
    extern __shared__ char qc[];
    __shared__ float sKs[2][32];
    __shared__ float sDen[128];
    const uint32_t sbase = smem_u32(qc);

    const int hh = blockIdx.x;
    const int m0 = blockIdx.y * 128;
    const int tid  = threadIdx.x;
    const int lane = tid & 31;
    const int wid  = tid >> 5;
    const int g  = lane >> 2;
    const int tq = lane & 3;
    const int wm = wid & 3;
    const int wn = wid >> 2;

    const __half* agb = g_phi_q + ((size_t)hh * NSEQ + m0) * FF;
    const __half* bgb = g_kvh + (size_t)hh * FF * DD;

    auto issue = [&](int kc, int slot) {
        uint32_t base = sbase + (uint32_t)slot * 18944u;
        #pragma unroll
        for (int l = 0; l < 2; ++l) {
            int u = tid + l * 512;
            if (u < 512) {
                int row = u >> 2, seg = u & 3;
                cp_async16(base + row*80 + seg*16,
                           agb + (size_t)row*FF + kc*32 + seg*8);
            } else {
                int w = u - 512;
                int row = w >> 4, seg = w & 15;
                cp_async16(base + 10240u + row*272 + seg*16,
                           bgb + (size_t)(kc*32 + row)*DD + seg*8);
            }
        }
        CP_COMMIT();
    };

    issue(0, 0);
    if (tid < 32) sKs[0][tid] = g_ksum[(size_t)hh * FF + tid];

    float acc[2][2][4];
    float acc2[2][2][4];
    #pragma unroll
    for (int mt = 0; mt < 2; ++mt)
        #pragma unroll
        for (int nt = 0; nt < 2; ++nt)
            #pragma unroll
            for (int e = 0; e < 4; ++e) { acc[mt][nt][e] = 0.f; acc2[mt][nt][e] = 0.f; }
    float den = 0.f;

    const int amrow   = wm*32 + (lane & 15);
    const int acoladd = ((lane >> 4) << 3);
    const int bseq = ((lane >> 3) & 1) * 8 + (lane & 7);
    const int bdc  = wn*32 + ((lane >> 4) << 3);

    for (int kc = 0; kc < 8; ++kc) {
        CP_WAIT0();
        __syncthreads();
        if (kc < 7) {
            issue(kc + 1, (kc + 1) & 1);
            if (tid < 32)
                sKs[(kc+1) & 1][tid] = g_ksum[(size_t)hh * FF + (kc+1)*32 + tid];
        }

        const uint32_t ab = sbase + (uint32_t)(kc & 1) * 18944u;
        const uint32_t bb = ab + 10240u;
        const __half* sAhp = reinterpret_cast<const __half*>(qc + (kc & 1) * 18944);
        const float* ks = sKs[kc & 1];

        if (tid < 128) {
            #pragma unroll
            for (int kk = 0; kk < 32; ++kk)
                den = fmaf(__half2float(sAhp[tid*40 + kk]), ks[kk], den);
        }

        uint32_t a[2][2][4];
        #pragma unroll
        for (int s = 0; s < 2; ++s)
            #pragma unroll
            for (int mt = 0; mt < 2; ++mt) {
                uint32_t ad = ab + (uint32_t)(((amrow + mt*16) * 40) + s*16 + acoladd) * 2u;
                ldsm_x4(a[mt][s][0], a[mt][s][1], a[mt][s][2], a[mt][s][3], ad);
            }
        #pragma unroll
        for (int s = 0; s < 2; ++s)
            #pragma unroll
            for (int p = 0; p < 2; ++p) {
                uint32_t b0, b1v, b2, b3;
                uint32_t bd = bb + (uint32_t)(((s*16 + bseq) * 136) + bdc + p*16) * 2u;
                ldsm_x4t(b0, b1v, b2, b3, bd);
                if (p == 0) {
                    mma_fp16(acc[0][0], a[0][s], b0, b1v);
                    mma_fp16(acc[0][1], a[0][s], b2, b3);
                    mma_fp16(acc[1][0], a[1][s], b0, b1v);
                    mma_fp16(acc[1][1], a[1][s], b2, b3);
                } else {
                    mma_fp16(acc2[0][0], a[0][s], b0, b1v);
                    mma_fp16(acc2[0][1], a[0][s], b2, b3);
                    mma_fp16(acc2[1][0], a[1][s], b0, b1v);
                    mma_fp16(acc2[1][1], a[1][s], b2, b3);
                }
            }
    }

    if (tid < 128) sDen[tid] = den;
    __syncthreads();

    float* op = out + ((size_t)hh * NSEQ + m0) * DD;
    #pragma unroll
    for (int mt = 0; mt < 2; ++mt)
        #pragma unroll
        for (int h = 0; h < 2; ++h) {
            const int row = wm*32 + mt*16 + 8*h + g;
            const float invd = 1.f / fmaxf(sDen[row], 1e-6f);
            #pragma unroll
            for (int nt = 0; nt < 4; ++nt) {
                const int d = wn*32 + nt*8 + tq*2;
                const float* av = (nt < 2) ? acc[mt][nt] : acc2[mt][nt-2];
                *reinterpret_cast<float2*>(op + (size_t)row * DD + d) =
                    make_float2(av[h*2] * invd, av[h*2+1] * invd);
            }
        }
}

// ---------------------------------------------------------------------------
extern "C" void kernel_launch(void* const* d_in, const int* in_sizes, int n_in,
                              void* d_out, int out_size)
{
    (void)in_sizes; (void)n_in; (void)out_size;
    const float* q  = (const float*)d_in[0];
    const float* k  = (const float*)d_in[1];
    const float* v  = (const float*)d_in[2];
    const float* W1 = (const float*)d_in[3];
    const float* b1 = (const float*)d_in[4];
    const float* W2 = (const float*)d_in[5];
    const float* b2 = (const float*)d_in[6];
    float* out = (float*)d_out;

    cudaFuncSetAttribute(phi_mma_kernel, cudaFuncAttributeMaxDynamicSharedMemorySize, PHI_SMEM);
    cudaFuncSetAttribute(kv_mma_kernel,  cudaFuncAttributeMaxDynamicSharedMemorySize, KV_SMEM);
    cudaFuncSetAttribute(qkv_mma_kernel, cudaFuncAttributeMaxDynamicSharedMemorySize, QKV_SMEM);

    prep_kernel<<<48, 256>>>(W1, W2);
    vprep_kernel<<<(NTOK*DD/4 + 255) / 256, 256>>>(v);
    phi_mma_kernel<<<4096, 256, PHI_SMEM>>>(q, k, b1, b2);
    kv_mma_kernel<<<dim3(32, 2, KSPLIT), 512, KV_SMEM>>>();
    {
        const int total = BH*FF*DD/4 + BH*FF;
        reduce_kernel<<<(total + 255) / 256, 256>>>();
    }
    qkv_mma_kernel<<<dim3(32, 32), 512, QKV_SMEM>>>(out);
}

// round 13
// speedup vs baseline: 4.8534x; 1.0723x over previous
#include <cuda_runtime.h>
#include <cuda_fp16.h>
#include <math.h>
#include <stdint.h>

// Problem constants
#define BH    32
#define NSEQ  4096
#define DD    128
#define FF    256
#define NTOK  (BH*NSEQ)
#define KSPLIT 4

// Scratch (device globals: allocation-free rule)
__device__ __half g_phi_q[(size_t)NTOK*FF];
__device__ __half g_phi_k[(size_t)NTOK*FF];
__device__ float  g_kvp[(size_t)KSPLIT*BH*FF*DD];
__device__ float  g_ksp[(size_t)KSPLIT*BH*FF];
__device__ __half g_kvh[(size_t)BH*FF*DD];
__device__ float  g_ksum[(size_t)BH*FF];
__device__ uint4  g_Wf[12288];            // W in mma B-fragment order (192KB, L2-resident)

// ---------------------------------------------------------------------------
// helpers
// ---------------------------------------------------------------------------
__device__ __forceinline__ uint32_t smem_u32(const void* p) {
    return (uint32_t)__cvta_generic_to_shared(p);
}
__device__ __forceinline__ void cp_async16(uint32_t dst, const void* src) {
    asm volatile("cp.async.cg.shared.global [%0], [%1], 16;"
                 :: "r"(dst), "l"(src) : "memory");
}
#define CP_COMMIT() asm volatile("cp.async.commit_group;" ::: "memory")
#define CP_WAIT0()  asm volatile("cp.async.wait_group 0;" ::: "memory")

__device__ __forceinline__ void ldsm_x4(uint32_t& r0, uint32_t& r1,
                                        uint32_t& r2, uint32_t& r3, uint32_t a) {
    asm volatile("ldmatrix.sync.aligned.m8n8.x4.shared.b16 {%0,%1,%2,%3}, [%4];"
                 : "=r"(r0), "=r"(r1), "=r"(r2), "=r"(r3) : "r"(a));
}
__device__ __forceinline__ void ldsm_x4t(uint32_t& r0, uint32_t& r1,
                                         uint32_t& r2, uint32_t& r3, uint32_t a) {
    asm volatile("ldmatrix.sync.aligned.m8n8.x4.trans.shared.b16 {%0,%1,%2,%3}, [%4];"
                 : "=r"(r0), "=r"(r1), "=r"(r2), "=r"(r3) : "r"(a));
}
__device__ __forceinline__ void mma_fp16(float* d, const uint32_t* a,
                                         uint32_t b0, uint32_t b1) {
    asm volatile("mma.sync.aligned.m16n8k16.row.col.f32.f16.f16.f32 "
                 "{%0,%1,%2,%3}, {%4,%5,%6,%7}, {%8,%9}, {%0,%1,%2,%3};"
                 : "+f"(d[0]), "+f"(d[1]), "+f"(d[2]), "+f"(d[3])
                 : "r"(a[0]), "r"(a[1]), "r"(a[2]), "r"(a[3]),
                   "r"(b0), "r"(b1));
}

// ---------------------------------------------------------------------------
// prep: W1/W2 -> fp16 B-fragment images (R12-proven mapping).
// ---------------------------------------------------------------------------
__global__ void prep_kernel(const float* __restrict__ W1, const float* __restrict__ W2)
{
    int i = blockIdx.x * blockDim.x + threadIdx.x;
    if (i >= 12288) return;
    int lane = i & 31, p = (i >> 5) & 3, s = (i >> 7) & 3, wn = (i >> 9) & 3, kc = i >> 11;
    int g = lane >> 2, tq = lane & 3;
    int n0 = wn*64 + p*16 + g;
    int kk = s*16 + 2*tq;
    const float* W = (kc < 2) ? W1 : W2;
    int k0 = (kc < 2) ? kc*64 : (kc - 2)*64;

    __half2 w0 = __floats2half2_rn(W[(size_t)(k0+kk  )*256 + n0],   W[(size_t)(k0+kk+1)*256 + n0]);
    __half2 w1 = __floats2half2_rn(W[(size_t)(k0+kk+8)*256 + n0],   W[(size_t)(k0+kk+9)*256 + n0]);
    __half2 w2 = __floats2half2_rn(W[(size_t)(k0+kk  )*256 + n0+8], W[(size_t)(k0+kk+1)*256 + n0+8]);
    __half2 w3 = __floats2half2_rn(W[(size_t)(k0+kk+8)*256 + n0+8], W[(size_t)(k0+kk+9)*256 + n0+8]);
    uint4 o;
    o.x = *reinterpret_cast<uint32_t*>(&w0);
    o.y = *reinterpret_cast<uint32_t*>(&w1);
    o.z = *reinterpret_cast<uint32_t*>(&w2);
    o.w = *reinterpret_cast<uint32_t*>(&w3);
    g_Wf[i] = o;
}

// ---------------------------------------------------------------------------
// phi kernel (unchanged from R12 — ~248us, at platform mma rate).
// ---------------------------------------------------------------------------
#define PHI_SMEM 37120

__global__ void __launch_bounds__(256, 2) phi_mma_kernel(
    const float* __restrict__ q, const float* __restrict__ k,
    const float* __restrict__ b1, const float* __restrict__ b2)
{
    extern __shared__ char smc[];
    __half* sAh = reinterpret_cast<__half*>(smc);
    float* sB1  = reinterpret_cast<float*>(smc + 33792);
    float* sB2  = reinterpret_cast<float*>(smc + 34816);
    float* sPrt = reinterpret_cast<float*>(smc + 35840);
    float* sInv = reinterpret_cast<float*>(smc + 36864);
    const uint32_t abase = smem_u32(smc);

    const int tid  = threadIdx.x;
    const int wid  = tid >> 5;
    const int lane = tid & 31;
    const int g    = lane >> 2;
    const int tq   = lane & 3;
    const int wm   = wid & 1;
    const int wn   = wid >> 1;

    const int bid = blockIdx.x;
    const float* src = (bid < 2048) ? q : k;
    __half*      dst = (bid < 2048) ? g_phi_q : g_phi_k;
    const int tok0 = (bid & 2047) * 64;

    {
        const float4* s4 = reinterpret_cast<const float4*>(src + (size_t)tok0 * DD);
        #pragma unroll
        for (int l = 0; l < 8; ++l) {
            int id  = tid + l * 256;
            int row = id >> 5, c4 = id & 31;
            float4 v = s4[row * 32 + c4];
            __half2* p = reinterpret_cast<__half2*>(sAh + row*136 + c4*4);
            p[0] = __floats2half2_rn(v.x, v.y);
            p[1] = __floats2half2_rn(v.z, v.w);
        }
    }
    sB1[tid] = b1[tid];
    sB2[tid] = b2[tid];
    __syncthreads();

    float acc[2][8][4];
    #pragma unroll
    for (int mt = 0; mt < 2; ++mt)
        #pragma unroll
        for (int nt = 0; nt < 8; ++nt)
            #pragma unroll
            for (int e = 0; e < 4; ++e) acc[mt][nt][e] = 0.f;

    const int amrow   = wm*32 + (lane & 15);
    const int acoladd = ((lane >> 4) << 3);
    const int wfbase = wn*512 + lane;

    uint4 bv[2][4];
    #pragma unroll
    for (int p = 0; p < 4; ++p) bv[0][p] = g_Wf[wfbase + p*32];

    #pragma unroll
    for (int kc = 0; kc < 6; ++kc) {
        if (kc == 2) {
            __syncthreads();
            #pragma unroll
            for (int mt = 0; mt < 2; ++mt)
                #pragma unroll
                for (int nt = 0; nt < 8; ++nt) {
                    const int col = wn*64 + nt*8 + tq*2;
                    #pragma unroll
                    for (int h = 0; h < 2; ++h) {
                        const int row = wm*32 + mt*16 + 8*h + g;
                        float x0 = acc[mt][nt][h*2]   + sB1[col];
                        float x1 = acc[mt][nt][h*2+1] + sB1[col+1];
                        float s0 = x0 / (1.f + __expf(-x0));
                        float s1 = x1 / (1.f + __expf(-x1));
                        *reinterpret_cast<__half2*>(sAh + row*264 + col) =
                            __floats2half2_rn(s0, s1);
                        acc[mt][nt][h*2] = 0.f;
                        acc[mt][nt][h*2+1] = 0.f;
                    }
                }
            __syncthreads();
        }

        #pragma unroll
        for (int s = 0; s < 4; ++s) {
            const int step = kc*4 + s;
            const int cur  = step & 1;

            if (step < 23) {
                const int ns = step + 1;
                const int nbase = (ns >> 2) * 2048 + ((ns & 3) * 128) + wfbase;
                #pragma unroll
                for (int p = 0; p < 4; ++p)
                    bv[cur ^ 1][p] = g_Wf[nbase + p*32];
            }

            const bool s1s = (kc < 2);
            const int astr = s1s ? 136 : 264;
            const int kbase = (s1s ? kc*64 : (kc - 2)*64) + s*16;
            uint32_t a[2][4];
            #pragma unroll
            for (int mt = 0; mt < 2; ++mt) {
                uint32_t ad = abase +
                    (uint32_t)(((amrow + mt*16) * astr) + kbase + acoladd) * 2u;
                ldsm_x4(a[mt][0], a[mt][1], a[mt][2], a[mt][3], ad);
            }

            #pragma unroll
            for (int p = 0; p < 4; ++p) {
                const uint4 b = bv[cur][p];
                mma_fp16(acc[0][2*p],   a[0], b.x, b.y);
                mma_fp16(acc[0][2*p+1], a[0], b.z, b.w);
                mma_fp16(acc[1][2*p],   a[1], b.x, b.y);
                mma_fp16(acc[1][2*p+1], a[1], b.z, b.w);
            }
        }
    }

    float ss[2][2] = {};
    #pragma unroll
    for (int mt = 0; mt < 2; ++mt)
        #pragma unroll
        for (int nt = 0; nt < 8; ++nt) {
            const int col = wn*64 + nt*8 + tq*2;
            #pragma unroll
            for (int h = 0; h < 2; ++h)
                #pragma unroll
                for (int pr = 0; pr < 2; ++pr) {
                    float x = acc[mt][nt][h*2+pr] + sB2[col+pr];
                    float p = (x > 0.f) ? (x + 1.f) : __expf(x);
                    acc[mt][nt][h*2+pr] = p;
                    ss[mt][h] = fmaf(p, p, ss[mt][h]);
                }
        }
    #pragma unroll
    for (int m = 1; m <= 2; m <<= 1)
        #pragma unroll
        for (int mt = 0; mt < 2; ++mt)
            #pragma unroll
            for (int h = 0; h < 2; ++h)
                ss[mt][h] += __shfl_xor_sync(0xffffffffu, ss[mt][h], m);
    if (tq == 0) {
        #pragma unroll
        for (int mt = 0; mt < 2; ++mt)
            #pragma unroll
            for (int h = 0; h < 2; ++h)
                sPrt[wn*64 + wm*32 + mt*16 + 8*h + g] = ss[mt][h];
    }
    __syncthreads();
    if (tid < 64)
        sInv[tid] = 1.f / (sqrtf(sPrt[tid] + sPrt[64+tid] +
                                 sPrt[128+tid] + sPrt[192+tid]) + 1e-6f);
    __syncthreads();

    #pragma unroll
    for (int mt = 0; mt < 2; ++mt)
        #pragma unroll
        for (int h = 0; h < 2; ++h) {
            const int row = wm*32 + mt*16 + 8*h + g;
            const float inv = sInv[row];
            __half* dr = dst + (size_t)(tok0 + row) * FF;
            #pragma unroll
            for (int nt = 0; nt < 8; ++nt) {
                const int col = wn*64 + nt*8 + tq*2;
                *reinterpret_cast<__half2*>(dr + col) =
                    __floats2half2_rn(acc[mt][nt][h*2] * inv,
                                      acc[mt][nt][h*2+1] * inv);
            }
        }
}

// ---------------------------------------------------------------------------
// kv kernel: v converted fp32->fp16 INLINE during staging (vprep eliminated).
// grid (32, 2, KSPLIT=4), 512 threads, 2 CTAs/SM.
// P tile via cp.async; V tile via LDG.128 x2 -> cvt -> STS.128, register
// double-buffered so the LDG rides under the previous tile's compute.
// SMEM: 2 x (P [32][136]h + V [32][136]h) = 34816 B.
// ---------------------------------------------------------------------------
#define KV_SMEM 34816

__global__ void __launch_bounds__(512, 2) kv_mma_kernel(const float* __restrict__ v)
{
    extern __shared__ char kvc[];
    const uint32_t sbase = smem_u32(kvc);

    const int hh = blockIdx.x;
    const int f0 = blockIdx.y * 128;
    const int ks = blockIdx.z;
    const int tid  = threadIdx.x;
    const int lane = tid & 31;
    const int wid  = tid >> 5;
    const int g  = lane >> 2;
    const int tq = lane & 3;
    const int wm = wid & 3;
    const int wn = wid >> 2;

    const __half* pbase = g_phi_k + ((size_t)hh * NSEQ + (size_t)ks * 1024) * FF + f0;
    const float*  vbase = v       + ((size_t)hh * NSEQ + (size_t)ks * 1024) * DD;

    const int vrow = tid >> 4;          // 0..31
    const int vseg = tid & 15;          // 0..15 (8 halves / 32B fp32 each)
    const uint32_t vsts_off = (uint32_t)(vrow*272 + vseg*16);

    // P tile cp.async (1 op/thread: 32 rows x 16 segs)
    auto issueP = [&](int b, int slot) {
        uint32_t base = sbase + (uint32_t)slot * 17408u;
        cp_async16(base + vrow*272 + vseg*16,
                   pbase + (size_t)(b*32 + vrow)*FF + vseg*8);
        CP_COMMIT();
    };
    // V tile gmem fp32 load (2 x LDG.128 into regs)
    auto ldgV = [&](int b, float4& v0, float4& v1) {
        const float4* p = reinterpret_cast<const float4*>(
            vbase + (size_t)(b*32 + vrow)*DD + vseg*8);
        v0 = p[0]; v1 = p[1];
    };

    float4 va0, va1;
    ldgV(0, va0, va1);
    issueP(0, 0);

    float acc[2][4][4];
    #pragma unroll
    for (int mt = 0; mt < 2; ++mt)
        #pragma unroll
        for (int nt = 0; nt < 4; ++nt)
            #pragma unroll
            for (int e = 0; e < 4; ++e) acc[mt][nt][e] = 0.f;
    float ksacc = 0.f;

    const int aseq = ((lane >> 4) << 3) + (lane & 7);
    const int afc  = wm*32 + ((lane >> 3) & 1) * 8;
    const int bseq = ((lane >> 3) & 1) * 8 + (lane & 7);
    const int bdc  = wn*32 + ((lane >> 4) << 3);

    for (int b = 0; b < 32; ++b) {
        // convert + store V[b] into slot b&1 (slot's readers finished at b-1's sync)
        {
            __half2 h0 = __floats2half2_rn(va0.x, va0.y);
            __half2 h1 = __floats2half2_rn(va0.z, va0.w);
            __half2 h2 = __floats2half2_rn(va1.x, va1.y);
            __half2 h3 = __floats2half2_rn(va1.z, va1.w);
            uint32_t addr = sbase + (uint32_t)(b & 1)*17408u + 8704u + vsts_off;
            asm volatile("st.shared.v4.b32 [%0], {%1,%2,%3,%4};" :: "r"(addr),
                "r"(*reinterpret_cast<uint32_t*>(&h0)),
                "r"(*reinterpret_cast<uint32_t*>(&h1)),
                "r"(*reinterpret_cast<uint32_t*>(&h2)),
                "r"(*reinterpret_cast<uint32_t*>(&h3)) : "memory");
        }
        CP_WAIT0();
        __syncthreads();
        if (b < 31) { issueP(b + 1, (b + 1) & 1); ldgV(b + 1, va0, va1); }

        const uint32_t pb = sbase + (uint32_t)(b & 1) * 17408u;
        const uint32_t vb = pb + 8704u;
        const __half* sP = reinterpret_cast<const __half*>(kvc + (b & 1) * 17408);

        if (tid < 128) {
            #pragma unroll
            for (int r = 0; r < 32; ++r)
                ksacc += __half2float(sP[r*136 + tid]);
        }

        uint32_t a[2][2][4];
        #pragma unroll
        for (int s = 0; s < 2; ++s)
            #pragma unroll
            for (int mt = 0; mt < 2; ++mt) {
                uint32_t ad = pb + (uint32_t)(((s*16 + aseq) * 136) + afc + mt*16) * 2u;
                ldsm_x4t(a[mt][s][0], a[mt][s][1], a[mt][s][2], a[mt][s][3], ad);
            }
        #pragma unroll
        for (int s = 0; s < 2; ++s)
            #pragma unroll
            for (int p = 0; p < 2; ++p) {
                uint32_t b0, b1v, b2, b3;
                uint32_t bd = vb + (uint32_t)(((s*16 + bseq) * 136) + bdc + p*16) * 2u;
                ldsm_x4t(b0, b1v, b2, b3, bd);
                mma_fp16(acc[0][2*p],   a[0][s], b0, b1v);
                mma_fp16(acc[0][2*p+1], a[0][s], b2, b3);
                mma_fp16(acc[1][2*p],   a[1][s], b0, b1v);
                mma_fp16(acc[1][2*p+1], a[1][s], b2, b3);
            }
    }

    float* outp = g_kvp + ((size_t)ks * BH + hh) * FF * DD;
    #pragma unroll
    for (int mt = 0; mt < 2; ++mt)
        #pragma unroll
        for (int h = 0; h < 2; ++h) {
            const int f = f0 + wm*32 + mt*16 + 8*h + g;
            #pragma unroll
            for (int nt = 0; nt < 4; ++nt) {
                const int d = wn*32 + nt*8 + tq*2;
                *reinterpret_cast<float2*>(outp + (size_t)f * DD + d) =
                    make_float2(acc[mt][nt][h*2], acc[mt][nt][h*2+1]);
            }
        }
    if (tid < 128)
        g_ksp[((size_t)ks * BH + hh) * FF + f0 + tid] = ksacc;
}

// ---------------------------------------------------------------------------
// reduce kernel (unchanged)
// ---------------------------------------------------------------------------
__global__ void reduce_kernel()
{
    const int NKV4 = BH * FF * DD / 4;
    const int NKS  = BH * FF;
    int i = blockIdx.x * blockDim.x + threadIdx.x;
    if (i < NKV4) {
        float4 s = make_float4(0.f, 0.f, 0.f, 0.f);
        #pragma unroll
        for (int p = 0; p < KSPLIT; ++p) {
            float4 t = reinterpret_cast<const float4*>(g_kvp)[(size_t)p * NKV4 + i];
            s.x += t.x; s.y += t.y; s.z += t.z; s.w += t.w;
        }
        __half2* o = reinterpret_cast<__half2*>(g_kvh + (size_t)i*4);
        o[0] = __floats2half2_rn(s.x, s.y);
        o[1] = __floats2half2_rn(s.z, s.w);
    } else {
        int j = i - NKV4;
        if (j < NKS) {
            float s = 0.f;
            #pragma unroll
            for (int p = 0; p < KSPLIT; ++p) s += g_ksp[(size_t)p * NKS + j];
            g_ksum[j] = s;
        }
    }
}

// ---------------------------------------------------------------------------
// qkv kernel: retiled to M0=256 tokens/CTA, warp tile 32x64 (8M x 2N warps).
// grid (32, 16), 512 threads. cp.async S=2. Per kc: 32 mma, 12 ldsm per warp.
// SMEM: 2 x (A [256][40]h=20480 + B [32][136]h=8704) = 58368 B dynamic.
// ---------------------------------------------------------------------------
#define QSLOT 29184u
#define QKV_SMEM 58368

__global__ void __launch_bounds__(512) qkv_mma_kernel(float* __restrict__ out)
{
    extern __shared__ char qc[];
    __shared__ float sKs[2][32];
    __shared__ float sDen[256];
    const uint32_t sbase = smem_u32(qc);

    const int hh = blockIdx.x;
    const int m0 = blockIdx.y * 256;
    const int tid  = threadIdx.x;
    const int lane = tid & 31;
    const int wid  = tid >> 5;
    const int g  = lane >> 2;
    const int tq = lane & 3;
    const int wm = wid & 7;      // 8 M tiles of 32 rows
    const int wn = wid >> 3;     // 2 N tiles of 64 cols

    const __half* agb = g_phi_q + ((size_t)hh * NSEQ + m0) * FF;
    const __half* bgb = g_kvh + (size_t)hh * FF * DD;

    auto issue = [&](int kc, int slot) {
        uint32_t base = sbase + (uint32_t)slot * QSLOT;
        // A: 256 rows x 4 segs = 1024 ops (2/thread)
        #pragma unroll
        for (int l = 0; l < 2; ++l) {
            int u = tid + l * 512;
            int row = u >> 2, seg = u & 3;
            cp_async16(base + row*80 + seg*16,
                       agb + (size_t)row*FF + kc*32 + seg*8);
        }
        // B: 32 rows x 16 segs = 512 ops (1/thread)
        {
            int row = tid >> 4, seg = tid & 15;
            cp_async16(base + 20480u + row*272 + seg*16,
                       bgb + (size_t)(kc*32 + row)*DD + seg*8);
        }
        CP_COMMIT();
    };

    issue(0, 0);
    if (tid < 32) sKs[0][tid] = g_ksum[(size_t)hh * FF + tid];

    float acc[2][8][4];
    #pragma unroll
    for (int mt = 0; mt < 2; ++mt)
        #pragma unroll
        for (int nt = 0; nt < 8; ++nt)
            #pragma unroll
            for (int e = 0; e < 4; ++e) acc[mt][nt][e] = 0.f;
    float den = 0.f;

    const int amrow   = wm*32 + (lane & 15);
    const int acoladd = ((lane >> 4) << 3);
    const int bseq = ((lane >> 3) & 1) * 8 + (lane & 7);
    const int bdc  = wn*64 + ((lane >> 4) << 3);

    for (int kc = 0; kc < 8; ++kc) {
        CP_WAIT0();
        __syncthreads();
        if (kc < 7) {
            issue(kc + 1, (kc + 1) & 1);
            if (tid < 32)
                sKs[(kc+1) & 1][tid] = g_ksum[(size_t)hh * FF + (kc+1)*32 + tid];
        }

        const uint32_t ab = sbase + (uint32_t)(kc & 1) * QSLOT;
        const uint32_t bb = ab + 20480u;
        const __half* sAhp = reinterpret_cast<const __half*>(qc + (kc & 1) * QSLOT);
        const float* ks = sKs[kc & 1];

        if (tid < 256) {
            #pragma unroll
            for (int kk = 0; kk < 32; ++kk)
                den = fmaf(__half2float(sAhp[tid*40 + kk]), ks[kk], den);
        }

        #pragma unroll
        for (int s = 0; s < 2; ++s) {
            uint32_t a[2][4];
            #pragma unroll
            for (int mt = 0; mt < 2; ++mt) {
                uint32_t ad = ab + (uint32_t)(((amrow + mt*16) * 40) + s*16 + acoladd) * 2u;
                ldsm_x4(a[mt][0], a[mt][1], a[mt][2], a[mt][3], ad);
            }
            #pragma unroll
            for (int p = 0; p < 4; ++p) {
                uint32_t b0, b1v, b2, b3;
                uint32_t bd = bb + (uint32_t)(((s*16 + bseq) * 136) + bdc + p*16) * 2u;
                ldsm_x4t(b0, b1v, b2, b3, bd);
                mma_fp16(acc[0][2*p],   a[0], b0, b1v);
                mma_fp16(acc[0][2*p+1], a[0], b2, b3);
                mma_fp16(acc[1][2*p],   a[1], b0, b1v);
                mma_fp16(acc[1][2*p+1], a[1], b2, b3);
            }
        }
    }

    if (tid < 256) sDen[tid] = den;
    __syncthreads();

    float* op = out + ((size_t)hh * NSEQ + m0) * DD;
    #pragma unroll
    for (int mt = 0; mt < 2; ++mt)
        #pragma unroll
        for (int h = 0; h < 2; ++h) {
            const int row = wm*32 + mt*16 + 8*h + g;
            const float invd = 1.f / fmaxf(sDen[row], 1e-6f);
            #pragma unroll
            for (int nt = 0; nt < 8; ++nt) {
                const int d = wn*64 + nt*8 + tq*2;
                *reinterpret_cast<float2*>(op + (size_t)row * DD + d) =
                    make_float2(acc[mt][nt][h*2] * invd, acc[mt][nt][h*2+1] * invd);
            }
        }
}

// ---------------------------------------------------------------------------
extern "C" void kernel_launch(void* const* d_in, const int* in_sizes, int n_in,
                              void* d_out, int out_size)
{
    (void)in_sizes; (void)n_in; (void)out_size;
    const float* q  = (const float*)d_in[0];
    const float* k  = (const float*)d_in[1];
    const float* v  = (const float*)d_in[2];
    const float* W1 = (const float*)d_in[3];
    const float* b1 = (const float*)d_in[4];
    const float* W2 = (const float*)d_in[5];
    const float* b2 = (const float*)d_in[6];
    float* out = (float*)d_out;

    cudaFuncSetAttribute(phi_mma_kernel, cudaFuncAttributeMaxDynamicSharedMemorySize, PHI_SMEM);
    cudaFuncSetAttribute(kv_mma_kernel,  cudaFuncAttributeMaxDynamicSharedMemorySize, KV_SMEM);
    cudaFuncSetAttribute(qkv_mma_kernel, cudaFuncAttributeMaxDynamicSharedMemorySize, QKV_SMEM);

    prep_kernel<<<48, 256>>>(W1, W2);
    phi_mma_kernel<<<4096, 256, PHI_SMEM>>>(q, k, b1, b2);
    kv_mma_kernel<<<dim3(32, 2, KSPLIT), 512, KV_SMEM>>>(v);
    {
        const int total = BH*FF*DD/4 + BH*FF;
        reduce_kernel<<<(total + 255) / 256, 256>>>();
    }
    qkv_mma_kernel<<<dim3(32, 16), 512, QKV_SMEM>>>(out);
}

// round 14
// speedup vs baseline: 5.2082x; 1.0731x over previous
#include <cuda_runtime.h>
#include <cuda_fp16.h>
#include <math.h>
#include <stdint.h>

// Problem constants
#define BH    32
#define NSEQ  4096
#define DD    128
#define FF    256
#define NTOK  (BH*NSEQ)
#define KSPLIT 4

// Scratch (device globals: allocation-free rule)
__device__ uint4  g_phiqf[(size_t)(NTOK/16)*16*32];  // phi_q in A-fragment order (67MB)
__device__ __half g_phi_k[(size_t)NTOK*FF];
__device__ float  g_kvp[(size_t)KSPLIT*BH*FF*DD];
__device__ float  g_ksp[(size_t)KSPLIT*BH*FF];
__device__ __half g_kvh[(size_t)BH*FF*DD];
__device__ float  g_ksum[(size_t)BH*FF];
__device__ uint4  g_Wf[12288];            // W in mma B-fragment order (192KB, L2-resident)

// ---------------------------------------------------------------------------
// helpers
// ---------------------------------------------------------------------------
__device__ __forceinline__ uint32_t smem_u32(const void* p) {
    return (uint32_t)__cvta_generic_to_shared(p);
}
__device__ __forceinline__ void cp_async16(uint32_t dst, const void* src) {
    asm volatile("cp.async.cg.shared.global [%0], [%1], 16;"
                 :: "r"(dst), "l"(src) : "memory");
}
#define CP_COMMIT() asm volatile("cp.async.commit_group;" ::: "memory")
#define CP_WAIT0()  asm volatile("cp.async.wait_group 0;" ::: "memory")

__device__ __forceinline__ void ldsm_x4(uint32_t& r0, uint32_t& r1,
                                        uint32_t& r2, uint32_t& r3, uint32_t a) {
    asm volatile("ldmatrix.sync.aligned.m8n8.x4.shared.b16 {%0,%1,%2,%3}, [%4];"
                 : "=r"(r0), "=r"(r1), "=r"(r2), "=r"(r3) : "r"(a));
}
__device__ __forceinline__ void ldsm_x4t(uint32_t& r0, uint32_t& r1,
                                         uint32_t& r2, uint32_t& r3, uint32_t a) {
    asm volatile("ldmatrix.sync.aligned.m8n8.x4.trans.shared.b16 {%0,%1,%2,%3}, [%4];"
                 : "=r"(r0), "=r"(r1), "=r"(r2), "=r"(r3) : "r"(a));
}
__device__ __forceinline__ void mma_fp16(float* d, const uint32_t* a,
                                         uint32_t b0, uint32_t b1) {
    asm volatile("mma.sync.aligned.m16n8k16.row.col.f32.f16.f16.f32 "
                 "{%0,%1,%2,%3}, {%4,%5,%6,%7}, {%8,%9}, {%0,%1,%2,%3};"
                 : "+f"(d[0]), "+f"(d[1]), "+f"(d[2]), "+f"(d[3])
                 : "r"(a[0]), "r"(a[1]), "r"(a[2]), "r"(a[3]),
                   "r"(b0), "r"(b1));
}
__device__ __forceinline__ float2 h2f2(uint32_t h) {
    __half2 v = *reinterpret_cast<__half2*>(&h);
    return __half22float2(v);
}

// ---------------------------------------------------------------------------
// prep: W1/W2 -> fp16 B-fragment images (R12-proven mapping).
// ---------------------------------------------------------------------------
__global__ void prep_kernel(const float* __restrict__ W1, const float* __restrict__ W2)
{
    int i = blockIdx.x * blockDim.x + threadIdx.x;
    if (i >= 12288) return;
    int lane = i & 31, p = (i >> 5) & 3, s = (i >> 7) & 3, wn = (i >> 9) & 3, kc = i >> 11;
    int g = lane >> 2, tq = lane & 3;
    int n0 = wn*64 + p*16 + g;
    int kk = s*16 + 2*tq;
    const float* W = (kc < 2) ? W1 : W2;
    int k0 = (kc < 2) ? kc*64 : (kc - 2)*64;

    __half2 w0 = __floats2half2_rn(W[(size_t)(k0+kk  )*256 + n0],   W[(size_t)(k0+kk+1)*256 + n0]);
    __half2 w1 = __floats2half2_rn(W[(size_t)(k0+kk+8)*256 + n0],   W[(size_t)(k0+kk+9)*256 + n0]);
    __half2 w2 = __floats2half2_rn(W[(size_t)(k0+kk  )*256 + n0+8], W[(size_t)(k0+kk+1)*256 + n0+8]);
    __half2 w3 = __floats2half2_rn(W[(size_t)(k0+kk+8)*256 + n0+8], W[(size_t)(k0+kk+9)*256 + n0+8]);
    uint4 o;
    o.x = *reinterpret_cast<uint32_t*>(&w0);
    o.y = *reinterpret_cast<uint32_t*>(&w1);
    o.z = *reinterpret_cast<uint32_t*>(&w2);
    o.w = *reinterpret_cast<uint32_t*>(&w3);
    g_Wf[i] = o;
}

// ---------------------------------------------------------------------------
// phi kernel: as R12/R13, except phi_q is written in A-fragment uint4 order.
// ---------------------------------------------------------------------------
#define PHI_SMEM 37120

__global__ void __launch_bounds__(256, 2) phi_mma_kernel(
    const float* __restrict__ q, const float* __restrict__ k,
    const float* __restrict__ b1, const float* __restrict__ b2)
{
    extern __shared__ char smc[];
    __half* sAh = reinterpret_cast<__half*>(smc);
    float* sB1  = reinterpret_cast<float*>(smc + 33792);
    float* sB2  = reinterpret_cast<float*>(smc + 34816);
    float* sPrt = reinterpret_cast<float*>(smc + 35840);
    float* sInv = reinterpret_cast<float*>(smc + 36864);
    const uint32_t abase = smem_u32(smc);

    const int tid  = threadIdx.x;
    const int wid  = tid >> 5;
    const int lane = tid & 31;
    const int g    = lane >> 2;
    const int tq   = lane & 3;
    const int wm   = wid & 1;
    const int wn   = wid >> 1;

    const int bid = blockIdx.x;
    const bool isq = (bid < 2048);
    const float* src = isq ? q : k;
    const int tok0 = (bid & 2047) * 64;

    {
        const float4* s4 = reinterpret_cast<const float4*>(src + (size_t)tok0 * DD);
        #pragma unroll
        for (int l = 0; l < 8; ++l) {
            int id  = tid + l * 256;
            int row = id >> 5, c4 = id & 31;
            float4 v = s4[row * 32 + c4];
            __half2* p = reinterpret_cast<__half2*>(sAh + row*136 + c4*4);
            p[0] = __floats2half2_rn(v.x, v.y);
            p[1] = __floats2half2_rn(v.z, v.w);
        }
    }
    sB1[tid] = b1[tid];
    sB2[tid] = b2[tid];
    __syncthreads();

    float acc[2][8][4];
    #pragma unroll
    for (int mt = 0; mt < 2; ++mt)
        #pragma unroll
        for (int nt = 0; nt < 8; ++nt)
            #pragma unroll
            for (int e = 0; e < 4; ++e) acc[mt][nt][e] = 0.f;

    const int amrow   = wm*32 + (lane & 15);
    const int acoladd = ((lane >> 4) << 3);
    const int wfbase = wn*512 + lane;

    uint4 bv[2][4];
    #pragma unroll
    for (int p = 0; p < 4; ++p) bv[0][p] = g_Wf[wfbase + p*32];

    #pragma unroll
    for (int kc = 0; kc < 6; ++kc) {
        if (kc == 2) {
            __syncthreads();
            #pragma unroll
            for (int mt = 0; mt < 2; ++mt)
                #pragma unroll
                for (int nt = 0; nt < 8; ++nt) {
                    const int col = wn*64 + nt*8 + tq*2;
                    #pragma unroll
                    for (int h = 0; h < 2; ++h) {
                        const int row = wm*32 + mt*16 + 8*h + g;
                        float x0 = acc[mt][nt][h*2]   + sB1[col];
                        float x1 = acc[mt][nt][h*2+1] + sB1[col+1];
                        float s0 = x0 / (1.f + __expf(-x0));
                        float s1 = x1 / (1.f + __expf(-x1));
                        *reinterpret_cast<__half2*>(sAh + row*264 + col) =
                            __floats2half2_rn(s0, s1);
                        acc[mt][nt][h*2] = 0.f;
                        acc[mt][nt][h*2+1] = 0.f;
                    }
                }
            __syncthreads();
        }

        #pragma unroll
        for (int s = 0; s < 4; ++s) {
            const int step = kc*4 + s;
            const int cur  = step & 1;

            if (step < 23) {
                const int ns = step + 1;
                const int nbase = (ns >> 2) * 2048 + ((ns & 3) * 128) + wfbase;
                #pragma unroll
                for (int p = 0; p < 4; ++p)
                    bv[cur ^ 1][p] = g_Wf[nbase + p*32];
            }

            const bool s1s = (kc < 2);
            const int astr = s1s ? 136 : 264;
            const int kbase = (s1s ? kc*64 : (kc - 2)*64) + s*16;
            uint32_t a[2][4];
            #pragma unroll
            for (int mt = 0; mt < 2; ++mt) {
                uint32_t ad = abase +
                    (uint32_t)(((amrow + mt*16) * astr) + kbase + acoladd) * 2u;
                ldsm_x4(a[mt][0], a[mt][1], a[mt][2], a[mt][3], ad);
            }

            #pragma unroll
            for (int p = 0; p < 4; ++p) {
                const uint4 b = bv[cur][p];
                mma_fp16(acc[0][2*p],   a[0], b.x, b.y);
                mma_fp16(acc[0][2*p+1], a[0], b.z, b.w);
                mma_fp16(acc[1][2*p],   a[1], b.x, b.y);
                mma_fp16(acc[1][2*p+1], a[1], b.z, b.w);
            }
        }
    }

    // ===== epilogue 2: p = elu(acc + b2)+1, row L2 norm =====
    float ss[2][2] = {};
    #pragma unroll
    for (int mt = 0; mt < 2; ++mt)
        #pragma unroll
        for (int nt = 0; nt < 8; ++nt) {
            const int col = wn*64 + nt*8 + tq*2;
            #pragma unroll
            for (int h = 0; h < 2; ++h)
                #pragma unroll
                for (int pr = 0; pr < 2; ++pr) {
                    float x = acc[mt][nt][h*2+pr] + sB2[col+pr];
                    float p = (x > 0.f) ? (x + 1.f) : __expf(x);
                    acc[mt][nt][h*2+pr] = p;
                    ss[mt][h] = fmaf(p, p, ss[mt][h]);
                }
        }
    #pragma unroll
    for (int m = 1; m <= 2; m <<= 1)
        #pragma unroll
        for (int mt = 0; mt < 2; ++mt)
            #pragma unroll
            for (int h = 0; h < 2; ++h)
                ss[mt][h] += __shfl_xor_sync(0xffffffffu, ss[mt][h], m);
    if (tq == 0) {
        #pragma unroll
        for (int mt = 0; mt < 2; ++mt)
            #pragma unroll
            for (int h = 0; h < 2; ++h)
                sPrt[wn*64 + wm*32 + mt*16 + 8*h + g] = ss[mt][h];
    }
    __syncthreads();
    if (tid < 64)
        sInv[tid] = 1.f / (sqrtf(sPrt[tid] + sPrt[64+tid] +
                                 sPrt[128+tid] + sPrt[192+tid]) + 1e-6f);
    __syncthreads();

    if (isq) {
        // phi_q: A-fragment layout. frag idx = (tb*16 + kb)*32 + lane.
        // uint4 = {h2(h0,ntE), h2(h1,ntE), h2(h0,ntO), h2(h1,ntO)}
        const int tb0 = (tok0 >> 4) + wm*2;
        #pragma unroll
        for (int mt = 0; mt < 2; ++mt) {
            const float inv0 = sInv[wm*32 + mt*16 + g];
            const float inv1 = sInv[wm*32 + mt*16 + 8 + g];
            const int tb = tb0 + mt;
            #pragma unroll
            for (int np = 0; np < 4; ++np) {
                const int ntE = 2*np, ntO = 2*np + 1;
                __half2 hx = __floats2half2_rn(acc[mt][ntE][0]*inv0, acc[mt][ntE][1]*inv0);
                __half2 hy = __floats2half2_rn(acc[mt][ntE][2]*inv1, acc[mt][ntE][3]*inv1);
                __half2 hz = __floats2half2_rn(acc[mt][ntO][0]*inv0, acc[mt][ntO][1]*inv0);
                __half2 hw = __floats2half2_rn(acc[mt][ntO][2]*inv1, acc[mt][ntO][3]*inv1);
                uint4 o;
                o.x = *reinterpret_cast<uint32_t*>(&hx);
                o.y = *reinterpret_cast<uint32_t*>(&hy);
                o.z = *reinterpret_cast<uint32_t*>(&hz);
                o.w = *reinterpret_cast<uint32_t*>(&hw);
                g_phiqf[((size_t)tb*16 + (wn*4 + np))*32 + lane] = o;
            }
        }
    } else {
        // phi_k: row-major half layout (kv consumes via ldsm.trans)
        #pragma unroll
        for (int mt = 0; mt < 2; ++mt)
            #pragma unroll
            for (int h = 0; h < 2; ++h) {
                const int row = wm*32 + mt*16 + 8*h + g;
                const float inv = sInv[row];
                __half* dr = g_phi_k + (size_t)(tok0 + row) * FF;
                #pragma unroll
                for (int nt = 0; nt < 8; ++nt) {
                    const int col = wn*64 + nt*8 + tq*2;
                    *reinterpret_cast<__half2*>(dr + col) =
                        __floats2half2_rn(acc[mt][nt][h*2] * inv,
                                          acc[mt][nt][h*2+1] * inv);
                }
            }
    }
}

// ---------------------------------------------------------------------------
// kv kernel (unchanged from R13): inline v fp32->fp16, cp.async P, S=2.
// ---------------------------------------------------------------------------
#define KV_SMEM 34816

__global__ void __launch_bounds__(512, 2) kv_mma_kernel(const float* __restrict__ v)
{
    extern __shared__ char kvc[];
    const uint32_t sbase = smem_u32(kvc);

    const int hh = blockIdx.x;
    const int f0 = blockIdx.y * 128;
    const int ks = blockIdx.z;
    const int tid  = threadIdx.x;
    const int lane = tid & 31;
    const int wid  = tid >> 5;
    const int g  = lane >> 2;
    const int tq = lane & 3;
    const int wm = wid & 3;
    const int wn = wid >> 2;

    const __half* pbase = g_phi_k + ((size_t)hh * NSEQ + (size_t)ks * 1024) * FF + f0;
    const float*  vbase = v       + ((size_t)hh * NSEQ + (size_t)ks * 1024) * DD;

    const int vrow = tid >> 4;
    const int vseg = tid & 15;
    const uint32_t vsts_off = (uint32_t)(vrow*272 + vseg*16);

    auto issueP = [&](int b, int slot) {
        uint32_t base = sbase + (uint32_t)slot * 17408u;
        cp_async16(base + vrow*272 + vseg*16,
                   pbase + (size_t)(b*32 + vrow)*FF + vseg*8);
        CP_COMMIT();
    };
    auto ldgV = [&](int b, float4& v0, float4& v1) {
        const float4* p = reinterpret_cast<const float4*>(
            vbase + (size_t)(b*32 + vrow)*DD + vseg*8);
        v0 = p[0]; v1 = p[1];
    };

    float4 va0, va1;
    ldgV(0, va0, va1);
    issueP(0, 0);

    float acc[2][4][4];
    #pragma unroll
    for (int mt = 0; mt < 2; ++mt)
        #pragma unroll
        for (int nt = 0; nt < 4; ++nt)
            #pragma unroll
            for (int e = 0; e < 4; ++e) acc[mt][nt][e] = 0.f;
    float ksacc = 0.f;

    const int aseq = ((lane >> 4) << 3) + (lane & 7);
    const int afc  = wm*32 + ((lane >> 3) & 1) * 8;
    const int bseq = ((lane >> 3) & 1) * 8 + (lane & 7);
    const int bdc  = wn*32 + ((lane >> 4) << 3);

    for (int b = 0; b < 32; ++b) {
        {
            __half2 h0 = __floats2half2_rn(va0.x, va0.y);
            __half2 h1 = __floats2half2_rn(va0.z, va0.w);
            __half2 h2 = __floats2half2_rn(va1.x, va1.y);
            __half2 h3 = __floats2half2_rn(va1.z, va1.w);
            uint32_t addr = sbase + (uint32_t)(b & 1)*17408u + 8704u + vsts_off;
            asm volatile("st.shared.v4.b32 [%0], {%1,%2,%3,%4};" :: "r"(addr),
                "r"(*reinterpret_cast<uint32_t*>(&h0)),
                "r"(*reinterpret_cast<uint32_t*>(&h1)),
                "r"(*reinterpret_cast<uint32_t*>(&h2)),
                "r"(*reinterpret_cast<uint32_t*>(&h3)) : "memory");
        }
        CP_WAIT0();
        __syncthreads();
        if (b < 31) { issueP(b + 1, (b + 1) & 1); ldgV(b + 1, va0, va1); }

        const uint32_t pb = sbase + (uint32_t)(b & 1) * 17408u;
        const uint32_t vb = pb + 8704u;
        const __half* sP = reinterpret_cast<const __half*>(kvc + (b & 1) * 17408);

        if (tid < 128) {
            #pragma unroll
            for (int r = 0; r < 32; ++r)
                ksacc += __half2float(sP[r*136 + tid]);
        }

        uint32_t a[2][2][4];
        #pragma unroll
        for (int s = 0; s < 2; ++s)
            #pragma unroll
            for (int mt = 0; mt < 2; ++mt) {
                uint32_t ad = pb + (uint32_t)(((s*16 + aseq) * 136) + afc + mt*16) * 2u;
                ldsm_x4t(a[mt][s][0], a[mt][s][1], a[mt][s][2], a[mt][s][3], ad);
            }
        #pragma unroll
        for (int s = 0; s < 2; ++s)
            #pragma unroll
            for (int p = 0; p < 2; ++p) {
                uint32_t b0, b1v, b2, b3;
                uint32_t bd = vb + (uint32_t)(((s*16 + bseq) * 136) + bdc + p*16) * 2u;
                ldsm_x4t(b0, b1v, b2, b3, bd);
                mma_fp16(acc[0][2*p],   a[0][s], b0, b1v);
                mma_fp16(acc[0][2*p+1], a[0][s], b2, b3);
                mma_fp16(acc[1][2*p],   a[1][s], b0, b1v);
                mma_fp16(acc[1][2*p+1], a[1][s], b2, b3);
            }
    }

    float* outp = g_kvp + ((size_t)ks * BH + hh) * FF * DD;
    #pragma unroll
    for (int mt = 0; mt < 2; ++mt)
        #pragma unroll
        for (int h = 0; h < 2; ++h) {
            const int f = f0 + wm*32 + mt*16 + 8*h + g;
            #pragma unroll
            for (int nt = 0; nt < 4; ++nt) {
                const int d = wn*32 + nt*8 + tq*2;
                *reinterpret_cast<float2*>(outp + (size_t)f * DD + d) =
                    make_float2(acc[mt][nt][h*2], acc[mt][nt][h*2+1]);
            }
        }
    if (tid < 128)
        g_ksp[((size_t)ks * BH + hh) * FF + f0 + tid] = ksacc;
}

// ---------------------------------------------------------------------------
// reduce kernel (unchanged)
// ---------------------------------------------------------------------------
__global__ void reduce_kernel()
{
    const int NKV4 = BH * FF * DD / 4;
    const int NKS  = BH * FF;
    int i = blockIdx.x * blockDim.x + threadIdx.x;
    if (i < NKV4) {
        float4 s = make_float4(0.f, 0.f, 0.f, 0.f);
        #pragma unroll
        for (int p = 0; p < KSPLIT; ++p) {
            float4 t = reinterpret_cast<const float4*>(g_kvp)[(size_t)p * NKV4 + i];
            s.x += t.x; s.y += t.y; s.z += t.z; s.w += t.w;
        }
        __half2* o = reinterpret_cast<__half2*>(g_kvh + (size_t)i*4);
        o[0] = __floats2half2_rn(s.x, s.y);
        o[1] = __floats2half2_rn(s.z, s.w);
    } else {
        int j = i - NKV4;
        if (j < NKS) {
            float s = 0.f;
            #pragma unroll
            for (int p = 0; p < KSPLIT; ++p) s += g_ksp[(size_t)p * NKS + j];
            g_ksum[j] = s;
        }
    }
}

// ---------------------------------------------------------------------------
// qkv kernel: A = phi_q fragments LDG.128'd directly to registers (double-
// buffered across kc); B = kv via cp.async+ldsm.trans; den from fragments.
// M0=256 tokens/CTA, warp tile 32x64 (8M x 2N warps), grid (32, 16), 512 thr.
// SMEM: 2 x B[32][136]h = 17408 B dynamic (+ statics).
// ---------------------------------------------------------------------------
#define QSLOT 8704u
#define QKV_SMEM 17408

__global__ void __launch_bounds__(512) qkv_mma_kernel(float* __restrict__ out)
{
    extern __shared__ char qc[];
    __shared__ float sKs[2][32];
    __shared__ float sDen[256];
    const uint32_t sbase = smem_u32(qc);

    const int hh = blockIdx.x;
    const int m0 = blockIdx.y * 256;
    const int tid  = threadIdx.x;
    const int lane = tid & 31;
    const int wid  = tid >> 5;
    const int g  = lane >> 2;
    const int tq = lane & 3;
    const int wm = wid & 7;      // 8 M tiles of 32 rows
    const int wn = wid >> 3;     // 2 N tiles of 64 cols

    const __half* bgb = g_kvh + (size_t)hh * FF * DD;
    // fragment base: tb = hh*256 + m0/16 + wm*2 + mt ; kb = kc*2 + s
    const size_t fbase = ((size_t)hh*256 + (m0 >> 4) + wm*2) * 16 * 32 + lane;

    auto issueB = [&](int kc, int slot) {
        uint32_t base = sbase + (uint32_t)slot * QSLOT;
        int row = tid >> 4, seg = tid & 15;
        cp_async16(base + row*272 + seg*16,
                   bgb + (size_t)(kc*32 + row)*DD + seg*8);
        CP_COMMIT();
    };

    issueB(0, 0);
    if (tid < 32) sKs[0][tid] = g_ksum[(size_t)hh * FF + tid];

    // A fragment register double buffer: [buf][mt*2+s]
    uint4 fa[2][4];
    #pragma unroll
    for (int mt = 0; mt < 2; ++mt)
        #pragma unroll
        for (int s = 0; s < 2; ++s)
            fa[0][mt*2+s] = g_phiqf[fbase + ((size_t)mt*16 + s)*32];

    float acc[2][8][4];
    #pragma unroll
    for (int mt = 0; mt < 2; ++mt)
        #pragma unroll
        for (int nt = 0; nt < 8; ++nt)
            #pragma unroll
            for (int e = 0; e < 4; ++e) acc[mt][nt][e] = 0.f;
    float den4[2][2] = {};   // [mt][row-half]

    const int bseq = ((lane >> 3) & 1) * 8 + (lane & 7);
    const int bdc  = wn*64 + ((lane >> 4) << 3);

    for (int kc = 0; kc < 8; ++kc) {
        const int cur = kc & 1;
        // prefetch next kc's A fragments
        if (kc < 7) {
            #pragma unroll
            for (int mt = 0; mt < 2; ++mt)
                #pragma unroll
                for (int s = 0; s < 2; ++s)
                    fa[cur ^ 1][mt*2+s] =
                        g_phiqf[fbase + ((size_t)mt*16 + (kc+1)*2 + s)*32];
        }

        CP_WAIT0();
        __syncthreads();
        if (kc < 7) {
            issueB(kc + 1, (kc + 1) & 1);
            if (tid < 32)
                sKs[(kc+1) & 1][tid] = g_ksum[(size_t)hh * FF + (kc+1)*32 + tid];
        }

        const uint32_t bb = sbase + (uint32_t)cur * QSLOT;
        const float* ks = sKs[cur];

        // den partials from fragments (rows duplicated across wn -> wn==0 only)
        if (wn == 0) {
            #pragma unroll
            for (int mt = 0; mt < 2; ++mt)
                #pragma unroll
                for (int s = 0; s < 2; ++s) {
                    const uint4 f = fa[cur][mt*2+s];
                    const int k0 = s*16 + 2*tq;
                    float2 xv = h2f2(f.x), yv = h2f2(f.y);
                    float2 zv = h2f2(f.z), wv = h2f2(f.w);
                    den4[mt][0] = fmaf(xv.x, ks[k0],   den4[mt][0]);
                    den4[mt][0] = fmaf(xv.y, ks[k0+1], den4[mt][0]);
                    den4[mt][0] = fmaf(zv.x, ks[k0+8], den4[mt][0]);
                    den4[mt][0] = fmaf(zv.y, ks[k0+9], den4[mt][0]);
                    den4[mt][1] = fmaf(yv.x, ks[k0],   den4[mt][1]);
                    den4[mt][1] = fmaf(yv.y, ks[k0+1], den4[mt][1]);
                    den4[mt][1] = fmaf(wv.x, ks[k0+8], den4[mt][1]);
                    den4[mt][1] = fmaf(wv.y, ks[k0+9], den4[mt][1]);
                }
        }

        #pragma unroll
        for (int s = 0; s < 2; ++s) {
            const uint32_t* a0 = reinterpret_cast<const uint32_t*>(&fa[cur][s]);
            const uint32_t* a1 = reinterpret_cast<const uint32_t*>(&fa[cur][2+s]);
            #pragma unroll
            for (int p = 0; p < 4; ++p) {
                uint32_t b0, b1v, b2, b3;
                uint32_t bd = bb + (uint32_t)(((s*16 + bseq) * 136) + bdc + p*16) * 2u;
                ldsm_x4t(b0, b1v, b2, b3, bd);
                mma_fp16(acc[0][2*p],   a0, b0, b1v);
                mma_fp16(acc[0][2*p+1], a0, b2, b3);
                mma_fp16(acc[1][2*p],   a1, b0, b1v);
                mma_fp16(acc[1][2*p+1], a1, b2, b3);
            }
        }
    }

    // reduce den over quad (tq lanes), write sDen
    #pragma unroll
    for (int m = 1; m <= 2; m <<= 1)
        #pragma unroll
        for (int mt = 0; mt < 2; ++mt)
            #pragma unroll
            for (int h = 0; h < 2; ++h)
                den4[mt][h] += __shfl_xor_sync(0xffffffffu, den4[mt][h], m);
    if (wn == 0 && tq == 0) {
        #pragma unroll
        for (int mt = 0; mt < 2; ++mt) {
            sDen[wm*32 + mt*16 + g]     = den4[mt][0];
            sDen[wm*32 + mt*16 + 8 + g] = den4[mt][1];
        }
    }
    __syncthreads();

    float* op = out + ((size_t)hh * NSEQ + m0) * DD;
    #pragma unroll
    for (int mt = 0; mt < 2; ++mt)
        #pragma unroll
        for (int h = 0; h < 2; ++h) {
            const int row = wm*32 + mt*16 + 8*h + g;
            const float invd = 1.f / fmaxf(sDen[row], 1e-6f);
            #pragma unroll
            for (int nt = 0; nt < 8; ++nt) {
                const int d = wn*64 + nt*8 + tq*2;
                *reinterpret_cast<float2*>(op + (size_t)row * DD + d) =
                    make_float2(acc[mt][nt][h*2] * invd, acc[mt][nt][h*2+1] * invd);
            }
        }
}

// ---------------------------------------------------------------------------
extern "C" void kernel_launch(void* const* d_in, const int* in_sizes, int n_in,
                              void* d_out, int out_size)
{
    (void)in_sizes; (void)n_in; (void)out_size;
    const float* q  = (const float*)d_in[0];
    const float* k  = (const float*)d_in[1];
    const float* v  = (const float*)d_in[2];
    const float* W1 = (const float*)d_in[3];
    const float* b1 = (const float*)d_in[4];
    const float* W2 = (const float*)d_in[5];
    const float* b2 = (const float*)d_in[6];
    float* out = (float*)d_out;

    cudaFuncSetAttribute(phi_mma_kernel, cudaFuncAttributeMaxDynamicSharedMemorySize, PHI_SMEM);
    cudaFuncSetAttribute(kv_mma_kernel,  cudaFuncAttributeMaxDynamicSharedMemorySize, KV_SMEM);
    cudaFuncSetAttribute(qkv_mma_kernel, cudaFuncAttributeMaxDynamicSharedMemorySize, QKV_SMEM);

    prep_kernel<<<48, 256>>>(W1, W2);
    phi_mma_kernel<<<4096, 256, PHI_SMEM>>>(q, k, b1, b2);
    kv_mma_kernel<<<dim3(32, 2, KSPLIT), 512, KV_SMEM>>>(v);
    {
        const int total = BH*FF*DD/4 + BH*FF;
        reduce_kernel<<<(total + 255) / 256, 256>>>();
    }
    qkv_mma_kernel<<<dim3(32, 16), 512, QKV_SMEM>>>(out);
}